// round 9
// baseline (speedup 1.0000x reference)
#include <cuda_runtime.h>
#include <cuda_bf16.h>
#include <math.h>

#define Mtot  4096
#define Hdim  768
#define FFdim 3072
#define NHnum 12
#define DHdim 64
#define Sdim  512
#define Bdim  8
#define Ldim  9
#define NLnum 12

#define KE_H  (3 * Hdim)    // 2304
#define KE_FF (3 * FFdim)   // 9216

// ---------------- scratch (static device allocations) ----------------
__device__ float g_h[Mtot * Hdim];
__device__ float g_q[Mtot * Hdim];
__device__ float g_k[Mtot * Hdim];
__device__ float g_v[Mtot * Hdim];
__device__ float g_t[Mtot * Hdim];
__device__ float g_feats[Mtot * Ldim];
__device__ float g_logZ[Bdim];
__device__ float g_num[Bdim];
__device__ int   g_tags[Bdim * Sdim];

// split-bf16 ext activations (A operands): [M][3K], slots per k: ah, al, ah
__device__ __align__(256) __nv_bfloat16 g_hext[Mtot * KE_H];
__device__ __align__(256) __nv_bfloat16 g_ctxext[Mtot * KE_H];
__device__ __align__(256) __nv_bfloat16 g_ffext[(size_t)Mtot * KE_FF];

// packed split-bf16 weights (B operands): [3K/2][N] u32, pair=(ext row 2i, 2i+1)
// slots per k: bh, bh, bl
#define PKH (3 * Hdim / 2)    // 1152
#define PKF (3 * FFdim / 2)   // 4608
__device__ __align__(256) unsigned int g_Wqp[NLnum * PKH * Hdim];
__device__ __align__(256) unsigned int g_Wkp[NLnum * PKH * Hdim];
__device__ __align__(256) unsigned int g_Wvp[NLnum * PKH * Hdim];
__device__ __align__(256) unsigned int g_Wop[NLnum * PKH * Hdim];
__device__ __align__(256) unsigned int g_W1p[(size_t)NLnum * PKH * FFdim];
__device__ __align__(256) unsigned int g_W2p[(size_t)NLnum * PKF * Hdim];

// ---------------- helpers ----------------
__device__ __forceinline__ float blk_sum256(float v, float* red) {
    int lane = threadIdx.x & 31, w = threadIdx.x >> 5;
#pragma unroll
    for (int o = 16; o; o >>= 1) v += __shfl_xor_sync(0xffffffffu, v, o);
    __syncthreads();
    if (lane == 0) red[w] = v;
    __syncthreads();
    float s = 0.f;
#pragma unroll
    for (int i = 0; i < 8; i++) s += red[i];
    return s;
}

__device__ __forceinline__ void split2(float x, __nv_bfloat16& hi, __nv_bfloat16& lo) {
    hi = __float2bfloat16(x);
    lo = __float2bfloat16(x - __bfloat162float(hi));
}

__device__ __forceinline__ void write_ext3(__nv_bfloat16* p, float x) {
    __nv_bfloat16 h, l;
    split2(x, h, l);
    p[0] = h; p[1] = l; p[2] = h;   // A-ext slots: ah, al, ah
}

// fast exp on the FMA pipe (no MUFU)
__device__ __forceinline__ float fexp(float x) {
    float t = x * 1.4426950408889634f;
    t = fmaxf(t, -126.0f);
    float fl = floorf(t);
    float f = t - fl;
    float p = 1.525273e-5f;
    p = fmaf(p, f, 1.5403530e-4f);
    p = fmaf(p, f, 1.3333558e-3f);
    p = fmaf(p, f, 9.6181291e-3f);
    p = fmaf(p, f, 5.5504109e-2f);
    p = fmaf(p, f, 2.4022651e-1f);
    p = fmaf(p, f, 6.9314718e-1f);
    p = fmaf(p, f, 1.0f);
    return p * __int_as_float(((int)fl + 127) << 23);
}

// ---------------- weight conversion: fp32 [L][K][N] -> packed [L][3K/2][N] u32 ---
__device__ __forceinline__ unsigned int packw(const float* __restrict__ W, int K, int N,
                                              int l, int i, int n) {
    int s0 = 2 * i, s1 = 2 * i + 1;
    int k0 = s0 / 3, r0 = s0 % 3;
    int k1 = s1 / 3, r1 = s1 % 3;
    float w0 = W[((size_t)l * K + k0) * N + n];
    float w1 = W[((size_t)l * K + k1) * N + n];
    __nv_bfloat16 h0, l0, h1, l1;
    split2(w0, h0, l0);
    split2(w1, h1, l1);
    __nv_bfloat16 v0 = (r0 == 2) ? l0 : h0;   // B-ext slots: bh, bh, bl
    __nv_bfloat16 v1 = (r1 == 2) ? l1 : h1;
    __nv_bfloat162 pr(v0, v1);
    return *reinterpret_cast<unsigned int*>(&pr);
}

__global__ void convB_kernel(const float* __restrict__ W, unsigned int* __restrict__ out,
                             int K, int N, int L) {
    size_t PK = (size_t)3 * K / 2;
    size_t total = (size_t)L * PK * N;
    for (size_t idx = (size_t)blockIdx.x * blockDim.x + threadIdx.x; idx < total;
         idx += (size_t)gridDim.x * blockDim.x) {
        int n = (int)(idx % N);
        size_t rest = idx / N;
        int i = (int)(rest % PK);
        int l = (int)(rest / PK);
        out[idx] = packw(W, K, N, l, i, n);
    }
}

// two same-shape tensors in one launch (cuts launch count so ncu hits the GEMM)
__global__ void convB2_kernel(const float* __restrict__ Wa, unsigned int* __restrict__ outa,
                              const float* __restrict__ Wb, unsigned int* __restrict__ outb,
                              int K, int N, int L) {
    size_t PK = (size_t)3 * K / 2;
    size_t total = (size_t)L * PK * N;
    for (size_t idx = (size_t)blockIdx.x * blockDim.x + threadIdx.x; idx < 2 * total;
         idx += (size_t)gridDim.x * blockDim.x) {
        const float* W = (idx < total) ? Wa : Wb;
        unsigned int* out = (idx < total) ? outa : outb;
        size_t j = (idx < total) ? idx : idx - total;
        int n = (int)(j % N);
        size_t rest = j / N;
        int i = (int)(rest % PK);
        int l = (int)(rest / PK);
        out[j] = packw(W, K, N, l, i, n);
    }
}

// ---------------- embedding + LayerNorm ----------------
__global__ void embed_ln_kernel(const float* __restrict__ we, const float* __restrict__ pe,
                                const float* __restrict__ te, const float* __restrict__ gs,
                                const float* __restrict__ gb, const int* __restrict__ ids,
                                const int* __restrict__ tts, float* __restrict__ out,
                                __nv_bfloat16* __restrict__ ext) {
    __shared__ float red[8];
    int m = blockIdx.x;
    int s = m & (Sdim - 1);
    int id = ids[m], tt = tts[m];
    float vals[3];
    float lsum = 0.f;
#pragma unroll
    for (int u = 0; u < 3; u++) {
        int j = threadIdx.x + u * 256;
        float v = we[(size_t)id * Hdim + j] + pe[(size_t)s * Hdim + j] + te[(size_t)tt * Hdim + j];
        vals[u] = v;
        lsum += v;
    }
    float mean = blk_sum256(lsum, red) * (1.f / Hdim);
    float lsq = 0.f;
#pragma unroll
    for (int u = 0; u < 3; u++) { float d = vals[u] - mean; lsq += d * d; }
    float var = blk_sum256(lsq, red) * (1.f / Hdim);
    float inv = rsqrtf(var + 1e-12f);
#pragma unroll
    for (int u = 0; u < 3; u++) {
        int j = threadIdx.x + u * 256;
        float y = (vals[u] - mean) * inv * gs[j] + gb[j];
        out[(size_t)m * Hdim + j] = y;
        write_ext3(ext + (size_t)m * KE_H + 3 * j, y);
    }
}

// ---------------- LayerNorm ----------------
__global__ void ln_kernel(const float* __restrict__ x, const float* __restrict__ gs,
                          const float* __restrict__ gb, float* __restrict__ y,
                          __nv_bfloat16* __restrict__ ext) {
    __shared__ float red[8];
    int m = blockIdx.x;
    const float* xr = x + (size_t)m * Hdim;
    float vals[3];
    float lsum = 0.f;
#pragma unroll
    for (int u = 0; u < 3; u++) {
        vals[u] = xr[threadIdx.x + u * 256];
        lsum += vals[u];
    }
    float mean = blk_sum256(lsum, red) * (1.f / Hdim);
    float lsq = 0.f;
#pragma unroll
    for (int u = 0; u < 3; u++) { float d = vals[u] - mean; lsq += d * d; }
    float var = blk_sum256(lsq, red) * (1.f / Hdim);
    float inv = rsqrtf(var + 1e-12f);
#pragma unroll
    for (int u = 0; u < 3; u++) {
        int j = threadIdx.x + u * 256;
        float yy = (vals[u] - mean) * inv * gs[j] + gb[j];
        y[(size_t)m * Hdim + j] = yy;
        write_ext3(ext + (size_t)m * KE_H + 3 * j, yy);
    }
}

// ================= tensor-core GEMM (split-bf16, K extended 3x) =================
// 2 CTAs/SM: BKE=48, 4 stages, 107KB smem/CTA
#define BM 128
#define BN 128
#define BKE 48                 // ext bf16 k per tile
#define BKP 24                 // packed pair-rows per tile
#define AS_STRIDE 28           // u32 words per A smem row (24 data + 4 pad)
#define BS_STRIDE 136          // u32 words per B smem row (128 data + 8 pad)
#define STAGE_WORDS (128 * AS_STRIDE + BKP * BS_STRIDE)  // 6848
#define NSTAGE 4
#define GEMM_SMEM (NSTAGE * STAGE_WORDS * 4)             // 109568 B

__device__ __forceinline__ void cp16(unsigned int saddr, const void* gptr) {
    asm volatile("cp.async.cg.shared.global [%0], [%1], 16;\n" ::"r"(saddr), "l"(gptr));
}
__device__ __forceinline__ void cp_commit() { asm volatile("cp.async.commit_group;\n"); }
__device__ __forceinline__ void cp_wait2() { asm volatile("cp.async.wait_group 2;\n"); }

#define MMA16816(d, a, b)                                                      \
    asm volatile(                                                              \
        "mma.sync.aligned.m16n8k16.row.col.f32.bf16.bf16.f32 "                 \
        "{%0,%1,%2,%3}, {%4,%5,%6,%7}, {%8,%9}, {%0,%1,%2,%3};\n"              \
        : "+f"(d[0]), "+f"(d[1]), "+f"(d[2]), "+f"(d[3])                       \
        : "r"(a[0]), "r"(a[1]), "r"(a[2]), "r"(a[3]), "r"(b[0]), "r"(b[1]))

__device__ __forceinline__ void gemm_core(const __nv_bfloat16* __restrict__ A,
                                          const unsigned int* __restrict__ B,
                                          const float* __restrict__ bias,
                                          const float* __restrict__ res,
                                          float* __restrict__ Cf,
                                          __nv_bfloat16* __restrict__ Ce,
                                          int N, int KE, int act, int addres, int outp,
                                          unsigned int* smem) {
    const int tid = threadIdx.x;
    const int lane = tid & 31;
    const int wid = tid >> 5;
    const int warp_m = wid >> 2;   // 0..1
    const int warp_n = wid & 3;    // 0..3
    const int m0 = blockIdx.y * BM;
    const int n0 = blockIdx.x * BN;
    const int T = KE / BKE;
    const int g = lane >> 2, t4 = lane & 3;

    float acc[4][4][4];
#pragma unroll
    for (int i = 0; i < 4; i++)
#pragma unroll
        for (int j = 0; j < 4; j++)
#pragma unroll
            for (int r = 0; r < 4; r++) acc[i][j][r] = 0.f;

    const unsigned int sbase = (unsigned int)__cvta_generic_to_shared(smem);

    auto load_stage = [&](int tile, int stg) {
        unsigned int abase = sbase + (unsigned int)(stg * STAGE_WORDS) * 4u;
        unsigned int bbase = abase + 128u * AS_STRIDE * 4u;
        const __nv_bfloat16* Ag = A + (size_t)m0 * KE + tile * BKE;
#pragma unroll
        for (int l = 0; l < 3; l++) {
            int i = tid + l * 256;
            int r = i / 6, c = i % 6;                // 128 rows x 6 chunks(16B)
            cp16(abase + (unsigned int)(r * AS_STRIDE + c * 4) * 4u,
                 Ag + (size_t)r * KE + c * 8);
        }
        const unsigned int* Bg = B + (size_t)(tile * BKP) * N + n0;
#pragma unroll
        for (int l = 0; l < 3; l++) {
            int i = tid + l * 256;
            int r = i / 32, c = i % 32;              // 24 rows x 32 chunks(16B)
            cp16(bbase + (unsigned int)(r * BS_STRIDE + c * 4) * 4u,
                 Bg + (size_t)r * N + c * 4);
        }
    };

    load_stage(0, 0); cp_commit();
    load_stage(1, 1); cp_commit();
    load_stage(2, 2); cp_commit();

    for (int t = 0; t < T; t++) {
        cp_wait2();
        __syncthreads();
        if (t + 3 < T) load_stage(t + 3, (t + 3) & 3);
        cp_commit();   // always commit (possibly empty) so wait_group maps to tiles

        const unsigned int* As = smem + (size_t)(t & 3) * STAGE_WORDS;
        const unsigned int* Bs = As + 128 * AS_STRIDE;
#pragma unroll
        for (int s = 0; s < 3; s++) {
            unsigned int a[4][4], b[4][2];
#pragma unroll
            for (int mi = 0; mi < 4; mi++) {
                int r = warp_m * 64 + mi * 16 + g;
                int cp = s * 8 + t4;
                a[mi][0] = As[r * AS_STRIDE + cp];
                a[mi][1] = As[(r + 8) * AS_STRIDE + cp];
                a[mi][2] = As[r * AS_STRIDE + cp + 4];
                a[mi][3] = As[(r + 8) * AS_STRIDE + cp + 4];
            }
#pragma unroll
            for (int nj = 0; nj < 4; nj++) {
                int n = warp_n * 32 + nj * 8 + g;
                b[nj][0] = Bs[(s * 8 + t4) * BS_STRIDE + n];
                b[nj][1] = Bs[(s * 8 + t4 + 4) * BS_STRIDE + n];
            }
#pragma unroll
            for (int mi = 0; mi < 4; mi++)
#pragma unroll
                for (int nj = 0; nj < 4; nj++) MMA16816(acc[mi][nj], a[mi], b[nj]);
        }
        __syncthreads();
    }

    // ---- epilogue ----
#pragma unroll
    for (int mi = 0; mi < 4; mi++) {
        int row0 = m0 + warp_m * 64 + mi * 16 + g;
#pragma unroll
        for (int nj = 0; nj < 4; nj++) {
            int col = n0 + warp_n * 32 + nj * 8 + t4 * 2;
            float b0 = bias[col], b1 = bias[col + 1];
#pragma unroll
            for (int half = 0; half < 2; half++) {
                int row = row0 + half * 8;
                float v0 = acc[mi][nj][half * 2 + 0] + b0;
                float v1 = acc[mi][nj][half * 2 + 1] + b1;
                if (addres) {
                    float2 rr = *(const float2*)(res + (size_t)row * N + col);
                    v0 += rr.x;
                    v1 += rr.y;
                }
                if (act) {
                    v0 = 0.5f * v0 * (1.f + erff(v0 * 0.70710678118654752440f));
                    v1 = 0.5f * v1 * (1.f + erff(v1 * 0.70710678118654752440f));
                }
                if (outp == 0) {
                    *(float2*)(Cf + (size_t)row * N + col) = make_float2(v0, v1);
                } else {
                    __nv_bfloat16* p = Ce + (size_t)row * (3 * N) + 3 * col;
                    write_ext3(p, v0);
                    write_ext3(p + 3, v1);
                }
            }
        }
    }
}

__global__ void __launch_bounds__(256, 2) gemm_k1(const __nv_bfloat16* __restrict__ A,
                                                  const unsigned int* __restrict__ B,
                                                  const float* __restrict__ bias,
                                                  const float* __restrict__ res,
                                                  float* __restrict__ Cf,
                                                  __nv_bfloat16* __restrict__ Ce,
                                                  int N, int KE, int act, int addres, int outp) {
    extern __shared__ unsigned int smem[];
    gemm_core(A, B, bias, res, Cf, Ce, N, KE, act, addres, outp, smem);
}

__global__ void __launch_bounds__(256, 2) gemm_k3(const __nv_bfloat16* __restrict__ A,
                                                  const unsigned int* __restrict__ B0,
                                                  const unsigned int* __restrict__ B1,
                                                  const unsigned int* __restrict__ B2,
                                                  const float* __restrict__ bias0,
                                                  const float* __restrict__ bias1,
                                                  const float* __restrict__ bias2,
                                                  float* __restrict__ C0, float* __restrict__ C1,
                                                  float* __restrict__ C2, int KE) {
    extern __shared__ unsigned int smem[];
    int z = blockIdx.z;
    const unsigned int* B = (z == 0) ? B0 : (z == 1) ? B1 : B2;
    const float* bias = (z == 0) ? bias0 : (z == 1) ? bias1 : bias2;
    float* Cf = (z == 0) ? C0 : (z == 1) ? C1 : C2;
    gemm_core(A, B, bias, nullptr, Cf, nullptr, Hdim, KE, 0, 0, 0, smem);
}

// ---------------- attention (fp32 SIMT; fast exp; epilogue emits split-bf16 ext) --------
__global__ void __launch_bounds__(256) attn_kernel(const float* __restrict__ Q,
                                                   const float* __restrict__ Kp,
                                                   const float* __restrict__ Vp,
                                                   const int* __restrict__ amask,
                                                   __nv_bfloat16* __restrict__ Oext) {
    extern __shared__ float sm[];
    float* sc = sm;
    float* qT = sm + 64 * 512;
    float* kT = qT + 64 * 64;
    const int tid = threadIdx.x;
    const int q0 = blockIdx.x * 64;
    const int h = blockIdx.y;
    const int b = blockIdx.z;
    const size_t base = (size_t)b * Sdim * Hdim + h * 64;
    const int ty = tid >> 4, tx = tid & 15;

    for (int i = tid; i < 1024; i += 256) {
        int r = i >> 4, c4 = i & 15;
        float4 v = *(const float4*)(Q + base + (size_t)(q0 + r) * Hdim + c4 * 4);
        qT[(c4 * 4 + 0) * 64 + r] = v.x;
        qT[(c4 * 4 + 1) * 64 + r] = v.y;
        qT[(c4 * 4 + 2) * 64 + r] = v.z;
        qT[(c4 * 4 + 3) * 64 + r] = v.w;
    }

    for (int kt = 0; kt < 8; kt++) {
        int k0 = kt * 64;
        __syncthreads();
        for (int i = tid; i < 1024; i += 256) {
            int r = i >> 4, c4 = i & 15;
            float4 v = *(const float4*)(Kp + base + (size_t)(k0 + r) * Hdim + c4 * 4);
            kT[(c4 * 4 + 0) * 64 + r] = v.x;
            kT[(c4 * 4 + 1) * 64 + r] = v.y;
            kT[(c4 * 4 + 2) * 64 + r] = v.z;
            kT[(c4 * 4 + 3) * 64 + r] = v.w;
        }
        __syncthreads();
        float acc[4][4];
#pragma unroll
        for (int i = 0; i < 4; i++)
#pragma unroll
            for (int j = 0; j < 4; j++) acc[i][j] = 0.f;
        for (int d = 0; d < 64; d++) {
            float a[4], bb[4];
            *(float4*)a = *(const float4*)(&qT[d * 64 + ty * 4]);
            *(float4*)bb = *(const float4*)(&kT[d * 64 + tx * 4]);
#pragma unroll
            for (int i = 0; i < 4; i++)
#pragma unroll
                for (int j = 0; j < 4; j++) acc[i][j] += a[i] * bb[j];
        }
#pragma unroll
        for (int i = 0; i < 4; i++) {
            float4 v = make_float4(acc[i][0], acc[i][1], acc[i][2], acc[i][3]);
            *(float4*)(&sc[(ty * 4 + i) * 512 + k0 + tx * 4]) = v;
        }
    }
    __syncthreads();

    {
        int row = tid >> 2, lane = tid & 3;
        float mx = -1e30f;
        for (int k = lane; k < 512; k += 4) {
            float mb = (1.f - (float)amask[b * Sdim + k]) * -10000.f;
            float v = sc[row * 512 + k] * 0.125f + mb;
            sc[row * 512 + k] = v;
            mx = fmaxf(mx, v);
        }
        mx = fmaxf(mx, __shfl_xor_sync(0xffffffffu, mx, 1, 4));
        mx = fmaxf(mx, __shfl_xor_sync(0xffffffffu, mx, 2, 4));
        float sum = 0.f;
        for (int k = lane; k < 512; k += 4) {
            float e = fexp(sc[row * 512 + k] - mx);
            sc[row * 512 + k] = e;
            sum += e;
        }
        sum += __shfl_xor_sync(0xffffffffu, sum, 1, 4);
        sum += __shfl_xor_sync(0xffffffffu, sum, 2, 4);
        float inv = 1.f / sum;
        for (int k = lane; k < 512; k += 4) sc[row * 512 + k] *= inv;
    }

    float acc[4][4];
#pragma unroll
    for (int i = 0; i < 4; i++)
#pragma unroll
        for (int j = 0; j < 4; j++) acc[i][j] = 0.f;
    for (int kt = 0; kt < 8; kt++) {
        int k0 = kt * 64;
        __syncthreads();
        for (int i = tid; i < 1024; i += 256) {
            int r = i >> 4, c4 = i & 15;
            float4 v = *(const float4*)(Vp + base + (size_t)(k0 + r) * Hdim + c4 * 4);
            *(float4*)(&kT[r * 64 + c4 * 4]) = v;
        }
        __syncthreads();
        for (int kk = 0; kk < 64; kk++) {
            float bb[4];
            *(float4*)bb = *(const float4*)(&kT[kk * 64 + tx * 4]);
            float p0 = sc[(ty * 4 + 0) * 512 + k0 + kk];
            float p1 = sc[(ty * 4 + 1) * 512 + k0 + kk];
            float p2 = sc[(ty * 4 + 2) * 512 + k0 + kk];
            float p3 = sc[(ty * 4 + 3) * 512 + k0 + kk];
#pragma unroll
            for (int j = 0; j < 4; j++) {
                acc[0][j] += p0 * bb[j];
                acc[1][j] += p1 * bb[j];
                acc[2][j] += p2 * bb[j];
                acc[3][j] += p3 * bb[j];
            }
        }
    }
#pragma unroll
    for (int i = 0; i < 4; i++) {
        int m = b * Sdim + q0 + ty * 4 + i;
        int colbase = h * 64 + tx * 4;
        __nv_bfloat16* p = Oext + (size_t)m * KE_H + 3 * colbase;
#pragma unroll
        for (int j = 0; j < 4; j++) write_ext3(p + 3 * j, acc[i][j]);
    }
}

// ---------------- classifier ----------------
__global__ void clf_kernel(const float* __restrict__ X, const float* __restrict__ W,
                           const float* __restrict__ bias, float* __restrict__ F) {
    __shared__ float red[8][Ldim];
    int m = blockIdx.x;
    int tid = threadIdx.x;
    float acc[Ldim];
#pragma unroll
    for (int j = 0; j < Ldim; j++) acc[j] = 0.f;
    for (int k = tid; k < Hdim; k += 256) {
        float x = X[(size_t)m * Hdim + k];
#pragma unroll
        for (int j = 0; j < Ldim; j++) acc[j] += x * W[k * Ldim + j];
    }
    int lane = tid & 31, w = tid >> 5;
#pragma unroll
    for (int j = 0; j < Ldim; j++)
#pragma unroll
        for (int o = 16; o; o >>= 1) acc[j] += __shfl_down_sync(0xffffffffu, acc[j], o);
    if (lane == 0)
#pragma unroll
        for (int j = 0; j < Ldim; j++) red[w][j] = acc[j];
    __syncthreads();
    if (tid < Ldim) {
        float s = bias[tid];
#pragma unroll
        for (int ww = 0; ww < 8; ww++) s += red[ww][tid];
        F[(size_t)m * Ldim + tid] = s;
    }
}

// ---------------- CRF numerator ----------------
__global__ void crf_num_kernel(const float* __restrict__ feats, const int* __restrict__ amask,
                               const int* __restrict__ labels, const float* __restrict__ start,
                               const float* __restrict__ endv, const float* __restrict__ trans,
                               float* __restrict__ num) {
    __shared__ float red[8];
    int b = blockIdx.x;
    int tid = threadIdx.x;
    float s = 0.f, msum = 0.f;
    for (int t = tid; t < Sdim; t += 256) {
        int tag = labels[b * Sdim + t];
        float em = feats[(size_t)(b * Sdim + t) * Ldim + tag];
        float m = (float)amask[b * Sdim + t];
        msum += m;
        if (t == 0) {
            s += start[tag] + em;
        } else {
            int pt = labels[b * Sdim + t - 1];
            s += (em + trans[pt * Ldim + tag]) * m;
        }
    }
    float stotal = blk_sum256(s, red);
    float mtotal = blk_sum256(msum, red);
    if (tid == 0) {
        int last = (int)(mtotal + 0.5f) - 1;
        num[b] = stotal + endv[labels[b * Sdim + last]];
    }
}

// ---------------- CRF forward ----------------
__global__ void crf_fwd_kernel(const float* __restrict__ feats, const int* __restrict__ amask,
                               const float* __restrict__ start, const float* __restrict__ endv,
                               const float* __restrict__ trans, float* __restrict__ logZ) {
    int b = threadIdx.x >> 5;
    int j = threadIdx.x & 31;
    bool act = j < Ldim;
    float tr[Ldim];
#pragma unroll
    for (int i = 0; i < Ldim; i++) tr[i] = act ? trans[i * Ldim + j] : 0.f;
    float score = act ? start[j] + feats[(size_t)(b * Sdim) * Ldim + j] : -1e30f;
    for (int t = 1; t < Sdim; t++) {
        float e = act ? feats[(size_t)(b * Sdim + t) * Ldim + j] : 0.f;
        int m = amask[b * Sdim + t];
        float v[Ldim];
        float mx = -1e30f;
#pragma unroll
        for (int i = 0; i < Ldim; i++) {
            float si = __shfl_sync(0xffffffffu, score, i);
            v[i] = si + tr[i];
            mx = fmaxf(mx, v[i]);
        }
        float ssum = 0.f;
#pragma unroll
        for (int i = 0; i < Ldim; i++) ssum += expf(v[i] - mx);
        float nxt = mx + logf(ssum) + e;
        if (act && m > 0) score = nxt;
    }
    float tot = act ? score + endv[j] : -1e30f;
    float mx = tot;
#pragma unroll
    for (int o = 16; o; o >>= 1) mx = fmaxf(mx, __shfl_xor_sync(0xffffffffu, mx, o));
    float ex = act ? expf(tot - mx) : 0.f;
#pragma unroll
    for (int o = 16; o; o >>= 1) ex += __shfl_xor_sync(0xffffffffu, ex, o);
    if (j == 0) logZ[b] = mx + logf(ex);
}

// ---------------- Viterbi ----------------
__global__ void viterbi_kernel(const float* __restrict__ feats, const int* __restrict__ amask,
                               const float* __restrict__ start, const float* __restrict__ endv,
                               const float* __restrict__ trans, int* __restrict__ tags) {
    __shared__ unsigned char hist[(Sdim - 1) * Ldim];
    int b = blockIdx.x;
    int j = threadIdx.x;
    bool act = j < Ldim;
    float tr[Ldim];
#pragma unroll
    for (int i = 0; i < Ldim; i++) tr[i] = act ? trans[i * Ldim + j] : 0.f;
    float score = act ? start[j] + feats[(size_t)(b * Sdim) * Ldim + j] : -1e30f;
    for (int t = 1; t < Sdim; t++) {
        float e = act ? feats[(size_t)(b * Sdim + t) * Ldim + j] : 0.f;
        int m = amask[b * Sdim + t];
        float best = -1e30f;
        int barg = 0;
#pragma unroll
        for (int i = 0; i < Ldim; i++) {
            float si = __shfl_sync(0xffffffffu, score, i);
            float v = si + tr[i];
            if (v > best) { best = v; barg = i; }
        }
        if (act) {
            hist[(t - 1) * Ldim + j] = (unsigned char)barg;
            float nxt = best + e;
            if (m > 0) score = nxt;
        }
    }
    __syncwarp();
    float tot = act ? score + endv[j] : -1e30f;
    float bb = tot;
    int bj = act ? j : 0;
#pragma unroll
    for (int o = 16; o; o >>= 1) {
        float ov = __shfl_down_sync(0xffffffffu, bb, o);
        int oj = __shfl_down_sync(0xffffffffu, bj, o);
        if (ov > bb) { bb = ov; bj = oj; }
    }
    if (j == 0) {
        int tag = bj;
        tags[b * Sdim + Sdim - 1] = tag;
        for (int t = Sdim - 2; t >= 0; t--) {
            tag = hist[t * Ldim + tag];
            tags[b * Sdim + t] = tag;
        }
    }
}

// ---------------- finalize ----------------
__global__ void finalize_kernel(const float* __restrict__ logZ, const float* __restrict__ num,
                                const int* __restrict__ tags, float* __restrict__ out,
                                int out_size) {
    int i = blockIdx.x * blockDim.x + threadIdx.x;
    if (i >= out_size) return;
    if (i == 0) {
        float s = 0.f;
        for (int b = 0; b < Bdim; b++) s += logZ[b] - num[b];
        out[0] = s * (1.f / Bdim);
    } else if (i - 1 < Bdim * Sdim) {
        out[i] = (float)tags[i - 1];
    } else {
        out[i] = 0.f;
    }
}

// ---------------- host launch ----------------
extern "C" void kernel_launch(void* const* d_in, const int* in_sizes, int n_in,
                              void* d_out, int out_size) {
    const float* word_emb = (const float*)d_in[0];
    const float* pos_emb  = (const float*)d_in[1];
    const float* type_emb = (const float*)d_in[2];
    const float* eln_s    = (const float*)d_in[3];
    const float* eln_b    = (const float*)d_in[4];
    const float* Wq = (const float*)d_in[5];
    const float* bq = (const float*)d_in[6];
    const float* Wk = (const float*)d_in[7];
    const float* bk = (const float*)d_in[8];
    const float* Wv = (const float*)d_in[9];
    const float* bv = (const float*)d_in[10];
    const float* Wo = (const float*)d_in[11];
    const float* bo = (const float*)d_in[12];
    const float* ln1s = (const float*)d_in[13];
    const float* ln1b = (const float*)d_in[14];
    const float* W1 = (const float*)d_in[15];
    const float* b1 = (const float*)d_in[16];
    const float* W2 = (const float*)d_in[17];
    const float* b2 = (const float*)d_in[18];
    const float* ln2s = (const float*)d_in[19];
    const float* ln2b = (const float*)d_in[20];
    const float* clfW = (const float*)d_in[21];
    const float* clfb = (const float*)d_in[22];
    const float* crf_start = (const float*)d_in[23];
    const float* crf_end   = (const float*)d_in[24];
    const float* crf_trans = (const float*)d_in[25];
    const int* input_ids   = (const int*)d_in[26];
    const int* token_type  = (const int*)d_in[27];
    const int* attn_mask   = (const int*)d_in[28];
    const int* labels      = (const int*)d_in[29];

    float *h, *q, *k, *v, *t, *feats, *logZ, *num;
    int* tags;
    __nv_bfloat16 *hext, *ctxext, *ffext;
    unsigned int *Wqp, *Wkp, *Wvp, *Wop, *W1p, *W2p;
    cudaGetSymbolAddress((void**)&h, g_h);
    cudaGetSymbolAddress((void**)&q, g_q);
    cudaGetSymbolAddress((void**)&k, g_k);
    cudaGetSymbolAddress((void**)&v, g_v);
    cudaGetSymbolAddress((void**)&t, g_t);
    cudaGetSymbolAddress((void**)&feats, g_feats);
    cudaGetSymbolAddress((void**)&logZ, g_logZ);
    cudaGetSymbolAddress((void**)&num, g_num);
    cudaGetSymbolAddress((void**)&tags, g_tags);
    cudaGetSymbolAddress((void**)&hext, g_hext);
    cudaGetSymbolAddress((void**)&ctxext, g_ctxext);
    cudaGetSymbolAddress((void**)&ffext, g_ffext);
    cudaGetSymbolAddress((void**)&Wqp, g_Wqp);
    cudaGetSymbolAddress((void**)&Wkp, g_Wkp);
    cudaGetSymbolAddress((void**)&Wvp, g_Wvp);
    cudaGetSymbolAddress((void**)&Wop, g_Wop);
    cudaGetSymbolAddress((void**)&W1p, g_W1p);
    cudaGetSymbolAddress((void**)&W2p, g_W2p);

    const int attn_smem = (64 * 512 + 64 * 64 + 64 * 64) * 4;
    cudaFuncSetAttribute(attn_kernel, cudaFuncAttributeMaxDynamicSharedMemorySize, attn_smem);
    cudaFuncSetAttribute(gemm_k1, cudaFuncAttributeMaxDynamicSharedMemorySize, GEMM_SMEM);
    cudaFuncSetAttribute(gemm_k3, cudaFuncAttributeMaxDynamicSharedMemorySize, GEMM_SMEM);

    // launches 1-5 (4 conv + embed), so ncu -s 5 -c 1 profiles the first gemm_k3
    convB2_kernel<<<4096, 256>>>(Wq, Wqp, Wk, Wkp, Hdim, Hdim, NLnum);
    convB2_kernel<<<4096, 256>>>(Wv, Wvp, Wo, Wop, Hdim, Hdim, NLnum);
    convB_kernel<<<4096, 256>>>(W1, W1p, Hdim, FFdim, NLnum);
    convB_kernel<<<4096, 256>>>(W2, W2p, FFdim, Hdim, NLnum);
    embed_ln_kernel<<<Mtot, 256>>>(word_emb, pos_emb, type_emb, eln_s, eln_b,
                                   input_ids, token_type, h, hext);

    dim3 gQKV(Hdim / BN, Mtot / BM, 3);
    dim3 gProj(Hdim / BN, Mtot / BM);
    dim3 gFF1(FFdim / BN, Mtot / BM);
    dim3 gAttn(Sdim / 64, NHnum, Bdim);
    const size_t woff = (size_t)PKH * Hdim;
    const size_t w1off = (size_t)PKH * FFdim;
    const size_t w2off = (size_t)PKF * Hdim;

    for (int l = 0; l < NLnum; l++) {
        gemm_k3<<<gQKV, 256, GEMM_SMEM>>>(hext, Wqp + l * woff, Wkp + l * woff, Wvp + l * woff,
                                          bq + l * Hdim, bk + l * Hdim, bv + l * Hdim,
                                          q, k, v, KE_H);
        attn_kernel<<<gAttn, 256, attn_smem>>>(q, k, v, attn_mask, ctxext);
        gemm_k1<<<gProj, 256, GEMM_SMEM>>>(ctxext, Wop + l * woff, bo + l * Hdim, h, t,
                                           nullptr, Hdim, KE_H, 0, 1, 0);
        ln_kernel<<<Mtot, 256>>>(t, ln1s + l * Hdim, ln1b + l * Hdim, h, hext);
        gemm_k1<<<gFF1, 256, GEMM_SMEM>>>(hext, W1p + l * w1off, b1 + l * FFdim, nullptr,
                                          nullptr, ffext, FFdim, KE_H, 1, 0, 1);
        gemm_k1<<<gProj, 256, GEMM_SMEM>>>(ffext, W2p + l * w2off, b2 + l * Hdim, h, t,
                                           nullptr, Hdim, KE_FF, 0, 1, 0);
        ln_kernel<<<Mtot, 256>>>(t, ln2s + l * Hdim, ln2b + l * Hdim, h, hext);
    }

    clf_kernel<<<Mtot, 256>>>(h, clfW, clfb, feats);
    crf_num_kernel<<<Bdim, 256>>>(feats, attn_mask, labels, crf_start, crf_end, crf_trans, num);
    crf_fwd_kernel<<<1, 256>>>(feats, attn_mask, crf_start, crf_end, crf_trans, logZ);
    viterbi_kernel<<<Bdim, 32>>>(feats, attn_mask, crf_start, crf_end, crf_trans, tags);

    int nfin = (out_size + 255) / 256;
    if (nfin < 1) nfin = 1;
    finalize_kernel<<<nfin, 256>>>(logZ, num, tags, (float*)d_out, out_size);
}

// round 10
// speedup vs baseline: 1.0041x; 1.0041x over previous
#include <cuda_runtime.h>
#include <cuda_bf16.h>
#include <math.h>

#define Mtot  4096
#define Hdim  768
#define FFdim 3072
#define NHnum 12
#define DHdim 64
#define Sdim  512
#define Bdim  8
#define Ldim  9
#define NLnum 12

#define KE_H  (3 * Hdim)    // 2304
#define KE_FF (3 * FFdim)   // 9216

// ---------------- scratch (static device allocations) ----------------
__device__ float g_h[Mtot * Hdim];
__device__ float g_q[Mtot * Hdim];
__device__ float g_k[Mtot * Hdim];
__device__ float g_v[Mtot * Hdim];
__device__ float g_t[Mtot * Hdim];
__device__ float g_feats[Mtot * Ldim];
__device__ float g_logZ[Bdim];
__device__ float g_num[Bdim];
__device__ int   g_tags[Bdim * Sdim];

// split-bf16 ext activations (A operands): [M][3K], slots per k: ah, al, ah
__device__ __align__(256) __nv_bfloat16 g_hext[Mtot * KE_H];
__device__ __align__(256) __nv_bfloat16 g_ctxext[Mtot * KE_H];
__device__ __align__(256) __nv_bfloat16 g_ffext[(size_t)Mtot * KE_FF];

// packed split-bf16 weights (B operands): [3K/2][N] u32, pair=(ext row 2i, 2i+1)
// slots per k: bh, bh, bl
#define PKH (3 * Hdim / 2)    // 1152
#define PKF (3 * FFdim / 2)   // 4608
__device__ __align__(256) unsigned int g_Wqp[NLnum * PKH * Hdim];
__device__ __align__(256) unsigned int g_Wkp[NLnum * PKH * Hdim];
__device__ __align__(256) unsigned int g_Wvp[NLnum * PKH * Hdim];
__device__ __align__(256) unsigned int g_Wop[NLnum * PKH * Hdim];
__device__ __align__(256) unsigned int g_W1p[(size_t)NLnum * PKH * FFdim];
__device__ __align__(256) unsigned int g_W2p[(size_t)NLnum * PKF * Hdim];

// ---------------- helpers ----------------
__device__ __forceinline__ float blk_sum256(float v, float* red) {
    int lane = threadIdx.x & 31, w = threadIdx.x >> 5;
#pragma unroll
    for (int o = 16; o; o >>= 1) v += __shfl_xor_sync(0xffffffffu, v, o);
    __syncthreads();
    if (lane == 0) red[w] = v;
    __syncthreads();
    float s = 0.f;
#pragma unroll
    for (int i = 0; i < 8; i++) s += red[i];
    return s;
}

__device__ __forceinline__ void split2(float x, __nv_bfloat16& hi, __nv_bfloat16& lo) {
    hi = __float2bfloat16(x);
    lo = __float2bfloat16(x - __bfloat162float(hi));
}

__device__ __forceinline__ void write_ext3(__nv_bfloat16* p, float x) {
    __nv_bfloat16 h, l;
    split2(x, h, l);
    p[0] = h; p[1] = l; p[2] = h;   // A-ext slots: ah, al, ah
}

// fast exp on the FMA pipe (no MUFU)
__device__ __forceinline__ float fexp(float x) {
    float t = x * 1.4426950408889634f;
    t = fmaxf(t, -126.0f);
    float fl = floorf(t);
    float f = t - fl;
    float p = 1.525273e-5f;
    p = fmaf(p, f, 1.5403530e-4f);
    p = fmaf(p, f, 1.3333558e-3f);
    p = fmaf(p, f, 9.6181291e-3f);
    p = fmaf(p, f, 5.5504109e-2f);
    p = fmaf(p, f, 2.4022651e-1f);
    p = fmaf(p, f, 6.9314718e-1f);
    p = fmaf(p, f, 1.0f);
    return p * __int_as_float(((int)fl + 127) << 23);
}

// ---------------- weight conversion: fp32 [L][K][N] -> packed [L][3K/2][N] u32 ---
__device__ __forceinline__ unsigned int packw(const float* __restrict__ W, int K, int N,
                                              int l, int i, int n) {
    int s0 = 2 * i, s1 = 2 * i + 1;
    int k0 = s0 / 3, r0 = s0 % 3;
    int k1 = s1 / 3, r1 = s1 % 3;
    float w0 = W[((size_t)l * K + k0) * N + n];
    float w1 = W[((size_t)l * K + k1) * N + n];
    __nv_bfloat16 h0, l0, h1, l1;
    split2(w0, h0, l0);
    split2(w1, h1, l1);
    __nv_bfloat16 v0 = (r0 == 2) ? l0 : h0;   // B-ext slots: bh, bh, bl
    __nv_bfloat16 v1 = (r1 == 2) ? l1 : h1;
    __nv_bfloat162 pr(v0, v1);
    return *reinterpret_cast<unsigned int*>(&pr);
}

__global__ void convB_kernel(const float* __restrict__ W, unsigned int* __restrict__ out,
                             int K, int N, int L) {
    size_t PK = (size_t)3 * K / 2;
    size_t total = (size_t)L * PK * N;
    for (size_t idx = (size_t)blockIdx.x * blockDim.x + threadIdx.x; idx < total;
         idx += (size_t)gridDim.x * blockDim.x) {
        int n = (int)(idx % N);
        size_t rest = idx / N;
        int i = (int)(rest % PK);
        int l = (int)(rest / PK);
        out[idx] = packw(W, K, N, l, i, n);
    }
}

// two same-shape tensors in one launch (cuts launch count so ncu hits the GEMM)
__global__ void convB2_kernel(const float* __restrict__ Wa, unsigned int* __restrict__ outa,
                              const float* __restrict__ Wb, unsigned int* __restrict__ outb,
                              int K, int N, int L) {
    size_t PK = (size_t)3 * K / 2;
    size_t total = (size_t)L * PK * N;
    for (size_t idx = (size_t)blockIdx.x * blockDim.x + threadIdx.x; idx < 2 * total;
         idx += (size_t)gridDim.x * blockDim.x) {
        const float* W = (idx < total) ? Wa : Wb;
        unsigned int* out = (idx < total) ? outa : outb;
        size_t j = (idx < total) ? idx : idx - total;
        int n = (int)(j % N);
        size_t rest = j / N;
        int i = (int)(rest % PK);
        int l = (int)(rest / PK);
        out[j] = packw(W, K, N, l, i, n);
    }
}

// ---------------- embedding + LayerNorm ----------------
__global__ void embed_ln_kernel(const float* __restrict__ we, const float* __restrict__ pe,
                                const float* __restrict__ te, const float* __restrict__ gs,
                                const float* __restrict__ gb, const int* __restrict__ ids,
                                const int* __restrict__ tts, float* __restrict__ out,
                                __nv_bfloat16* __restrict__ ext) {
    __shared__ float red[8];
    int m = blockIdx.x;
    int s = m & (Sdim - 1);
    int id = ids[m], tt = tts[m];
    float vals[3];
    float lsum = 0.f;
#pragma unroll
    for (int u = 0; u < 3; u++) {
        int j = threadIdx.x + u * 256;
        float v = we[(size_t)id * Hdim + j] + pe[(size_t)s * Hdim + j] + te[(size_t)tt * Hdim + j];
        vals[u] = v;
        lsum += v;
    }
    float mean = blk_sum256(lsum, red) * (1.f / Hdim);
    float lsq = 0.f;
#pragma unroll
    for (int u = 0; u < 3; u++) { float d = vals[u] - mean; lsq += d * d; }
    float var = blk_sum256(lsq, red) * (1.f / Hdim);
    float inv = rsqrtf(var + 1e-12f);
#pragma unroll
    for (int u = 0; u < 3; u++) {
        int j = threadIdx.x + u * 256;
        float y = (vals[u] - mean) * inv * gs[j] + gb[j];
        out[(size_t)m * Hdim + j] = y;
        write_ext3(ext + (size_t)m * KE_H + 3 * j, y);
    }
}

// ---------------- LayerNorm ----------------
__global__ void ln_kernel(const float* __restrict__ x, const float* __restrict__ gs,
                          const float* __restrict__ gb, float* __restrict__ y,
                          __nv_bfloat16* __restrict__ ext) {
    __shared__ float red[8];
    int m = blockIdx.x;
    const float* xr = x + (size_t)m * Hdim;
    float vals[3];
    float lsum = 0.f;
#pragma unroll
    for (int u = 0; u < 3; u++) {
        vals[u] = xr[threadIdx.x + u * 256];
        lsum += vals[u];
    }
    float mean = blk_sum256(lsum, red) * (1.f / Hdim);
    float lsq = 0.f;
#pragma unroll
    for (int u = 0; u < 3; u++) { float d = vals[u] - mean; lsq += d * d; }
    float var = blk_sum256(lsq, red) * (1.f / Hdim);
    float inv = rsqrtf(var + 1e-12f);
#pragma unroll
    for (int u = 0; u < 3; u++) {
        int j = threadIdx.x + u * 256;
        float yy = (vals[u] - mean) * inv * gs[j] + gb[j];
        y[(size_t)m * Hdim + j] = yy;
        write_ext3(ext + (size_t)m * KE_H + 3 * j, yy);
    }
}

// ================= tensor-core GEMM (split-bf16, K extended 3x) =================
// 2 CTAs/SM: BKE=48, 4 stages, 107KB smem/CTA
#define BM 128
#define BN 128
#define BKE 48                 // ext bf16 k per tile
#define BKP 24                 // packed pair-rows per tile
#define AS_STRIDE 28           // u32 words per A smem row (24 data + 4 pad)
#define BS_STRIDE 136          // u32 words per B smem row (128 data + 8 pad)
#define STAGE_WORDS (128 * AS_STRIDE + BKP * BS_STRIDE)  // 6848
#define NSTAGE 4
#define GEMM_SMEM (NSTAGE * STAGE_WORDS * 4)             // 109568 B

__device__ __forceinline__ void cp16(unsigned int saddr, const void* gptr) {
    asm volatile("cp.async.cg.shared.global [%0], [%1], 16;\n" ::"r"(saddr), "l"(gptr));
}
__device__ __forceinline__ void cp_commit() { asm volatile("cp.async.commit_group;\n"); }
__device__ __forceinline__ void cp_wait2() { asm volatile("cp.async.wait_group 2;\n"); }

#define MMA16816(d, a, b)                                                      \
    asm volatile(                                                              \
        "mma.sync.aligned.m16n8k16.row.col.f32.bf16.bf16.f32 "                 \
        "{%0,%1,%2,%3}, {%4,%5,%6,%7}, {%8,%9}, {%0,%1,%2,%3};\n"              \
        : "+f"(d[0]), "+f"(d[1]), "+f"(d[2]), "+f"(d[3])                       \
        : "r"(a[0]), "r"(a[1]), "r"(a[2]), "r"(a[3]), "r"(b[0]), "r"(b[1]))

__device__ __forceinline__ void gemm_core(const __nv_bfloat16* __restrict__ A,
                                          const unsigned int* __restrict__ B,
                                          const float* __restrict__ bias,
                                          const float* __restrict__ res,
                                          float* __restrict__ Cf,
                                          __nv_bfloat16* __restrict__ Ce,
                                          int N, int KE, int act, int addres, int outp,
                                          unsigned int* smem) {
    const int tid = threadIdx.x;
    const int lane = tid & 31;
    const int wid = tid >> 5;
    const int warp_m = wid >> 2;   // 0..1
    const int warp_n = wid & 3;    // 0..3
    const int m0 = blockIdx.y * BM;
    const int n0 = blockIdx.x * BN;
    const int T = KE / BKE;
    const int g = lane >> 2, t4 = lane & 3;

    float acc[4][4][4];
#pragma unroll
    for (int i = 0; i < 4; i++)
#pragma unroll
        for (int j = 0; j < 4; j++)
#pragma unroll
            for (int r = 0; r < 4; r++) acc[i][j][r] = 0.f;

    const unsigned int sbase = (unsigned int)__cvta_generic_to_shared(smem);

    auto load_stage = [&](int tile, int stg) {
        unsigned int abase = sbase + (unsigned int)(stg * STAGE_WORDS) * 4u;
        unsigned int bbase = abase + 128u * AS_STRIDE * 4u;
        const __nv_bfloat16* Ag = A + (size_t)m0 * KE + tile * BKE;
#pragma unroll
        for (int l = 0; l < 3; l++) {
            int i = tid + l * 256;
            int r = i / 6, c = i % 6;                // 128 rows x 6 chunks(16B)
            cp16(abase + (unsigned int)(r * AS_STRIDE + c * 4) * 4u,
                 Ag + (size_t)r * KE + c * 8);
        }
        const unsigned int* Bg = B + (size_t)(tile * BKP) * N + n0;
#pragma unroll
        for (int l = 0; l < 3; l++) {
            int i = tid + l * 256;
            int r = i / 32, c = i % 32;              // 24 rows x 32 chunks(16B)
            cp16(bbase + (unsigned int)(r * BS_STRIDE + c * 4) * 4u,
                 Bg + (size_t)r * N + c * 4);
        }
    };

    load_stage(0, 0); cp_commit();
    load_stage(1, 1); cp_commit();
    load_stage(2, 2); cp_commit();

    for (int t = 0; t < T; t++) {
        cp_wait2();
        __syncthreads();
        if (t + 3 < T) load_stage(t + 3, (t + 3) & 3);
        cp_commit();   // always commit (possibly empty) so wait_group maps to tiles

        const unsigned int* As = smem + (size_t)(t & 3) * STAGE_WORDS;
        const unsigned int* Bs = As + 128 * AS_STRIDE;
#pragma unroll
        for (int s = 0; s < 3; s++) {
            unsigned int a[4][4], b[4][2];
#pragma unroll
            for (int mi = 0; mi < 4; mi++) {
                int r = warp_m * 64 + mi * 16 + g;
                int cp = s * 8 + t4;
                a[mi][0] = As[r * AS_STRIDE + cp];
                a[mi][1] = As[(r + 8) * AS_STRIDE + cp];
                a[mi][2] = As[r * AS_STRIDE + cp + 4];
                a[mi][3] = As[(r + 8) * AS_STRIDE + cp + 4];
            }
#pragma unroll
            for (int nj = 0; nj < 4; nj++) {
                int n = warp_n * 32 + nj * 8 + g;
                b[nj][0] = Bs[(s * 8 + t4) * BS_STRIDE + n];
                b[nj][1] = Bs[(s * 8 + t4 + 4) * BS_STRIDE + n];
            }
#pragma unroll
            for (int mi = 0; mi < 4; mi++)
#pragma unroll
                for (int nj = 0; nj < 4; nj++) MMA16816(acc[mi][nj], a[mi], b[nj]);
        }
        __syncthreads();
    }

    // ---- epilogue ----
#pragma unroll
    for (int mi = 0; mi < 4; mi++) {
        int row0 = m0 + warp_m * 64 + mi * 16 + g;
#pragma unroll
        for (int nj = 0; nj < 4; nj++) {
            int col = n0 + warp_n * 32 + nj * 8 + t4 * 2;
            float b0 = bias[col], b1 = bias[col + 1];
#pragma unroll
            for (int half = 0; half < 2; half++) {
                int row = row0 + half * 8;
                float v0 = acc[mi][nj][half * 2 + 0] + b0;
                float v1 = acc[mi][nj][half * 2 + 1] + b1;
                if (addres) {
                    float2 rr = *(const float2*)(res + (size_t)row * N + col);
                    v0 += rr.x;
                    v1 += rr.y;
                }
                if (act) {
                    v0 = 0.5f * v0 * (1.f + erff(v0 * 0.70710678118654752440f));
                    v1 = 0.5f * v1 * (1.f + erff(v1 * 0.70710678118654752440f));
                }
                if (outp == 0) {
                    *(float2*)(Cf + (size_t)row * N + col) = make_float2(v0, v1);
                } else {
                    __nv_bfloat16* p = Ce + (size_t)row * (3 * N) + 3 * col;
                    write_ext3(p, v0);
                    write_ext3(p + 3, v1);
                }
            }
        }
    }
}

__global__ void __launch_bounds__(256, 2) gemm_k1(const __nv_bfloat16* __restrict__ A,
                                                  const unsigned int* __restrict__ B,
                                                  const float* __restrict__ bias,
                                                  const float* __restrict__ res,
                                                  float* __restrict__ Cf,
                                                  __nv_bfloat16* __restrict__ Ce,
                                                  int N, int KE, int act, int addres, int outp) {
    extern __shared__ unsigned int smem[];
    gemm_core(A, B, bias, res, Cf, Ce, N, KE, act, addres, outp, smem);
}

__global__ void __launch_bounds__(256, 2) gemm_k3(const __nv_bfloat16* __restrict__ A,
                                                  const unsigned int* __restrict__ B0,
                                                  const unsigned int* __restrict__ B1,
                                                  const unsigned int* __restrict__ B2,
                                                  const float* __restrict__ bias0,
                                                  const float* __restrict__ bias1,
                                                  const float* __restrict__ bias2,
                                                  float* __restrict__ C0, float* __restrict__ C1,
                                                  float* __restrict__ C2, int KE) {
    extern __shared__ unsigned int smem[];
    int z = blockIdx.z;
    const unsigned int* B = (z == 0) ? B0 : (z == 1) ? B1 : B2;
    const float* bias = (z == 0) ? bias0 : (z == 1) ? bias1 : bias2;
    float* Cf = (z == 0) ? C0 : (z == 1) ? C1 : C2;
    gemm_core(A, B, bias, nullptr, Cf, nullptr, Hdim, KE, 0, 0, 0, smem);
}

// ---------------- attention (fp32 SIMT; fast exp; epilogue emits split-bf16 ext) --------
__global__ void __launch_bounds__(256) attn_kernel(const float* __restrict__ Q,
                                                   const float* __restrict__ Kp,
                                                   const float* __restrict__ Vp,
                                                   const int* __restrict__ amask,
                                                   __nv_bfloat16* __restrict__ Oext) {
    extern __shared__ float sm[];
    float* sc = sm;
    float* qT = sm + 64 * 512;
    float* kT = qT + 64 * 64;
    const int tid = threadIdx.x;
    const int q0 = blockIdx.x * 64;
    const int h = blockIdx.y;
    const int b = blockIdx.z;
    const size_t base = (size_t)b * Sdim * Hdim + h * 64;
    const int ty = tid >> 4, tx = tid & 15;

    for (int i = tid; i < 1024; i += 256) {
        int r = i >> 4, c4 = i & 15;
        float4 v = *(const float4*)(Q + base + (size_t)(q0 + r) * Hdim + c4 * 4);
        qT[(c4 * 4 + 0) * 64 + r] = v.x;
        qT[(c4 * 4 + 1) * 64 + r] = v.y;
        qT[(c4 * 4 + 2) * 64 + r] = v.z;
        qT[(c4 * 4 + 3) * 64 + r] = v.w;
    }

    for (int kt = 0; kt < 8; kt++) {
        int k0 = kt * 64;
        __syncthreads();
        for (int i = tid; i < 1024; i += 256) {
            int r = i >> 4, c4 = i & 15;
            float4 v = *(const float4*)(Kp + base + (size_t)(k0 + r) * Hdim + c4 * 4);
            kT[(c4 * 4 + 0) * 64 + r] = v.x;
            kT[(c4 * 4 + 1) * 64 + r] = v.y;
            kT[(c4 * 4 + 2) * 64 + r] = v.z;
            kT[(c4 * 4 + 3) * 64 + r] = v.w;
        }
        __syncthreads();
        float acc[4][4];
#pragma unroll
        for (int i = 0; i < 4; i++)
#pragma unroll
            for (int j = 0; j < 4; j++) acc[i][j] = 0.f;
        for (int d = 0; d < 64; d++) {
            float a[4], bb[4];
            *(float4*)a = *(const float4*)(&qT[d * 64 + ty * 4]);
            *(float4*)bb = *(const float4*)(&kT[d * 64 + tx * 4]);
#pragma unroll
            for (int i = 0; i < 4; i++)
#pragma unroll
                for (int j = 0; j < 4; j++) acc[i][j] += a[i] * bb[j];
        }
#pragma unroll
        for (int i = 0; i < 4; i++) {
            float4 v = make_float4(acc[i][0], acc[i][1], acc[i][2], acc[i][3]);
            *(float4*)(&sc[(ty * 4 + i) * 512 + k0 + tx * 4]) = v;
        }
    }
    __syncthreads();

    {
        int row = tid >> 2, lane = tid & 3;
        float mx = -1e30f;
        for (int k = lane; k < 512; k += 4) {
            float mb = (1.f - (float)amask[b * Sdim + k]) * -10000.f;
            float v = sc[row * 512 + k] * 0.125f + mb;
            sc[row * 512 + k] = v;
            mx = fmaxf(mx, v);
        }
        mx = fmaxf(mx, __shfl_xor_sync(0xffffffffu, mx, 1, 4));
        mx = fmaxf(mx, __shfl_xor_sync(0xffffffffu, mx, 2, 4));
        float sum = 0.f;
        for (int k = lane; k < 512; k += 4) {
            float e = fexp(sc[row * 512 + k] - mx);
            sc[row * 512 + k] = e;
            sum += e;
        }
        sum += __shfl_xor_sync(0xffffffffu, sum, 1, 4);
        sum += __shfl_xor_sync(0xffffffffu, sum, 2, 4);
        float inv = 1.f / sum;
        for (int k = lane; k < 512; k += 4) sc[row * 512 + k] *= inv;
    }

    float acc[4][4];
#pragma unroll
    for (int i = 0; i < 4; i++)
#pragma unroll
        for (int j = 0; j < 4; j++) acc[i][j] = 0.f;
    for (int kt = 0; kt < 8; kt++) {
        int k0 = kt * 64;
        __syncthreads();
        for (int i = tid; i < 1024; i += 256) {
            int r = i >> 4, c4 = i & 15;
            float4 v = *(const float4*)(Vp + base + (size_t)(k0 + r) * Hdim + c4 * 4);
            *(float4*)(&kT[r * 64 + c4 * 4]) = v;
        }
        __syncthreads();
        for (int kk = 0; kk < 64; kk++) {
            float bb[4];
            *(float4*)bb = *(const float4*)(&kT[kk * 64 + tx * 4]);
            float p0 = sc[(ty * 4 + 0) * 512 + k0 + kk];
            float p1 = sc[(ty * 4 + 1) * 512 + k0 + kk];
            float p2 = sc[(ty * 4 + 2) * 512 + k0 + kk];
            float p3 = sc[(ty * 4 + 3) * 512 + k0 + kk];
#pragma unroll
            for (int j = 0; j < 4; j++) {
                acc[0][j] += p0 * bb[j];
                acc[1][j] += p1 * bb[j];
                acc[2][j] += p2 * bb[j];
                acc[3][j] += p3 * bb[j];
            }
        }
    }
#pragma unroll
    for (int i = 0; i < 4; i++) {
        int m = b * Sdim + q0 + ty * 4 + i;
        int colbase = h * 64 + tx * 4;
        __nv_bfloat16* p = Oext + (size_t)m * KE_H + 3 * colbase;
#pragma unroll
        for (int j = 0; j < 4; j++) write_ext3(p + 3 * j, acc[i][j]);
    }
}

// ---------------- classifier ----------------
__global__ void clf_kernel(const float* __restrict__ X, const float* __restrict__ W,
                           const float* __restrict__ bias, float* __restrict__ F) {
    __shared__ float red[8][Ldim];
    int m = blockIdx.x;
    int tid = threadIdx.x;
    float acc[Ldim];
#pragma unroll
    for (int j = 0; j < Ldim; j++) acc[j] = 0.f;
    for (int k = tid; k < Hdim; k += 256) {
        float x = X[(size_t)m * Hdim + k];
#pragma unroll
        for (int j = 0; j < Ldim; j++) acc[j] += x * W[k * Ldim + j];
    }
    int lane = tid & 31, w = tid >> 5;
#pragma unroll
    for (int j = 0; j < Ldim; j++)
#pragma unroll
        for (int o = 16; o; o >>= 1) acc[j] += __shfl_down_sync(0xffffffffu, acc[j], o);
    if (lane == 0)
#pragma unroll
        for (int j = 0; j < Ldim; j++) red[w][j] = acc[j];
    __syncthreads();
    if (tid < Ldim) {
        float s = bias[tid];
#pragma unroll
        for (int ww = 0; ww < 8; ww++) s += red[ww][tid];
        F[(size_t)m * Ldim + tid] = s;
    }
}

// ---------------- CRF numerator ----------------
__global__ void crf_num_kernel(const float* __restrict__ feats, const int* __restrict__ amask,
                               const int* __restrict__ labels, const float* __restrict__ start,
                               const float* __restrict__ endv, const float* __restrict__ trans,
                               float* __restrict__ num) {
    __shared__ float red[8];
    int b = blockIdx.x;
    int tid = threadIdx.x;
    float s = 0.f, msum = 0.f;
    for (int t = tid; t < Sdim; t += 256) {
        int tag = labels[b * Sdim + t];
        float em = feats[(size_t)(b * Sdim + t) * Ldim + tag];
        float m = (float)amask[b * Sdim + t];
        msum += m;
        if (t == 0) {
            s += start[tag] + em;
        } else {
            int pt = labels[b * Sdim + t - 1];
            s += (em + trans[pt * Ldim + tag]) * m;
        }
    }
    float stotal = blk_sum256(s, red);
    float mtotal = blk_sum256(msum, red);
    if (tid == 0) {
        int last = (int)(mtotal + 0.5f) - 1;
        num[b] = stotal + endv[labels[b * Sdim + last]];
    }
}

// ---------------- CRF forward ----------------
__global__ void crf_fwd_kernel(const float* __restrict__ feats, const int* __restrict__ amask,
                               const float* __restrict__ start, const float* __restrict__ endv,
                               const float* __restrict__ trans, float* __restrict__ logZ) {
    int b = threadIdx.x >> 5;
    int j = threadIdx.x & 31;
    bool act = j < Ldim;
    float tr[Ldim];
#pragma unroll
    for (int i = 0; i < Ldim; i++) tr[i] = act ? trans[i * Ldim + j] : 0.f;
    float score = act ? start[j] + feats[(size_t)(b * Sdim) * Ldim + j] : -1e30f;
    for (int t = 1; t < Sdim; t++) {
        float e = act ? feats[(size_t)(b * Sdim + t) * Ldim + j] : 0.f;
        int m = amask[b * Sdim + t];
        float v[Ldim];
        float mx = -1e30f;
#pragma unroll
        for (int i = 0; i < Ldim; i++) {
            float si = __shfl_sync(0xffffffffu, score, i);
            v[i] = si + tr[i];
            mx = fmaxf(mx, v[i]);
        }
        float ssum = 0.f;
#pragma unroll
        for (int i = 0; i < Ldim; i++) ssum += expf(v[i] - mx);
        float nxt = mx + logf(ssum) + e;
        if (act && m > 0) score = nxt;
    }
    float tot = act ? score + endv[j] : -1e30f;
    float mx = tot;
#pragma unroll
    for (int o = 16; o; o >>= 1) mx = fmaxf(mx, __shfl_xor_sync(0xffffffffu, mx, o));
    float ex = act ? expf(tot - mx) : 0.f;
#pragma unroll
    for (int o = 16; o; o >>= 1) ex += __shfl_xor_sync(0xffffffffu, ex, o);
    if (j == 0) logZ[b] = mx + logf(ex);
}

// ---------------- Viterbi ----------------
__global__ void viterbi_kernel(const float* __restrict__ feats, const int* __restrict__ amask,
                               const float* __restrict__ start, const float* __restrict__ endv,
                               const float* __restrict__ trans, int* __restrict__ tags) {
    __shared__ unsigned char hist[(Sdim - 1) * Ldim];
    int b = blockIdx.x;
    int j = threadIdx.x;
    bool act = j < Ldim;
    float tr[Ldim];
#pragma unroll
    for (int i = 0; i < Ldim; i++) tr[i] = act ? trans[i * Ldim + j] : 0.f;
    float score = act ? start[j] + feats[(size_t)(b * Sdim) * Ldim + j] : -1e30f;
    for (int t = 1; t < Sdim; t++) {
        float e = act ? feats[(size_t)(b * Sdim + t) * Ldim + j] : 0.f;
        int m = amask[b * Sdim + t];
        float best = -1e30f;
        int barg = 0;
#pragma unroll
        for (int i = 0; i < Ldim; i++) {
            float si = __shfl_sync(0xffffffffu, score, i);
            float v = si + tr[i];
            if (v > best) { best = v; barg = i; }
        }
        if (act) {
            hist[(t - 1) * Ldim + j] = (unsigned char)barg;
            float nxt = best + e;
            if (m > 0) score = nxt;
        }
    }
    __syncwarp();
    float tot = act ? score + endv[j] : -1e30f;
    float bb = tot;
    int bj = act ? j : 0;
#pragma unroll
    for (int o = 16; o; o >>= 1) {
        float ov = __shfl_down_sync(0xffffffffu, bb, o);
        int oj = __shfl_down_sync(0xffffffffu, bj, o);
        if (ov > bb) { bb = ov; bj = oj; }
    }
    if (j == 0) {
        int tag = bj;
        tags[b * Sdim + Sdim - 1] = tag;
        for (int t = Sdim - 2; t >= 0; t--) {
            tag = hist[t * Ldim + tag];
            tags[b * Sdim + t] = tag;
        }
    }
}

// ---------------- finalize ----------------
__global__ void finalize_kernel(const float* __restrict__ logZ, const float* __restrict__ num,
                                const int* __restrict__ tags, float* __restrict__ out,
                                int out_size) {
    int i = blockIdx.x * blockDim.x + threadIdx.x;
    if (i >= out_size) return;
    if (i == 0) {
        float s = 0.f;
        for (int b = 0; b < Bdim; b++) s += logZ[b] - num[b];
        out[0] = s * (1.f / Bdim);
    } else if (i - 1 < Bdim * Sdim) {
        out[i] = (float)tags[i - 1];
    } else {
        out[i] = 0.f;
    }
}

// ---------------- host launch ----------------
extern "C" void kernel_launch(void* const* d_in, const int* in_sizes, int n_in,
                              void* d_out, int out_size) {
    const float* word_emb = (const float*)d_in[0];
    const float* pos_emb  = (const float*)d_in[1];
    const float* type_emb = (const float*)d_in[2];
    const float* eln_s    = (const float*)d_in[3];
    const float* eln_b    = (const float*)d_in[4];
    const float* Wq = (const float*)d_in[5];
    const float* bq = (const float*)d_in[6];
    const float* Wk = (const float*)d_in[7];
    const float* bk = (const float*)d_in[8];
    const float* Wv = (const float*)d_in[9];
    const float* bv = (const float*)d_in[10];
    const float* Wo = (const float*)d_in[11];
    const float* bo = (const float*)d_in[12];
    const float* ln1s = (const float*)d_in[13];
    const float* ln1b = (const float*)d_in[14];
    const float* W1 = (const float*)d_in[15];
    const float* b1 = (const float*)d_in[16];
    const float* W2 = (const float*)d_in[17];
    const float* b2 = (const float*)d_in[18];
    const float* ln2s = (const float*)d_in[19];
    const float* ln2b = (const float*)d_in[20];
    const float* clfW = (const float*)d_in[21];
    const float* clfb = (const float*)d_in[22];
    const float* crf_start = (const float*)d_in[23];
    const float* crf_end   = (const float*)d_in[24];
    const float* crf_trans = (const float*)d_in[25];
    const int* input_ids   = (const int*)d_in[26];
    const int* token_type  = (const int*)d_in[27];
    const int* attn_mask   = (const int*)d_in[28];
    const int* labels      = (const int*)d_in[29];

    float *h, *q, *k, *v, *t, *feats, *logZ, *num;
    int* tags;
    __nv_bfloat16 *hext, *ctxext, *ffext;
    unsigned int *Wqp, *Wkp, *Wvp, *Wop, *W1p, *W2p;
    cudaGetSymbolAddress((void**)&h, g_h);
    cudaGetSymbolAddress((void**)&q, g_q);
    cudaGetSymbolAddress((void**)&k, g_k);
    cudaGetSymbolAddress((void**)&v, g_v);
    cudaGetSymbolAddress((void**)&t, g_t);
    cudaGetSymbolAddress((void**)&feats, g_feats);
    cudaGetSymbolAddress((void**)&logZ, g_logZ);
    cudaGetSymbolAddress((void**)&num, g_num);
    cudaGetSymbolAddress((void**)&tags, g_tags);
    cudaGetSymbolAddress((void**)&hext, g_hext);
    cudaGetSymbolAddress((void**)&ctxext, g_ctxext);
    cudaGetSymbolAddress((void**)&ffext, g_ffext);
    cudaGetSymbolAddress((void**)&Wqp, g_Wqp);
    cudaGetSymbolAddress((void**)&Wkp, g_Wkp);
    cudaGetSymbolAddress((void**)&Wvp, g_Wvp);
    cudaGetSymbolAddress((void**)&Wop, g_Wop);
    cudaGetSymbolAddress((void**)&W1p, g_W1p);
    cudaGetSymbolAddress((void**)&W2p, g_W2p);

    const int attn_smem = (64 * 512 + 64 * 64 + 64 * 64) * 4;
    cudaFuncSetAttribute(attn_kernel, cudaFuncAttributeMaxDynamicSharedMemorySize, attn_smem);
    cudaFuncSetAttribute(gemm_k1, cudaFuncAttributeMaxDynamicSharedMemorySize, GEMM_SMEM);
    cudaFuncSetAttribute(gemm_k3, cudaFuncAttributeMaxDynamicSharedMemorySize, GEMM_SMEM);

    // launches 1-5 (4 conv + embed), so ncu -s 5 -c 1 profiles the first gemm_k3
    convB2_kernel<<<4096, 256>>>(Wq, Wqp, Wk, Wkp, Hdim, Hdim, NLnum);
    convB2_kernel<<<4096, 256>>>(Wv, Wvp, Wo, Wop, Hdim, Hdim, NLnum);
    convB_kernel<<<4096, 256>>>(W1, W1p, Hdim, FFdim, NLnum);
    convB_kernel<<<4096, 256>>>(W2, W2p, FFdim, Hdim, NLnum);
    embed_ln_kernel<<<Mtot, 256>>>(word_emb, pos_emb, type_emb, eln_s, eln_b,
                                   input_ids, token_type, h, hext);

    dim3 gQKV(Hdim / BN, Mtot / BM, 3);
    dim3 gProj(Hdim / BN, Mtot / BM);
    dim3 gFF1(FFdim / BN, Mtot / BM);
    dim3 gAttn(Sdim / 64, NHnum, Bdim);
    const size_t woff = (size_t)PKH * Hdim;
    const size_t w1off = (size_t)PKH * FFdim;
    const size_t w2off = (size_t)PKF * Hdim;

    for (int l = 0; l < NLnum; l++) {
        gemm_k3<<<gQKV, 256, GEMM_SMEM>>>(hext, Wqp + l * woff, Wkp + l * woff, Wvp + l * woff,
                                          bq + l * Hdim, bk + l * Hdim, bv + l * Hdim,
                                          q, k, v, KE_H);
        attn_kernel<<<gAttn, 256, attn_smem>>>(q, k, v, attn_mask, ctxext);
        gemm_k1<<<gProj, 256, GEMM_SMEM>>>(ctxext, Wop + l * woff, bo + l * Hdim, h, t,
                                           nullptr, Hdim, KE_H, 0, 1, 0);
        ln_kernel<<<Mtot, 256>>>(t, ln1s + l * Hdim, ln1b + l * Hdim, h, hext);
        gemm_k1<<<gFF1, 256, GEMM_SMEM>>>(hext, W1p + l * w1off, b1 + l * FFdim, nullptr,
                                          nullptr, ffext, FFdim, KE_H, 1, 0, 1);
        gemm_k1<<<gProj, 256, GEMM_SMEM>>>(ffext, W2p + l * w2off, b2 + l * Hdim, h, t,
                                           nullptr, Hdim, KE_FF, 0, 1, 0);
        ln_kernel<<<Mtot, 256>>>(t, ln2s + l * Hdim, ln2b + l * Hdim, h, hext);
    }

    clf_kernel<<<Mtot, 256>>>(h, clfW, clfb, feats);
    crf_num_kernel<<<Bdim, 256>>>(feats, attn_mask, labels, crf_start, crf_end, crf_trans, num);
    crf_fwd_kernel<<<1, 256>>>(feats, attn_mask, crf_start, crf_end, crf_trans, logZ);
    viterbi_kernel<<<Bdim, 32>>>(feats, attn_mask, crf_start, crf_end, crf_trans, tags);

    int nfin = (out_size + 255) / 256;
    if (nfin < 1) nfin = 1;
    finalize_kernel<<<nfin, 256>>>(logZ, num, tags, (float*)d_out, out_size);
}

// round 11
// speedup vs baseline: 1.1328x; 1.1281x over previous
#include <cuda_runtime.h>
#include <cuda_bf16.h>
#include <math.h>

#define Mtot  4096
#define Hdim  768
#define FFdim 3072
#define NHnum 12
#define DHdim 64
#define Sdim  512
#define Bdim  8
#define Ldim  9
#define NLnum 12

#define KE_H  (3 * Hdim)    // 2304
#define KE_FF (3 * FFdim)   // 9216

// ---------------- scratch (static device allocations) ----------------
__device__ float g_h[Mtot * Hdim];
__device__ float g_q[Mtot * Hdim];
__device__ float g_k[Mtot * Hdim];
__device__ float g_v[Mtot * Hdim];
__device__ float g_t[Mtot * Hdim];
__device__ float g_feats[Mtot * Ldim];
__device__ float g_logZ[Bdim];
__device__ float g_num[Bdim];
__device__ int   g_tags[Bdim * Sdim];

// split-bf16 ext activations (A operands): [M][3K], slots per k: ah, al, ah
__device__ __align__(256) __nv_bfloat16 g_hext[Mtot * KE_H];
__device__ __align__(256) __nv_bfloat16 g_ctxext[Mtot * KE_H];
__device__ __align__(256) __nv_bfloat16 g_ffext[(size_t)Mtot * KE_FF];

// packed split-bf16 weights (B operands): [3K/2][N] u32, pair=(ext row 2i, 2i+1)
// slots per k: bh, bh, bl
#define PKH (3 * Hdim / 2)    // 1152
#define PKF (3 * FFdim / 2)   // 4608
__device__ __align__(256) unsigned int g_Wqp[NLnum * PKH * Hdim];
__device__ __align__(256) unsigned int g_Wkp[NLnum * PKH * Hdim];
__device__ __align__(256) unsigned int g_Wvp[NLnum * PKH * Hdim];
__device__ __align__(256) unsigned int g_Wop[NLnum * PKH * Hdim];
__device__ __align__(256) unsigned int g_W1p[(size_t)NLnum * PKH * FFdim];
__device__ __align__(256) unsigned int g_W2p[(size_t)NLnum * PKF * Hdim];

// ---------------- helpers ----------------
__device__ __forceinline__ float blk_sum256(float v, float* red) {
    int lane = threadIdx.x & 31, w = threadIdx.x >> 5;
#pragma unroll
    for (int o = 16; o; o >>= 1) v += __shfl_xor_sync(0xffffffffu, v, o);
    __syncthreads();
    if (lane == 0) red[w] = v;
    __syncthreads();
    float s = 0.f;
#pragma unroll
    for (int i = 0; i < 8; i++) s += red[i];
    return s;
}

__device__ __forceinline__ void split2(float x, __nv_bfloat16& hi, __nv_bfloat16& lo) {
    hi = __float2bfloat16(x);
    lo = __float2bfloat16(x - __bfloat162float(hi));
}

__device__ __forceinline__ void write_ext3(__nv_bfloat16* p, float x) {
    __nv_bfloat16 h, l;
    split2(x, h, l);
    p[0] = h; p[1] = l; p[2] = h;   // A-ext slots: ah, al, ah
}

// fast exp on the FMA pipe (no MUFU)
__device__ __forceinline__ float fexp(float x) {
    float t = x * 1.4426950408889634f;
    t = fmaxf(t, -126.0f);
    float fl = floorf(t);
    float f = t - fl;
    float p = 1.525273e-5f;
    p = fmaf(p, f, 1.5403530e-4f);
    p = fmaf(p, f, 1.3333558e-3f);
    p = fmaf(p, f, 9.6181291e-3f);
    p = fmaf(p, f, 5.5504109e-2f);
    p = fmaf(p, f, 2.4022651e-1f);
    p = fmaf(p, f, 6.9314718e-1f);
    p = fmaf(p, f, 1.0f);
    return p * __int_as_float(((int)fl + 127) << 23);
}

// ---------------- weight conversion: fp32 [L][K][N] -> packed [L][3K/2][N] u32 ---
__device__ __forceinline__ unsigned int packw(const float* __restrict__ W, int K, int N,
                                              int l, int i, int n) {
    int s0 = 2 * i, s1 = 2 * i + 1;
    int k0 = s0 / 3, r0 = s0 % 3;
    int k1 = s1 / 3, r1 = s1 % 3;
    float w0 = W[((size_t)l * K + k0) * N + n];
    float w1 = W[((size_t)l * K + k1) * N + n];
    __nv_bfloat16 h0, l0, h1, l1;
    split2(w0, h0, l0);
    split2(w1, h1, l1);
    __nv_bfloat16 v0 = (r0 == 2) ? l0 : h0;   // B-ext slots: bh, bh, bl
    __nv_bfloat16 v1 = (r1 == 2) ? l1 : h1;
    __nv_bfloat162 pr(v0, v1);
    return *reinterpret_cast<unsigned int*>(&pr);
}

__global__ void convB_kernel(const float* __restrict__ W, unsigned int* __restrict__ out,
                             int K, int N, int L) {
    size_t PK = (size_t)3 * K / 2;
    size_t total = (size_t)L * PK * N;
    for (size_t idx = (size_t)blockIdx.x * blockDim.x + threadIdx.x; idx < total;
         idx += (size_t)gridDim.x * blockDim.x) {
        int n = (int)(idx % N);
        size_t rest = idx / N;
        int i = (int)(rest % PK);
        int l = (int)(rest / PK);
        out[idx] = packw(W, K, N, l, i, n);
    }
}

__global__ void convB2_kernel(const float* __restrict__ Wa, unsigned int* __restrict__ outa,
                              const float* __restrict__ Wb, unsigned int* __restrict__ outb,
                              int K, int N, int L) {
    size_t PK = (size_t)3 * K / 2;
    size_t total = (size_t)L * PK * N;
    for (size_t idx = (size_t)blockIdx.x * blockDim.x + threadIdx.x; idx < 2 * total;
         idx += (size_t)gridDim.x * blockDim.x) {
        const float* W = (idx < total) ? Wa : Wb;
        unsigned int* out = (idx < total) ? outa : outb;
        size_t j = (idx < total) ? idx : idx - total;
        int n = (int)(j % N);
        size_t rest = j / N;
        int i = (int)(rest % PK);
        int l = (int)(rest / PK);
        out[j] = packw(W, K, N, l, i, n);
    }
}

// ---------------- embedding + LayerNorm ----------------
__global__ void embed_ln_kernel(const float* __restrict__ we, const float* __restrict__ pe,
                                const float* __restrict__ te, const float* __restrict__ gs,
                                const float* __restrict__ gb, const int* __restrict__ ids,
                                const int* __restrict__ tts, float* __restrict__ out,
                                __nv_bfloat16* __restrict__ ext) {
    __shared__ float red[8];
    int m = blockIdx.x;
    int s = m & (Sdim - 1);
    int id = ids[m], tt = tts[m];
    float vals[3];
    float lsum = 0.f;
#pragma unroll
    for (int u = 0; u < 3; u++) {
        int j = threadIdx.x + u * 256;
        float v = we[(size_t)id * Hdim + j] + pe[(size_t)s * Hdim + j] + te[(size_t)tt * Hdim + j];
        vals[u] = v;
        lsum += v;
    }
    float mean = blk_sum256(lsum, red) * (1.f / Hdim);
    float lsq = 0.f;
#pragma unroll
    for (int u = 0; u < 3; u++) { float d = vals[u] - mean; lsq += d * d; }
    float var = blk_sum256(lsq, red) * (1.f / Hdim);
    float inv = rsqrtf(var + 1e-12f);
#pragma unroll
    for (int u = 0; u < 3; u++) {
        int j = threadIdx.x + u * 256;
        float y = (vals[u] - mean) * inv * gs[j] + gb[j];
        out[(size_t)m * Hdim + j] = y;
        write_ext3(ext + (size_t)m * KE_H + 3 * j, y);
    }
}

// ---------------- LayerNorm ----------------
__global__ void ln_kernel(const float* __restrict__ x, const float* __restrict__ gs,
                          const float* __restrict__ gb, float* __restrict__ y,
                          __nv_bfloat16* __restrict__ ext) {
    __shared__ float red[8];
    int m = blockIdx.x;
    const float* xr = x + (size_t)m * Hdim;
    float vals[3];
    float lsum = 0.f;
#pragma unroll
    for (int u = 0; u < 3; u++) {
        vals[u] = xr[threadIdx.x + u * 256];
        lsum += vals[u];
    }
    float mean = blk_sum256(lsum, red) * (1.f / Hdim);
    float lsq = 0.f;
#pragma unroll
    for (int u = 0; u < 3; u++) { float d = vals[u] - mean; lsq += d * d; }
    float var = blk_sum256(lsq, red) * (1.f / Hdim);
    float inv = rsqrtf(var + 1e-12f);
#pragma unroll
    for (int u = 0; u < 3; u++) {
        int j = threadIdx.x + u * 256;
        float yy = (vals[u] - mean) * inv * gs[j] + gb[j];
        y[(size_t)m * Hdim + j] = yy;
        write_ext3(ext + (size_t)m * KE_H + 3 * j, yy);
    }
}

// ================= tensor-core GEMM (split-bf16, K extended 3x) =================
#define BM 128
#define BN 128
#define BKE 48
#define BKP 24
#define AS_STRIDE 28
#define BS_STRIDE 136
#define STAGE_WORDS (128 * AS_STRIDE + BKP * BS_STRIDE)  // 6848
#define NSTAGE 4
#define GEMM_SMEM (NSTAGE * STAGE_WORDS * 4)             // 109568 B

__device__ __forceinline__ void cp16(unsigned int saddr, const void* gptr) {
    asm volatile("cp.async.cg.shared.global [%0], [%1], 16;\n" ::"r"(saddr), "l"(gptr));
}
__device__ __forceinline__ void cp_commit() { asm volatile("cp.async.commit_group;\n"); }
__device__ __forceinline__ void cp_wait2() { asm volatile("cp.async.wait_group 2;\n"); }

#define MMA16816(d, a, b)                                                      \
    asm volatile(                                                              \
        "mma.sync.aligned.m16n8k16.row.col.f32.bf16.bf16.f32 "                 \
        "{%0,%1,%2,%3}, {%4,%5,%6,%7}, {%8,%9}, {%0,%1,%2,%3};\n"              \
        : "+f"(d[0]), "+f"(d[1]), "+f"(d[2]), "+f"(d[3])                       \
        : "r"(a[0]), "r"(a[1]), "r"(a[2]), "r"(a[3]), "r"(b[0]), "r"(b[1]))

__device__ __forceinline__ void gemm_core(const __nv_bfloat16* __restrict__ A,
                                          const unsigned int* __restrict__ B,
                                          const float* __restrict__ bias,
                                          const float* __restrict__ res,
                                          float* __restrict__ Cf,
                                          __nv_bfloat16* __restrict__ Ce,
                                          int N, int KE, int act, int addres, int outp,
                                          unsigned int* smem) {
    const int tid = threadIdx.x;
    const int lane = tid & 31;
    const int wid = tid >> 5;
    const int warp_m = wid >> 2;
    const int warp_n = wid & 3;
    const int m0 = blockIdx.y * BM;
    const int n0 = blockIdx.x * BN;
    const int T = KE / BKE;
    const int g = lane >> 2, t4 = lane & 3;

    float acc[4][4][4];
#pragma unroll
    for (int i = 0; i < 4; i++)
#pragma unroll
        for (int j = 0; j < 4; j++)
#pragma unroll
            for (int r = 0; r < 4; r++) acc[i][j][r] = 0.f;

    const unsigned int sbase = (unsigned int)__cvta_generic_to_shared(smem);

    auto load_stage = [&](int tile, int stg) {
        unsigned int abase = sbase + (unsigned int)(stg * STAGE_WORDS) * 4u;
        unsigned int bbase = abase + 128u * AS_STRIDE * 4u;
        const __nv_bfloat16* Ag = A + (size_t)m0 * KE + tile * BKE;
#pragma unroll
        for (int l = 0; l < 3; l++) {
            int i = tid + l * 256;
            int r = i / 6, c = i % 6;
            cp16(abase + (unsigned int)(r * AS_STRIDE + c * 4) * 4u,
                 Ag + (size_t)r * KE + c * 8);
        }
        const unsigned int* Bg = B + (size_t)(tile * BKP) * N + n0;
#pragma unroll
        for (int l = 0; l < 3; l++) {
            int i = tid + l * 256;
            int r = i / 32, c = i % 32;
            cp16(bbase + (unsigned int)(r * BS_STRIDE + c * 4) * 4u,
                 Bg + (size_t)r * N + c * 4);
        }
    };

    load_stage(0, 0); cp_commit();
    load_stage(1, 1); cp_commit();
    load_stage(2, 2); cp_commit();

    for (int t = 0; t < T; t++) {
        cp_wait2();
        __syncthreads();
        if (t + 3 < T) load_stage(t + 3, (t + 3) & 3);
        cp_commit();

        const unsigned int* As = smem + (size_t)(t & 3) * STAGE_WORDS;
        const unsigned int* Bs = As + 128 * AS_STRIDE;
#pragma unroll
        for (int s = 0; s < 3; s++) {
            unsigned int a[4][4], b[4][2];
#pragma unroll
            for (int mi = 0; mi < 4; mi++) {
                int r = warp_m * 64 + mi * 16 + g;
                int cp = s * 8 + t4;
                a[mi][0] = As[r * AS_STRIDE + cp];
                a[mi][1] = As[(r + 8) * AS_STRIDE + cp];
                a[mi][2] = As[r * AS_STRIDE + cp + 4];
                a[mi][3] = As[(r + 8) * AS_STRIDE + cp + 4];
            }
#pragma unroll
            for (int nj = 0; nj < 4; nj++) {
                int n = warp_n * 32 + nj * 8 + g;
                b[nj][0] = Bs[(s * 8 + t4) * BS_STRIDE + n];
                b[nj][1] = Bs[(s * 8 + t4 + 4) * BS_STRIDE + n];
            }
#pragma unroll
            for (int mi = 0; mi < 4; mi++)
#pragma unroll
                for (int nj = 0; nj < 4; nj++) MMA16816(acc[mi][nj], a[mi], b[nj]);
        }
        __syncthreads();
    }

#pragma unroll
    for (int mi = 0; mi < 4; mi++) {
        int row0 = m0 + warp_m * 64 + mi * 16 + g;
#pragma unroll
        for (int nj = 0; nj < 4; nj++) {
            int col = n0 + warp_n * 32 + nj * 8 + t4 * 2;
            float b0 = bias[col], b1 = bias[col + 1];
#pragma unroll
            for (int half = 0; half < 2; half++) {
                int row = row0 + half * 8;
                float v0 = acc[mi][nj][half * 2 + 0] + b0;
                float v1 = acc[mi][nj][half * 2 + 1] + b1;
                if (addres) {
                    float2 rr = *(const float2*)(res + (size_t)row * N + col);
                    v0 += rr.x;
                    v1 += rr.y;
                }
                if (act) {
                    v0 = 0.5f * v0 * (1.f + erff(v0 * 0.70710678118654752440f));
                    v1 = 0.5f * v1 * (1.f + erff(v1 * 0.70710678118654752440f));
                }
                if (outp == 0) {
                    *(float2*)(Cf + (size_t)row * N + col) = make_float2(v0, v1);
                } else {
                    __nv_bfloat16* p = Ce + (size_t)row * (3 * N) + 3 * col;
                    write_ext3(p, v0);
                    write_ext3(p + 3, v1);
                }
            }
        }
    }
}

__global__ void __launch_bounds__(256, 2) gemm_k1(const __nv_bfloat16* __restrict__ A,
                                                  const unsigned int* __restrict__ B,
                                                  const float* __restrict__ bias,
                                                  const float* __restrict__ res,
                                                  float* __restrict__ Cf,
                                                  __nv_bfloat16* __restrict__ Ce,
                                                  int N, int KE, int act, int addres, int outp) {
    extern __shared__ unsigned int smem[];
    gemm_core(A, B, bias, res, Cf, Ce, N, KE, act, addres, outp, smem);
}

__global__ void __launch_bounds__(256, 2) gemm_k3(const __nv_bfloat16* __restrict__ A,
                                                  const unsigned int* __restrict__ B0,
                                                  const unsigned int* __restrict__ B1,
                                                  const unsigned int* __restrict__ B2,
                                                  const float* __restrict__ bias0,
                                                  const float* __restrict__ bias1,
                                                  const float* __restrict__ bias2,
                                                  float* __restrict__ C0, float* __restrict__ C1,
                                                  float* __restrict__ C2, int KE) {
    extern __shared__ unsigned int smem[];
    int z = blockIdx.z;
    const unsigned int* B = (z == 0) ? B0 : (z == 1) ? B1 : B2;
    const float* bias = (z == 0) ? bias0 : (z == 1) ? bias1 : bias2;
    float* Cf = (z == 0) ? C0 : (z == 1) ? C1 : C2;
    gemm_core(A, B, bias, nullptr, Cf, nullptr, Hdim, KE, 0, 0, 0, smem);
}

// ======== tensor-core attention (split-bf16 3-slot; mma.sync; 2-phase softmax) ========
// smem layout (u32 offsets)
#define A_OFF_MB 0                     // mbias[512] f32
#define A_OFF_Q  512                   // Qext  64 rows x 100 u32
#define A_OFF_K  (512 + 6400)          // Kext  96 pair-rows x 72 u32
#define A_OFF_V  (512 + 6400 + 6912)   // Vtext 96 pair-rows x 72 u32
#define A_OFF_P  (512 + 6400 + 13824)  // Pext  64 rows x 100 u32
#define A_OFF_PM (512 + 6400 + 13824 + 6400)   // partmax[64][2]
#define A_OFF_RM (A_OFF_PM + 128)              // rowmax[64]
#define A_OFF_PS (A_OFF_RM + 64)               // partsum[64][2]
#define A_OFF_RS (A_OFF_PS + 128)              // rowsum[64]
#define ATTN_SMEM ((A_OFF_RS + 64) * 4)        // 110336 B

__global__ void __launch_bounds__(256) attn_kernel(const float* __restrict__ Q,
                                                   const float* __restrict__ Kp,
                                                   const float* __restrict__ Vp,
                                                   const int* __restrict__ amask,
                                                   __nv_bfloat16* __restrict__ Oext) {
    extern __shared__ unsigned int sm[];
    float* mbias = (float*)(sm + A_OFF_MB);
    unsigned int* qx = sm + A_OFF_Q;
    unsigned int* kx = sm + A_OFF_K;
    unsigned int* vx = sm + A_OFF_V;
    unsigned int* px = sm + A_OFF_P;
    float* partmax = (float*)(sm + A_OFF_PM);
    float* rowmax = (float*)(sm + A_OFF_RM);
    float* partsum = (float*)(sm + A_OFF_PS);
    float* rowsum = (float*)(sm + A_OFF_RS);
    unsigned short* qx16 = (unsigned short*)qx;
    unsigned short* kx16 = (unsigned short*)kx;
    unsigned short* vx16 = (unsigned short*)vx;
    unsigned short* px16 = (unsigned short*)px;

    const int tid = threadIdx.x, lane = tid & 31, w = tid >> 5;
    const int wm = w >> 1, wn = w & 1, g = lane >> 2, t4 = lane & 3;
    const int q0 = blockIdx.x * 64, h = blockIdx.y, b = blockIdx.z;
    const size_t base = (size_t)b * Sdim * Hdim + h * 64;
    const int r0 = wm * 16 + g, r1 = r0 + 8;

    for (int i = tid; i < Sdim; i += 256)
        mbias[i] = (1.f - (float)amask[b * Sdim + i]) * -10000.f;

    // build Qext (A-slots: ah, al, ah), row stride 100 u32 = 200 u16
    for (int i = tid; i < 4096; i += 256) {
        int r = i >> 6, d = i & 63;
        float xv = Q[base + (size_t)(q0 + r) * Hdim + d];
        __nv_bfloat16 hh, ll;
        split2(xv, hh, ll);
        unsigned short uh = *(unsigned short*)&hh, ul = *(unsigned short*)&ll;
        int o = r * 200 + 3 * d;
        qx16[o] = uh; qx16[o + 1] = ul; qx16[o + 2] = uh;
    }
    __syncthreads();

    // ---- phase 1: S = Q K^T (scores reg-resident), then row max ----
    float sacc[32][4];
#pragma unroll
    for (int i = 0; i < 32; i++)
#pragma unroll
        for (int j = 0; j < 4; j++) sacc[i][j] = 0.f;

#pragma unroll
    for (int kb = 0; kb < 8; kb++) {
        // build Kext block (B-slots: kh, kh, kl), pair-row stride 72 u32 = 144 u16
        for (int i = tid; i < 4096; i += 256) {
            int kk = i >> 6, d = i & 63;
            float xv = Kp[base + (size_t)(kb * 64 + kk) * Hdim + d];
            __nv_bfloat16 hh, ll;
            split2(xv, hh, ll);
            unsigned short uh = *(unsigned short*)&hh, ul = *(unsigned short*)&ll;
            int e = 3 * d;
            kx16[(e >> 1) * 144 + kk * 2 + (e & 1)] = uh;
            kx16[((e + 1) >> 1) * 144 + kk * 2 + ((e + 1) & 1)] = uh;
            kx16[((e + 2) >> 1) * 144 + kk * 2 + ((e + 2) & 1)] = ul;
        }
        __syncthreads();
#pragma unroll
        for (int s = 0; s < 12; s++) {
            unsigned int a[4];
            int ar = r0 * 100 + s * 8 + t4;
            a[0] = qx[ar]; a[1] = qx[ar + 800]; a[2] = qx[ar + 4]; a[3] = qx[ar + 804];
#pragma unroll
            for (int j = 0; j < 4; j++) {
                unsigned int bb[2];
                int br = (s * 8 + t4) * 72 + wn * 32 + j * 8 + g;
                bb[0] = kx[br]; bb[1] = kx[br + 288];
                MMA16816(sacc[kb * 4 + j], a, bb);
            }
        }
        __syncthreads();
    }

    // scale + mask + row max
    float rm0 = -1e30f, rm1 = -1e30f;
#pragma unroll
    for (int kb = 0; kb < 8; kb++)
#pragma unroll
        for (int j = 0; j < 4; j++) {
            int c = kb * 64 + wn * 32 + j * 8 + 2 * t4;
            float m0 = mbias[c], m1 = mbias[c + 1];
            float* A = sacc[kb * 4 + j];
            A[0] = A[0] * 0.125f + m0;
            A[1] = A[1] * 0.125f + m1;
            A[2] = A[2] * 0.125f + m0;
            A[3] = A[3] * 0.125f + m1;
            rm0 = fmaxf(rm0, fmaxf(A[0], A[1]));
            rm1 = fmaxf(rm1, fmaxf(A[2], A[3]));
        }
    rm0 = fmaxf(rm0, __shfl_xor_sync(0xffffffffu, rm0, 1));
    rm0 = fmaxf(rm0, __shfl_xor_sync(0xffffffffu, rm0, 2));
    rm1 = fmaxf(rm1, __shfl_xor_sync(0xffffffffu, rm1, 1));
    rm1 = fmaxf(rm1, __shfl_xor_sync(0xffffffffu, rm1, 2));
    if (t4 == 0) {
        partmax[r0 * 2 + wn] = rm0;
        partmax[r1 * 2 + wn] = rm1;
    }
    __syncthreads();
    if (tid < 64) rowmax[tid] = fmaxf(partmax[tid * 2], partmax[tid * 2 + 1]);
    __syncthreads();
    const float mx0 = rowmax[r0], mx1 = rowmax[r1];

    // ---- phase 2: P (split) + PV mma + sums ----
    float oacc[4][4];
#pragma unroll
    for (int j = 0; j < 4; j++)
#pragma unroll
        for (int r = 0; r < 4; r++) oacc[j][r] = 0.f;
    float sum0 = 0.f, sum1 = 0.f;

#pragma unroll
    for (int kb = 0; kb < 8; kb++) {
        // build V^T ext block (B-slots: vh, vh, vl): [ext-key pair rows][d cols]
        for (int i = tid; i < 4096; i += 256) {
            int kk = i >> 6, d = i & 63;
            float xv = Vp[base + (size_t)(kb * 64 + kk) * Hdim + d];
            __nv_bfloat16 hh, ll;
            split2(xv, hh, ll);
            unsigned short uh = *(unsigned short*)&hh, ul = *(unsigned short*)&ll;
            int e = 3 * kk;
            vx16[(e >> 1) * 144 + d * 2 + (e & 1)] = uh;
            vx16[((e + 1) >> 1) * 144 + d * 2 + ((e + 1) & 1)] = uh;
            vx16[((e + 2) >> 1) * 144 + d * 2 + ((e + 2) & 1)] = ul;
        }
        // write Pext (A-slots: ph, pl, ph) for this block
#pragma unroll
        for (int j = 0; j < 4; j++) {
            float* A = sacc[kb * 4 + j];
#pragma unroll
            for (int c01 = 0; c01 < 2; c01++) {
                int lc = wn * 32 + j * 8 + 2 * t4 + c01;
                float p0 = fexp(A[c01] - mx0);
                float p1 = fexp(A[2 + c01] - mx1);
                sum0 += p0;
                sum1 += p1;
                __nv_bfloat16 hh, ll;
                split2(p0, hh, ll);
                int o0 = r0 * 200 + 3 * lc;
                px16[o0] = *(unsigned short*)&hh;
                px16[o0 + 1] = *(unsigned short*)&ll;
                px16[o0 + 2] = *(unsigned short*)&hh;
                split2(p1, hh, ll);
                int o1 = r1 * 200 + 3 * lc;
                px16[o1] = *(unsigned short*)&hh;
                px16[o1 + 1] = *(unsigned short*)&ll;
                px16[o1 + 2] = *(unsigned short*)&hh;
            }
        }
        __syncthreads();
#pragma unroll
        for (int s = 0; s < 12; s++) {
            unsigned int a[4];
            int ar = r0 * 100 + s * 8 + t4;
            a[0] = px[ar]; a[1] = px[ar + 800]; a[2] = px[ar + 4]; a[3] = px[ar + 804];
#pragma unroll
            for (int j2 = 0; j2 < 4; j2++) {
                unsigned int bb[2];
                int br = (s * 8 + t4) * 72 + wn * 32 + j2 * 8 + g;
                bb[0] = vx[br]; bb[1] = vx[br + 288];
                MMA16816(oacc[j2], a, bb);
            }
        }
        __syncthreads();
    }

    sum0 += __shfl_xor_sync(0xffffffffu, sum0, 1);
    sum0 += __shfl_xor_sync(0xffffffffu, sum0, 2);
    sum1 += __shfl_xor_sync(0xffffffffu, sum1, 1);
    sum1 += __shfl_xor_sync(0xffffffffu, sum1, 2);
    if (t4 == 0) {
        partsum[r0 * 2 + wn] = sum0;
        partsum[r1 * 2 + wn] = sum1;
    }
    __syncthreads();
    if (tid < 64) rowsum[tid] = partsum[tid * 2] + partsum[tid * 2 + 1];
    __syncthreads();
    const float inv0 = 1.f / rowsum[r0];
    const float inv1 = 1.f / rowsum[r1];

    // epilogue -> ctx ext (A-format)
#pragma unroll
    for (int j2 = 0; j2 < 4; j2++) {
        int dcol = wn * 32 + j2 * 8 + 2 * t4;
        int mrow0 = b * Sdim + q0 + r0;
        int mrow1 = b * Sdim + q0 + r1;
        __nv_bfloat16* p0 = Oext + (size_t)mrow0 * KE_H + 3 * (h * 64 + dcol);
        write_ext3(p0, oacc[j2][0] * inv0);
        write_ext3(p0 + 3, oacc[j2][1] * inv0);
        __nv_bfloat16* p1 = Oext + (size_t)mrow1 * KE_H + 3 * (h * 64 + dcol);
        write_ext3(p1, oacc[j2][2] * inv1);
        write_ext3(p1 + 3, oacc[j2][3] * inv1);
    }
}

// ---------------- classifier ----------------
__global__ void clf_kernel(const float* __restrict__ X, const float* __restrict__ W,
                           const float* __restrict__ bias, float* __restrict__ F) {
    __shared__ float red[8][Ldim];
    int m = blockIdx.x;
    int tid = threadIdx.x;
    float acc[Ldim];
#pragma unroll
    for (int j = 0; j < Ldim; j++) acc[j] = 0.f;
    for (int k = tid; k < Hdim; k += 256) {
        float x = X[(size_t)m * Hdim + k];
#pragma unroll
        for (int j = 0; j < Ldim; j++) acc[j] += x * W[k * Ldim + j];
    }
    int lane = tid & 31, w = tid >> 5;
#pragma unroll
    for (int j = 0; j < Ldim; j++)
#pragma unroll
        for (int o = 16; o; o >>= 1) acc[j] += __shfl_down_sync(0xffffffffu, acc[j], o);
    if (lane == 0)
#pragma unroll
        for (int j = 0; j < Ldim; j++) red[w][j] = acc[j];
    __syncthreads();
    if (tid < Ldim) {
        float s = bias[tid];
#pragma unroll
        for (int ww = 0; ww < 8; ww++) s += red[ww][tid];
        F[(size_t)m * Ldim + tid] = s;
    }
}

// ---------------- CRF numerator ----------------
__global__ void crf_num_kernel(const float* __restrict__ feats, const int* __restrict__ amask,
                               const int* __restrict__ labels, const float* __restrict__ start,
                               const float* __restrict__ endv, const float* __restrict__ trans,
                               float* __restrict__ num) {
    __shared__ float red[8];
    int b = blockIdx.x;
    int tid = threadIdx.x;
    float s = 0.f, msum = 0.f;
    for (int t = tid; t < Sdim; t += 256) {
        int tag = labels[b * Sdim + t];
        float em = feats[(size_t)(b * Sdim + t) * Ldim + tag];
        float m = (float)amask[b * Sdim + t];
        msum += m;
        if (t == 0) {
            s += start[tag] + em;
        } else {
            int pt = labels[b * Sdim + t - 1];
            s += (em + trans[pt * Ldim + tag]) * m;
        }
    }
    float stotal = blk_sum256(s, red);
    float mtotal = blk_sum256(msum, red);
    if (tid == 0) {
        int last = (int)(mtotal + 0.5f) - 1;
        num[b] = stotal + endv[labels[b * Sdim + last]];
    }
}

// ---------------- CRF forward ----------------
__global__ void crf_fwd_kernel(const float* __restrict__ feats, const int* __restrict__ amask,
                               const float* __restrict__ start, const float* __restrict__ endv,
                               const float* __restrict__ trans, float* __restrict__ logZ) {
    int b = threadIdx.x >> 5;
    int j = threadIdx.x & 31;
    bool act = j < Ldim;
    float tr[Ldim];
#pragma unroll
    for (int i = 0; i < Ldim; i++) tr[i] = act ? trans[i * Ldim + j] : 0.f;
    float score = act ? start[j] + feats[(size_t)(b * Sdim) * Ldim + j] : -1e30f;
    for (int t = 1; t < Sdim; t++) {
        float e = act ? feats[(size_t)(b * Sdim + t) * Ldim + j] : 0.f;
        int m = amask[b * Sdim + t];
        float v[Ldim];
        float mx = -1e30f;
#pragma unroll
        for (int i = 0; i < Ldim; i++) {
            float si = __shfl_sync(0xffffffffu, score, i);
            v[i] = si + tr[i];
            mx = fmaxf(mx, v[i]);
        }
        float ssum = 0.f;
#pragma unroll
        for (int i = 0; i < Ldim; i++) ssum += expf(v[i] - mx);
        float nxt = mx + logf(ssum) + e;
        if (act && m > 0) score = nxt;
    }
    float tot = act ? score + endv[j] : -1e30f;
    float mx = tot;
#pragma unroll
    for (int o = 16; o; o >>= 1) mx = fmaxf(mx, __shfl_xor_sync(0xffffffffu, mx, o));
    float ex = act ? expf(tot - mx) : 0.f;
#pragma unroll
    for (int o = 16; o; o >>= 1) ex += __shfl_xor_sync(0xffffffffu, ex, o);
    if (j == 0) logZ[b] = mx + logf(ex);
}

// ---------------- Viterbi ----------------
__global__ void viterbi_kernel(const float* __restrict__ feats, const int* __restrict__ amask,
                               const float* __restrict__ start, const float* __restrict__ endv,
                               const float* __restrict__ trans, int* __restrict__ tags) {
    __shared__ unsigned char hist[(Sdim - 1) * Ldim];
    int b = blockIdx.x;
    int j = threadIdx.x;
    bool act = j < Ldim;
    float tr[Ldim];
#pragma unroll
    for (int i = 0; i < Ldim; i++) tr[i] = act ? trans[i * Ldim + j] : 0.f;
    float score = act ? start[j] + feats[(size_t)(b * Sdim) * Ldim + j] : -1e30f;
    for (int t = 1; t < Sdim; t++) {
        float e = act ? feats[(size_t)(b * Sdim + t) * Ldim + j] : 0.f;
        int m = amask[b * Sdim + t];
        float best = -1e30f;
        int barg = 0;
#pragma unroll
        for (int i = 0; i < Ldim; i++) {
            float si = __shfl_sync(0xffffffffu, score, i);
            float v = si + tr[i];
            if (v > best) { best = v; barg = i; }
        }
        if (act) {
            hist[(t - 1) * Ldim + j] = (unsigned char)barg;
            float nxt = best + e;
            if (m > 0) score = nxt;
        }
    }
    __syncwarp();
    float tot = act ? score + endv[j] : -1e30f;
    float bb = tot;
    int bj = act ? j : 0;
#pragma unroll
    for (int o = 16; o; o >>= 1) {
        float ov = __shfl_down_sync(0xffffffffu, bb, o);
        int oj = __shfl_down_sync(0xffffffffu, bj, o);
        if (ov > bb) { bb = ov; bj = oj; }
    }
    if (j == 0) {
        int tag = bj;
        tags[b * Sdim + Sdim - 1] = tag;
        for (int t = Sdim - 2; t >= 0; t--) {
            tag = hist[t * Ldim + tag];
            tags[b * Sdim + t] = tag;
        }
    }
}

// ---------------- finalize ----------------
__global__ void finalize_kernel(const float* __restrict__ logZ, const float* __restrict__ num,
                                const int* __restrict__ tags, float* __restrict__ out,
                                int out_size) {
    int i = blockIdx.x * blockDim.x + threadIdx.x;
    if (i >= out_size) return;
    if (i == 0) {
        float s = 0.f;
        for (int b = 0; b < Bdim; b++) s += logZ[b] - num[b];
        out[0] = s * (1.f / Bdim);
    } else if (i - 1 < Bdim * Sdim) {
        out[i] = (float)tags[i - 1];
    } else {
        out[i] = 0.f;
    }
}

// ---------------- host launch ----------------
extern "C" void kernel_launch(void* const* d_in, const int* in_sizes, int n_in,
                              void* d_out, int out_size) {
    const float* word_emb = (const float*)d_in[0];
    const float* pos_emb  = (const float*)d_in[1];
    const float* type_emb = (const float*)d_in[2];
    const float* eln_s    = (const float*)d_in[3];
    const float* eln_b    = (const float*)d_in[4];
    const float* Wq = (const float*)d_in[5];
    const float* bq = (const float*)d_in[6];
    const float* Wk = (const float*)d_in[7];
    const float* bk = (const float*)d_in[8];
    const float* Wv = (const float*)d_in[9];
    const float* bv = (const float*)d_in[10];
    const float* Wo = (const float*)d_in[11];
    const float* bo = (const float*)d_in[12];
    const float* ln1s = (const float*)d_in[13];
    const float* ln1b = (const float*)d_in[14];
    const float* W1 = (const float*)d_in[15];
    const float* b1 = (const float*)d_in[16];
    const float* W2 = (const float*)d_in[17];
    const float* b2 = (const float*)d_in[18];
    const float* ln2s = (const float*)d_in[19];
    const float* ln2b = (const float*)d_in[20];
    const float* clfW = (const float*)d_in[21];
    const float* clfb = (const float*)d_in[22];
    const float* crf_start = (const float*)d_in[23];
    const float* crf_end   = (const float*)d_in[24];
    const float* crf_trans = (const float*)d_in[25];
    const int* input_ids   = (const int*)d_in[26];
    const int* token_type  = (const int*)d_in[27];
    const int* attn_mask   = (const int*)d_in[28];
    const int* labels      = (const int*)d_in[29];

    float *h, *q, *k, *v, *t, *feats, *logZ, *num;
    int* tags;
    __nv_bfloat16 *hext, *ctxext, *ffext;
    unsigned int *Wqp, *Wkp, *Wvp, *Wop, *W1p, *W2p;
    cudaGetSymbolAddress((void**)&h, g_h);
    cudaGetSymbolAddress((void**)&q, g_q);
    cudaGetSymbolAddress((void**)&k, g_k);
    cudaGetSymbolAddress((void**)&v, g_v);
    cudaGetSymbolAddress((void**)&t, g_t);
    cudaGetSymbolAddress((void**)&feats, g_feats);
    cudaGetSymbolAddress((void**)&logZ, g_logZ);
    cudaGetSymbolAddress((void**)&num, g_num);
    cudaGetSymbolAddress((void**)&tags, g_tags);
    cudaGetSymbolAddress((void**)&hext, g_hext);
    cudaGetSymbolAddress((void**)&ctxext, g_ctxext);
    cudaGetSymbolAddress((void**)&ffext, g_ffext);
    cudaGetSymbolAddress((void**)&Wqp, g_Wqp);
    cudaGetSymbolAddress((void**)&Wkp, g_Wkp);
    cudaGetSymbolAddress((void**)&Wvp, g_Wvp);
    cudaGetSymbolAddress((void**)&Wop, g_Wop);
    cudaGetSymbolAddress((void**)&W1p, g_W1p);
    cudaGetSymbolAddress((void**)&W2p, g_W2p);

    cudaFuncSetAttribute(attn_kernel, cudaFuncAttributeMaxDynamicSharedMemorySize, ATTN_SMEM);
    cudaFuncSetAttribute(gemm_k1, cudaFuncAttributeMaxDynamicSharedMemorySize, GEMM_SMEM);
    cudaFuncSetAttribute(gemm_k3, cudaFuncAttributeMaxDynamicSharedMemorySize, GEMM_SMEM);

    convB2_kernel<<<4096, 256>>>(Wq, Wqp, Wk, Wkp, Hdim, Hdim, NLnum);
    convB2_kernel<<<4096, 256>>>(Wv, Wvp, Wo, Wop, Hdim, Hdim, NLnum);
    convB_kernel<<<4096, 256>>>(W1, W1p, Hdim, FFdim, NLnum);
    convB_kernel<<<4096, 256>>>(W2, W2p, FFdim, Hdim, NLnum);
    embed_ln_kernel<<<Mtot, 256>>>(word_emb, pos_emb, type_emb, eln_s, eln_b,
                                   input_ids, token_type, h, hext);

    dim3 gQKV(Hdim / BN, Mtot / BM, 3);
    dim3 gProj(Hdim / BN, Mtot / BM);
    dim3 gFF1(FFdim / BN, Mtot / BM);
    dim3 gAttn(Sdim / 64, NHnum, Bdim);
    const size_t woff = (size_t)PKH * Hdim;
    const size_t w1off = (size_t)PKH * FFdim;
    const size_t w2off = (size_t)PKF * Hdim;

    for (int l = 0; l < NLnum; l++) {
        gemm_k3<<<gQKV, 256, GEMM_SMEM>>>(hext, Wqp + l * woff, Wkp + l * woff, Wvp + l * woff,
                                          bq + l * Hdim, bk + l * Hdim, bv + l * Hdim,
                                          q, k, v, KE_H);
        attn_kernel<<<gAttn, 256, ATTN_SMEM>>>(q, k, v, attn_mask, ctxext);
        gemm_k1<<<gProj, 256, GEMM_SMEM>>>(ctxext, Wop + l * woff, bo + l * Hdim, h, t,
                                           nullptr, Hdim, KE_H, 0, 1, 0);
        ln_kernel<<<Mtot, 256>>>(t, ln1s + l * Hdim, ln1b + l * Hdim, h, hext);
        gemm_k1<<<gFF1, 256, GEMM_SMEM>>>(hext, W1p + l * w1off, b1 + l * FFdim, nullptr,
                                          nullptr, ffext, FFdim, KE_H, 1, 0, 1);
        gemm_k1<<<gProj, 256, GEMM_SMEM>>>(ffext, W2p + l * w2off, b2 + l * Hdim, h, t,
                                           nullptr, Hdim, KE_FF, 0, 1, 0);
        ln_kernel<<<Mtot, 256>>>(t, ln2s + l * Hdim, ln2b + l * Hdim, h, hext);
    }

    clf_kernel<<<Mtot, 256>>>(h, clfW, clfb, feats);
    crf_num_kernel<<<Bdim, 256>>>(feats, attn_mask, labels, crf_start, crf_end, crf_trans, num);
    crf_fwd_kernel<<<1, 256>>>(feats, attn_mask, crf_start, crf_end, crf_trans, logZ);
    viterbi_kernel<<<Bdim, 32>>>(feats, attn_mask, crf_start, crf_end, crf_trans, tags);

    int nfin = (out_size + 255) / 256;
    if (nfin < 1) nfin = 1;
    finalize_kernel<<<nfin, 256>>>(logZ, num, tags, (float*)d_out, out_size);
}

// round 12
// speedup vs baseline: 1.1626x; 1.0263x over previous
#include <cuda_runtime.h>
#include <cuda_bf16.h>
#include <math.h>

#define Mtot  4096
#define Hdim  768
#define FFdim 3072
#define NHnum 12
#define DHdim 64
#define Sdim  512
#define Bdim  8
#define Ldim  9
#define NLnum 12

#define KE_H  (3 * Hdim)    // 2304
#define KE_FF (3 * FFdim)   // 9216

// ---------------- scratch ----------------
__device__ float g_h[Mtot * Hdim];
__device__ float g_q[Mtot * Hdim];
__device__ float g_k[Mtot * Hdim];
__device__ float g_v[Mtot * Hdim];
__device__ float g_t[Mtot * Hdim];
__device__ float g_feats[Mtot * Ldim];
__device__ float g_logZ[Bdim];
__device__ float g_num[Bdim];
__device__ int   g_tags[Bdim * Sdim];

__device__ __align__(256) __nv_bfloat16 g_hext[Mtot * KE_H];
__device__ __align__(256) __nv_bfloat16 g_ctxext[Mtot * KE_H];
__device__ __align__(256) __nv_bfloat16 g_ffext[(size_t)Mtot * KE_FF];

#define PKH (3 * Hdim / 2)    // 1152
#define PKF (3 * FFdim / 2)   // 4608
__device__ __align__(256) unsigned int g_Wqp[NLnum * PKH * Hdim];
__device__ __align__(256) unsigned int g_Wkp[NLnum * PKH * Hdim];
__device__ __align__(256) unsigned int g_Wvp[NLnum * PKH * Hdim];
__device__ __align__(256) unsigned int g_Wop[NLnum * PKH * Hdim];
__device__ __align__(256) unsigned int g_W1p[(size_t)NLnum * PKH * FFdim];
__device__ __align__(256) unsigned int g_W2p[(size_t)NLnum * PKF * Hdim];

// ---------------- helpers ----------------
__device__ __forceinline__ float blk_sum256(float v, float* red) {
    int lane = threadIdx.x & 31, w = threadIdx.x >> 5;
#pragma unroll
    for (int o = 16; o; o >>= 1) v += __shfl_xor_sync(0xffffffffu, v, o);
    __syncthreads();
    if (lane == 0) red[w] = v;
    __syncthreads();
    float s = 0.f;
#pragma unroll
    for (int i = 0; i < 8; i++) s += red[i];
    return s;
}

__device__ __forceinline__ void split2(float x, __nv_bfloat16& hi, __nv_bfloat16& lo) {
    hi = __float2bfloat16(x);
    lo = __float2bfloat16(x - __bfloat162float(hi));
}

__device__ __forceinline__ void write_ext3(__nv_bfloat16* p, float x) {
    __nv_bfloat16 h, l;
    split2(x, h, l);
    p[0] = h; p[1] = l; p[2] = h;
}

__device__ __forceinline__ float fexp(float x) {
    float t = x * 1.4426950408889634f;
    t = fmaxf(t, -126.0f);
    float fl = floorf(t);
    float f = t - fl;
    float p = 1.525273e-5f;
    p = fmaf(p, f, 1.5403530e-4f);
    p = fmaf(p, f, 1.3333558e-3f);
    p = fmaf(p, f, 9.6181291e-3f);
    p = fmaf(p, f, 5.5504109e-2f);
    p = fmaf(p, f, 2.4022651e-1f);
    p = fmaf(p, f, 6.9314718e-1f);
    p = fmaf(p, f, 1.0f);
    return p * __int_as_float(((int)fl + 127) << 23);
}

// ---------------- weight conversion (no runtime division) ----------------
// grid: (N/256, PK, L); thread handles (l, pair-row i, col n)
__global__ void convP_kernel(const float* __restrict__ W, unsigned int* __restrict__ out,
                             int K, int N) {
    int n = blockIdx.x * 256 + threadIdx.x;
    int i = blockIdx.y;
    int l = blockIdx.z;
    int PK = 3 * K / 2;
    int s0 = 2 * i, s1 = s0 + 1;
    int k0 = s0 / 3, r0 = s0 - 3 * k0;     // /3 by constant: mulhi, cheap
    int k1 = s1 / 3, r1 = s1 - 3 * k1;
    const float* Wl = W + (size_t)l * K * N;
    float w0 = Wl[(size_t)k0 * N + n];
    float w1 = Wl[(size_t)k1 * N + n];
    __nv_bfloat16 h0, l0, h1, l1;
    split2(w0, h0, l0);
    split2(w1, h1, l1);
    __nv_bfloat16 v0 = (r0 == 2) ? l0 : h0;
    __nv_bfloat16 v1 = (r1 == 2) ? l1 : h1;
    __nv_bfloat162 pr(v0, v1);
    out[((size_t)l * PK + i) * N + n] = *reinterpret_cast<unsigned int*>(&pr);
}

// ---------------- embedding + LayerNorm ----------------
__global__ void embed_ln_kernel(const float* __restrict__ we, const float* __restrict__ pe,
                                const float* __restrict__ te, const float* __restrict__ gs,
                                const float* __restrict__ gb, const int* __restrict__ ids,
                                const int* __restrict__ tts, float* __restrict__ out,
                                __nv_bfloat16* __restrict__ ext) {
    __shared__ float red[8];
    int m = blockIdx.x;
    int s = m & (Sdim - 1);
    int id = ids[m], tt = tts[m];
    float vals[3];
    float lsum = 0.f;
#pragma unroll
    for (int u = 0; u < 3; u++) {
        int j = threadIdx.x + u * 256;
        float v = we[(size_t)id * Hdim + j] + pe[(size_t)s * Hdim + j] + te[(size_t)tt * Hdim + j];
        vals[u] = v;
        lsum += v;
    }
    float mean = blk_sum256(lsum, red) * (1.f / Hdim);
    float lsq = 0.f;
#pragma unroll
    for (int u = 0; u < 3; u++) { float d = vals[u] - mean; lsq += d * d; }
    float var = blk_sum256(lsq, red) * (1.f / Hdim);
    float inv = rsqrtf(var + 1e-12f);
#pragma unroll
    for (int u = 0; u < 3; u++) {
        int j = threadIdx.x + u * 256;
        float y = (vals[u] - mean) * inv * gs[j] + gb[j];
        out[(size_t)m * Hdim + j] = y;
        write_ext3(ext + (size_t)m * KE_H + 3 * j, y);
    }
}

// ---------------- LayerNorm ----------------
__global__ void ln_kernel(const float* __restrict__ x, const float* __restrict__ gs,
                          const float* __restrict__ gb, float* __restrict__ y,
                          __nv_bfloat16* __restrict__ ext) {
    __shared__ float red[8];
    int m = blockIdx.x;
    const float* xr = x + (size_t)m * Hdim;
    float vals[3];
    float lsum = 0.f;
#pragma unroll
    for (int u = 0; u < 3; u++) {
        vals[u] = xr[threadIdx.x + u * 256];
        lsum += vals[u];
    }
    float mean = blk_sum256(lsum, red) * (1.f / Hdim);
    float lsq = 0.f;
#pragma unroll
    for (int u = 0; u < 3; u++) { float d = vals[u] - mean; lsq += d * d; }
    float var = blk_sum256(lsq, red) * (1.f / Hdim);
    float inv = rsqrtf(var + 1e-12f);
#pragma unroll
    for (int u = 0; u < 3; u++) {
        int j = threadIdx.x + u * 256;
        float yy = (vals[u] - mean) * inv * gs[j] + gb[j];
        y[(size_t)m * Hdim + j] = yy;
        write_ext3(ext + (size_t)m * KE_H + 3 * j, yy);
    }
}

// ================= shared GEMM bits =================
__device__ __forceinline__ void cp16(unsigned int saddr, const void* gptr) {
    asm volatile("cp.async.cg.shared.global [%0], [%1], 16;\n" ::"r"(saddr), "l"(gptr));
}
__device__ __forceinline__ void cp_commit() { asm volatile("cp.async.commit_group;\n"); }
__device__ __forceinline__ void cp_wait2() { asm volatile("cp.async.wait_group 2;\n"); }

#define MMA16816(d, a, b)                                                      \
    asm volatile(                                                              \
        "mma.sync.aligned.m16n8k16.row.col.f32.bf16.bf16.f32 "                 \
        "{%0,%1,%2,%3}, {%4,%5,%6,%7}, {%8,%9}, {%0,%1,%2,%3};\n"              \
        : "+f"(d[0]), "+f"(d[1]), "+f"(d[2]), "+f"(d[3])                       \
        : "r"(a[0]), "r"(a[1]), "r"(a[2]), "r"(a[3]), "r"(b[0]), "r"(b[1]))

// ================= 128x128 GEMM (O proj, FF2) =================
#define BKE 48
#define BKP 24
#define AS_STRIDE 28
#define BS_STRIDE 136
#define STAGE_WORDS (128 * AS_STRIDE + BKP * BS_STRIDE)  // 6848
#define GEMM_SMEM (4 * STAGE_WORDS * 4)                  // 109568 B

__device__ __forceinline__ void gemm_core(const __nv_bfloat16* __restrict__ A,
                                          const unsigned int* __restrict__ B,
                                          const float* __restrict__ bias,
                                          const float* __restrict__ res,
                                          float* __restrict__ Cf,
                                          __nv_bfloat16* __restrict__ Ce,
                                          int N, int KE, int act, int addres, int outp,
                                          unsigned int* smem) {
    const int tid = threadIdx.x;
    const int lane = tid & 31;
    const int wid = tid >> 5;
    const int warp_m = wid >> 2;
    const int warp_n = wid & 3;
    const int m0 = blockIdx.y * 128;
    const int n0 = blockIdx.x * 128;
    const int T = KE / BKE;
    const int g = lane >> 2, t4 = lane & 3;

    float acc[4][4][4];
#pragma unroll
    for (int i = 0; i < 4; i++)
#pragma unroll
        for (int j = 0; j < 4; j++)
#pragma unroll
            for (int r = 0; r < 4; r++) acc[i][j][r] = 0.f;

    const unsigned int sbase = (unsigned int)__cvta_generic_to_shared(smem);

    auto load_stage = [&](int tile, int stg) {
        unsigned int abase = sbase + (unsigned int)(stg * STAGE_WORDS) * 4u;
        unsigned int bbase = abase + 128u * AS_STRIDE * 4u;
        const __nv_bfloat16* Ag = A + (size_t)m0 * KE + tile * BKE;
#pragma unroll
        for (int l = 0; l < 3; l++) {
            int i = tid + l * 256;
            int r = i / 6, c = i % 6;
            cp16(abase + (unsigned int)(r * AS_STRIDE + c * 4) * 4u,
                 Ag + (size_t)r * KE + c * 8);
        }
        const unsigned int* Bg = B + (size_t)(tile * BKP) * N + n0;
#pragma unroll
        for (int l = 0; l < 3; l++) {
            int i = tid + l * 256;
            int r = i >> 5, c = i & 31;
            cp16(bbase + (unsigned int)(r * BS_STRIDE + c * 4) * 4u,
                 Bg + (size_t)r * N + c * 4);
        }
    };

    load_stage(0, 0); cp_commit();
    load_stage(1, 1); cp_commit();
    load_stage(2, 2); cp_commit();

    for (int t = 0; t < T; t++) {
        cp_wait2();
        __syncthreads();
        if (t + 3 < T) load_stage(t + 3, (t + 3) & 3);
        cp_commit();

        const unsigned int* As = smem + (size_t)(t & 3) * STAGE_WORDS;
        const unsigned int* Bs = As + 128 * AS_STRIDE;
#pragma unroll
        for (int s = 0; s < 3; s++) {
            unsigned int a[4][4], b[4][2];
#pragma unroll
            for (int mi = 0; mi < 4; mi++) {
                int r = warp_m * 64 + mi * 16 + g;
                int cp = s * 8 + t4;
                a[mi][0] = As[r * AS_STRIDE + cp];
                a[mi][1] = As[(r + 8) * AS_STRIDE + cp];
                a[mi][2] = As[r * AS_STRIDE + cp + 4];
                a[mi][3] = As[(r + 8) * AS_STRIDE + cp + 4];
            }
#pragma unroll
            for (int nj = 0; nj < 4; nj++) {
                int n = warp_n * 32 + nj * 8 + g;
                b[nj][0] = Bs[(s * 8 + t4) * BS_STRIDE + n];
                b[nj][1] = Bs[(s * 8 + t4 + 4) * BS_STRIDE + n];
            }
#pragma unroll
            for (int mi = 0; mi < 4; mi++)
#pragma unroll
                for (int nj = 0; nj < 4; nj++) MMA16816(acc[mi][nj], a[mi], b[nj]);
        }
        __syncthreads();
    }

#pragma unroll
    for (int mi = 0; mi < 4; mi++) {
        int row0 = m0 + warp_m * 64 + mi * 16 + g;
#pragma unroll
        for (int nj = 0; nj < 4; nj++) {
            int col = n0 + warp_n * 32 + nj * 8 + t4 * 2;
            float b0 = bias[col], b1 = bias[col + 1];
#pragma unroll
            for (int half = 0; half < 2; half++) {
                int row = row0 + half * 8;
                float v0 = acc[mi][nj][half * 2 + 0] + b0;
                float v1 = acc[mi][nj][half * 2 + 1] + b1;
                if (addres) {
                    float2 rr = *(const float2*)(res + (size_t)row * N + col);
                    v0 += rr.x;
                    v1 += rr.y;
                }
                if (act) {
                    v0 = 0.5f * v0 * (1.f + erff(v0 * 0.70710678118654752440f));
                    v1 = 0.5f * v1 * (1.f + erff(v1 * 0.70710678118654752440f));
                }
                if (outp == 0) {
                    *(float2*)(Cf + (size_t)row * N + col) = make_float2(v0, v1);
                } else {
                    __nv_bfloat16* p = Ce + (size_t)row * (3 * N) + 3 * col;
                    write_ext3(p, v0);
                    write_ext3(p + 3, v1);
                }
            }
        }
    }
}

__global__ void __launch_bounds__(256, 2) gemm_k1(const __nv_bfloat16* __restrict__ A,
                                                  const unsigned int* __restrict__ B,
                                                  const float* __restrict__ bias,
                                                  const float* __restrict__ res,
                                                  float* __restrict__ Cf,
                                                  __nv_bfloat16* __restrict__ Ce,
                                                  int N, int KE, int act, int addres, int outp) {
    extern __shared__ unsigned int smem[];
    gemm_core(A, B, bias, res, Cf, Ce, N, KE, act, addres, outp, smem);
}

// ================= 128x256 GEMM (QKV, FF1) =================
#define BSW_STRIDE 264
#define STAGE_WORDS_W (128 * AS_STRIDE + BKP * BSW_STRIDE)  // 3584 + 6336 = 9920
#define GEMM_SMEM_W (4 * STAGE_WORDS_W * 4)                 // 158720 B

__device__ __forceinline__ void gemm_core_w(const __nv_bfloat16* __restrict__ A,
                                            const unsigned int* __restrict__ B,
                                            const float* __restrict__ bias,
                                            float* __restrict__ Cf,
                                            __nv_bfloat16* __restrict__ Ce,
                                            int N, int KE, int act, int outp,
                                            unsigned int* smem) {
    const int tid = threadIdx.x;
    const int lane = tid & 31;
    const int wid = tid >> 5;
    const int warp_m = wid >> 2;   // 0..1 (64 rows)
    const int warp_n = wid & 3;    // 0..3 (64 cols)
    const int m0 = blockIdx.y * 128;
    const int n0 = blockIdx.x * 256;
    const int T = KE / BKE;
    const int g = lane >> 2, t4 = lane & 3;

    float acc[4][8][4];
#pragma unroll
    for (int i = 0; i < 4; i++)
#pragma unroll
        for (int j = 0; j < 8; j++)
#pragma unroll
            for (int r = 0; r < 4; r++) acc[i][j][r] = 0.f;

    const unsigned int sbase = (unsigned int)__cvta_generic_to_shared(smem);

    auto load_stage = [&](int tile, int stg) {
        unsigned int abase = sbase + (unsigned int)(stg * STAGE_WORDS_W) * 4u;
        unsigned int bbase = abase + 128u * AS_STRIDE * 4u;
        const __nv_bfloat16* Ag = A + (size_t)m0 * KE + tile * BKE;
#pragma unroll
        for (int l = 0; l < 3; l++) {
            int i = tid + l * 256;
            int r = i / 6, c = i % 6;
            cp16(abase + (unsigned int)(r * AS_STRIDE + c * 4) * 4u,
                 Ag + (size_t)r * KE + c * 8);
        }
        const unsigned int* Bg = B + (size_t)(tile * BKP) * N + n0;
#pragma unroll
        for (int l = 0; l < 6; l++) {
            int i = tid + l * 256;
            int r = i >> 6, c = i & 63;           // 24 rows x 64 chunks(16B)
            cp16(bbase + (unsigned int)(r * BSW_STRIDE + c * 4) * 4u,
                 Bg + (size_t)r * N + c * 4);
        }
    };

    load_stage(0, 0); cp_commit();
    load_stage(1, 1); cp_commit();
    load_stage(2, 2); cp_commit();

    for (int t = 0; t < T; t++) {
        cp_wait2();
        __syncthreads();
        if (t + 3 < T) load_stage(t + 3, (t + 3) & 3);
        cp_commit();

        const unsigned int* As = smem + (size_t)(t & 3) * STAGE_WORDS_W;
        const unsigned int* Bs = As + 128 * AS_STRIDE;
#pragma unroll
        for (int s = 0; s < 3; s++) {
            unsigned int a[4][4];
#pragma unroll
            for (int mi = 0; mi < 4; mi++) {
                int r = warp_m * 64 + mi * 16 + g;
                int cp = s * 8 + t4;
                a[mi][0] = As[r * AS_STRIDE + cp];
                a[mi][1] = As[(r + 8) * AS_STRIDE + cp];
                a[mi][2] = As[r * AS_STRIDE + cp + 4];
                a[mi][3] = As[(r + 8) * AS_STRIDE + cp + 4];
            }
#pragma unroll
            for (int nj = 0; nj < 8; nj++) {
                unsigned int b[2];
                int n = warp_n * 64 + nj * 8 + g;
                b[0] = Bs[(s * 8 + t4) * BSW_STRIDE + n];
                b[1] = Bs[(s * 8 + t4 + 4) * BSW_STRIDE + n];
#pragma unroll
                for (int mi = 0; mi < 4; mi++) MMA16816(acc[mi][nj], a[mi], b);
            }
        }
        __syncthreads();
    }

#pragma unroll
    for (int mi = 0; mi < 4; mi++) {
        int row0 = m0 + warp_m * 64 + mi * 16 + g;
#pragma unroll
        for (int nj = 0; nj < 8; nj++) {
            int col = n0 + warp_n * 64 + nj * 8 + t4 * 2;
            float b0 = bias[col], b1 = bias[col + 1];
#pragma unroll
            for (int half = 0; half < 2; half++) {
                int row = row0 + half * 8;
                float v0 = acc[mi][nj][half * 2 + 0] + b0;
                float v1 = acc[mi][nj][half * 2 + 1] + b1;
                if (act) {
                    v0 = 0.5f * v0 * (1.f + erff(v0 * 0.70710678118654752440f));
                    v1 = 0.5f * v1 * (1.f + erff(v1 * 0.70710678118654752440f));
                }
                if (outp == 0) {
                    *(float2*)(Cf + (size_t)row * N + col) = make_float2(v0, v1);
                } else {
                    __nv_bfloat16* p = Ce + (size_t)row * (3 * N) + 3 * col;
                    write_ext3(p, v0);
                    write_ext3(p + 3, v1);
                }
            }
        }
    }
}

__global__ void __launch_bounds__(256, 1) gemm_k1w(const __nv_bfloat16* __restrict__ A,
                                                   const unsigned int* __restrict__ B,
                                                   const float* __restrict__ bias,
                                                   float* __restrict__ Cf,
                                                   __nv_bfloat16* __restrict__ Ce,
                                                   int N, int KE, int act, int outp) {
    extern __shared__ unsigned int smem[];
    gemm_core_w(A, B, bias, Cf, Ce, N, KE, act, outp, smem);
}

__global__ void __launch_bounds__(256, 1) gemm_k3w(const __nv_bfloat16* __restrict__ A,
                                                   const unsigned int* __restrict__ B0,
                                                   const unsigned int* __restrict__ B1,
                                                   const unsigned int* __restrict__ B2,
                                                   const float* __restrict__ bias0,
                                                   const float* __restrict__ bias1,
                                                   const float* __restrict__ bias2,
                                                   float* __restrict__ C0, float* __restrict__ C1,
                                                   float* __restrict__ C2, int KE) {
    extern __shared__ unsigned int smem[];
    int z = blockIdx.z;
    const unsigned int* B = (z == 0) ? B0 : (z == 1) ? B1 : B2;
    const float* bias = (z == 0) ? bias0 : (z == 1) ? bias1 : bias2;
    float* Cf = (z == 0) ? C0 : (z == 1) ? C1 : C2;
    gemm_core_w(A, B, bias, Cf, nullptr, Hdim, KE, 0, 0, smem);
}

// ======== tensor-core attention (split-bf16 3-slot; mma.sync; 2-phase softmax) ========
#define A_OFF_MB 0
#define A_OFF_Q  512
#define A_OFF_K  (512 + 6400)
#define A_OFF_V  (512 + 6400 + 6912)
#define A_OFF_P  (512 + 6400 + 13824)
#define A_OFF_PM (512 + 6400 + 13824 + 6400)
#define A_OFF_RM (A_OFF_PM + 128)
#define A_OFF_PS (A_OFF_RM + 64)
#define A_OFF_RS (A_OFF_PS + 128)
#define ATTN_SMEM ((A_OFF_RS + 64) * 4)

__global__ void __launch_bounds__(256) attn_kernel(const float* __restrict__ Q,
                                                   const float* __restrict__ Kp,
                                                   const float* __restrict__ Vp,
                                                   const int* __restrict__ amask,
                                                   __nv_bfloat16* __restrict__ Oext) {
    extern __shared__ unsigned int sm[];
    float* mbias = (float*)(sm + A_OFF_MB);
    unsigned int* qx = sm + A_OFF_Q;
    unsigned int* kx = sm + A_OFF_K;
    unsigned int* vx = sm + A_OFF_V;
    unsigned int* px = sm + A_OFF_P;
    float* partmax = (float*)(sm + A_OFF_PM);
    float* rowmax = (float*)(sm + A_OFF_RM);
    float* partsum = (float*)(sm + A_OFF_PS);
    float* rowsum = (float*)(sm + A_OFF_RS);
    unsigned short* qx16 = (unsigned short*)qx;
    unsigned short* kx16 = (unsigned short*)kx;
    unsigned short* vx16 = (unsigned short*)vx;
    unsigned short* px16 = (unsigned short*)px;

    const int tid = threadIdx.x, lane = tid & 31, w = tid >> 5;
    const int wm = w >> 1, wn = w & 1, g = lane >> 2, t4 = lane & 3;
    const int q0 = blockIdx.x * 64, h = blockIdx.y, b = blockIdx.z;
    const size_t base = (size_t)b * Sdim * Hdim + h * 64;
    const int r0 = wm * 16 + g, r1 = r0 + 8;

    for (int i = tid; i < Sdim; i += 256)
        mbias[i] = (1.f - (float)amask[b * Sdim + i]) * -10000.f;

    for (int i = tid; i < 4096; i += 256) {
        int r = i >> 6, d = i & 63;
        float xv = Q[base + (size_t)(q0 + r) * Hdim + d];
        __nv_bfloat16 hh, ll;
        split2(xv, hh, ll);
        unsigned short uh = *(unsigned short*)&hh, ul = *(unsigned short*)&ll;
        int o = r * 200 + 3 * d;
        qx16[o] = uh; qx16[o + 1] = ul; qx16[o + 2] = uh;
    }
    __syncthreads();

    float sacc[32][4];
#pragma unroll
    for (int i = 0; i < 32; i++)
#pragma unroll
        for (int j = 0; j < 4; j++) sacc[i][j] = 0.f;

#pragma unroll
    for (int kb = 0; kb < 8; kb++) {
        for (int i = tid; i < 4096; i += 256) {
            int kk = i >> 6, d = i & 63;
            float xv = Kp[base + (size_t)(kb * 64 + kk) * Hdim + d];
            __nv_bfloat16 hh, ll;
            split2(xv, hh, ll);
            unsigned short uh = *(unsigned short*)&hh, ul = *(unsigned short*)&ll;
            int e = 3 * d;
            kx16[(e >> 1) * 144 + kk * 2 + (e & 1)] = uh;
            kx16[((e + 1) >> 1) * 144 + kk * 2 + ((e + 1) & 1)] = uh;
            kx16[((e + 2) >> 1) * 144 + kk * 2 + ((e + 2) & 1)] = ul;
        }
        __syncthreads();
#pragma unroll
        for (int s = 0; s < 12; s++) {
            unsigned int a[4];
            int ar = r0 * 100 + s * 8 + t4;
            a[0] = qx[ar]; a[1] = qx[ar + 800]; a[2] = qx[ar + 4]; a[3] = qx[ar + 804];
#pragma unroll
            for (int j = 0; j < 4; j++) {
                unsigned int bb[2];
                int br = (s * 8 + t4) * 72 + wn * 32 + j * 8 + g;
                bb[0] = kx[br]; bb[1] = kx[br + 288];
                MMA16816(sacc[kb * 4 + j], a, bb);
            }
        }
        __syncthreads();
    }

    float rm0 = -1e30f, rm1 = -1e30f;
#pragma unroll
    for (int kb = 0; kb < 8; kb++)
#pragma unroll
        for (int j = 0; j < 4; j++) {
            int c = kb * 64 + wn * 32 + j * 8 + 2 * t4;
            float m0 = mbias[c], m1 = mbias[c + 1];
            float* A = sacc[kb * 4 + j];
            A[0] = A[0] * 0.125f + m0;
            A[1] = A[1] * 0.125f + m1;
            A[2] = A[2] * 0.125f + m0;
            A[3] = A[3] * 0.125f + m1;
            rm0 = fmaxf(rm0, fmaxf(A[0], A[1]));
            rm1 = fmaxf(rm1, fmaxf(A[2], A[3]));
        }
    rm0 = fmaxf(rm0, __shfl_xor_sync(0xffffffffu, rm0, 1));
    rm0 = fmaxf(rm0, __shfl_xor_sync(0xffffffffu, rm0, 2));
    rm1 = fmaxf(rm1, __shfl_xor_sync(0xffffffffu, rm1, 1));
    rm1 = fmaxf(rm1, __shfl_xor_sync(0xffffffffu, rm1, 2));
    if (t4 == 0) {
        partmax[r0 * 2 + wn] = rm0;
        partmax[r1 * 2 + wn] = rm1;
    }
    __syncthreads();
    if (tid < 64) rowmax[tid] = fmaxf(partmax[tid * 2], partmax[tid * 2 + 1]);
    __syncthreads();
    const float mx0 = rowmax[r0], mx1 = rowmax[r1];

    float oacc[4][4];
#pragma unroll
    for (int j = 0; j < 4; j++)
#pragma unroll
        for (int r = 0; r < 4; r++) oacc[j][r] = 0.f;
    float sum0 = 0.f, sum1 = 0.f;

#pragma unroll
    for (int kb = 0; kb < 8; kb++) {
        for (int i = tid; i < 4096; i += 256) {
            int kk = i >> 6, d = i & 63;
            float xv = Vp[base + (size_t)(kb * 64 + kk) * Hdim + d];
            __nv_bfloat16 hh, ll;
            split2(xv, hh, ll);
            unsigned short uh = *(unsigned short*)&hh, ul = *(unsigned short*)&ll;
            int e = 3 * kk;
            vx16[(e >> 1) * 144 + d * 2 + (e & 1)] = uh;
            vx16[((e + 1) >> 1) * 144 + d * 2 + ((e + 1) & 1)] = uh;
            vx16[((e + 2) >> 1) * 144 + d * 2 + ((e + 2) & 1)] = ul;
        }
#pragma unroll
        for (int j = 0; j < 4; j++) {
            float* A = sacc[kb * 4 + j];
#pragma unroll
            for (int c01 = 0; c01 < 2; c01++) {
                int lc = wn * 32 + j * 8 + 2 * t4 + c01;
                float p0 = fexp(A[c01] - mx0);
                float p1 = fexp(A[2 + c01] - mx1);
                sum0 += p0;
                sum1 += p1;
                __nv_bfloat16 hh, ll;
                split2(p0, hh, ll);
                int o0 = r0 * 200 + 3 * lc;
                px16[o0] = *(unsigned short*)&hh;
                px16[o0 + 1] = *(unsigned short*)&ll;
                px16[o0 + 2] = *(unsigned short*)&hh;
                split2(p1, hh, ll);
                int o1 = r1 * 200 + 3 * lc;
                px16[o1] = *(unsigned short*)&hh;
                px16[o1 + 1] = *(unsigned short*)&ll;
                px16[o1 + 2] = *(unsigned short*)&hh;
            }
        }
        __syncthreads();
#pragma unroll
        for (int s = 0; s < 12; s++) {
            unsigned int a[4];
            int ar = r0 * 100 + s * 8 + t4;
            a[0] = px[ar]; a[1] = px[ar + 800]; a[2] = px[ar + 4]; a[3] = px[ar + 804];
#pragma unroll
            for (int j2 = 0; j2 < 4; j2++) {
                unsigned int bb[2];
                int br = (s * 8 + t4) * 72 + wn * 32 + j2 * 8 + g;
                bb[0] = vx[br]; bb[1] = vx[br + 288];
                MMA16816(oacc[j2], a, bb);
            }
        }
        __syncthreads();
    }

    sum0 += __shfl_xor_sync(0xffffffffu, sum0, 1);
    sum0 += __shfl_xor_sync(0xffffffffu, sum0, 2);
    sum1 += __shfl_xor_sync(0xffffffffu, sum1, 1);
    sum1 += __shfl_xor_sync(0xffffffffu, sum1, 2);
    if (t4 == 0) {
        partsum[r0 * 2 + wn] = sum0;
        partsum[r1 * 2 + wn] = sum1;
    }
    __syncthreads();
    if (tid < 64) rowsum[tid] = partsum[tid * 2] + partsum[tid * 2 + 1];
    __syncthreads();
    const float inv0 = 1.f / rowsum[r0];
    const float inv1 = 1.f / rowsum[r1];

#pragma unroll
    for (int j2 = 0; j2 < 4; j2++) {
        int dcol = wn * 32 + j2 * 8 + 2 * t4;
        int mrow0 = b * Sdim + q0 + r0;
        int mrow1 = b * Sdim + q0 + r1;
        __nv_bfloat16* p0 = Oext + (size_t)mrow0 * KE_H + 3 * (h * 64 + dcol);
        write_ext3(p0, oacc[j2][0] * inv0);
        write_ext3(p0 + 3, oacc[j2][1] * inv0);
        __nv_bfloat16* p1 = Oext + (size_t)mrow1 * KE_H + 3 * (h * 64 + dcol);
        write_ext3(p1, oacc[j2][2] * inv1);
        write_ext3(p1 + 3, oacc[j2][3] * inv1);
    }
}

// ---------------- classifier ----------------
__global__ void clf_kernel(const float* __restrict__ X, const float* __restrict__ W,
                           const float* __restrict__ bias, float* __restrict__ F) {
    __shared__ float red[8][Ldim];
    int m = blockIdx.x;
    int tid = threadIdx.x;
    float acc[Ldim];
#pragma unroll
    for (int j = 0; j < Ldim; j++) acc[j] = 0.f;
    for (int k = tid; k < Hdim; k += 256) {
        float x = X[(size_t)m * Hdim + k];
#pragma unroll
        for (int j = 0; j < Ldim; j++) acc[j] += x * W[k * Ldim + j];
    }
    int lane = tid & 31, w = tid >> 5;
#pragma unroll
    for (int j = 0; j < Ldim; j++)
#pragma unroll
        for (int o = 16; o; o >>= 1) acc[j] += __shfl_down_sync(0xffffffffu, acc[j], o);
    if (lane == 0)
#pragma unroll
        for (int j = 0; j < Ldim; j++) red[w][j] = acc[j];
    __syncthreads();
    if (tid < Ldim) {
        float s = bias[tid];
#pragma unroll
        for (int ww = 0; ww < 8; ww++) s += red[ww][tid];
        F[(size_t)m * Ldim + tid] = s;
    }
}

// ---------------- CRF numerator ----------------
__global__ void crf_num_kernel(const float* __restrict__ feats, const int* __restrict__ amask,
                               const int* __restrict__ labels, const float* __restrict__ start,
                               const float* __restrict__ endv, const float* __restrict__ trans,
                               float* __restrict__ num) {
    __shared__ float red[8];
    int b = blockIdx.x;
    int tid = threadIdx.x;
    float s = 0.f, msum = 0.f;
    for (int t = tid; t < Sdim; t += 256) {
        int tag = labels[b * Sdim + t];
        float em = feats[(size_t)(b * Sdim + t) * Ldim + tag];
        float m = (float)amask[b * Sdim + t];
        msum += m;
        if (t == 0) {
            s += start[tag] + em;
        } else {
            int pt = labels[b * Sdim + t - 1];
            s += (em + trans[pt * Ldim + tag]) * m;
        }
    }
    float stotal = blk_sum256(s, red);
    float mtotal = blk_sum256(msum, red);
    if (tid == 0) {
        int last = (int)(mtotal + 0.5f) - 1;
        num[b] = stotal + endv[labels[b * Sdim + last]];
    }
}

// ---------------- CRF forward ----------------
__global__ void crf_fwd_kernel(const float* __restrict__ feats, const int* __restrict__ amask,
                               const float* __restrict__ start, const float* __restrict__ endv,
                               const float* __restrict__ trans, float* __restrict__ logZ) {
    int b = threadIdx.x >> 5;
    int j = threadIdx.x & 31;
    bool act = j < Ldim;
    float tr[Ldim];
#pragma unroll
    for (int i = 0; i < Ldim; i++) tr[i] = act ? trans[i * Ldim + j] : 0.f;
    float score = act ? start[j] + feats[(size_t)(b * Sdim) * Ldim + j] : -1e30f;
    for (int t = 1; t < Sdim; t++) {
        float e = act ? feats[(size_t)(b * Sdim + t) * Ldim + j] : 0.f;
        int m = amask[b * Sdim + t];
        float v[Ldim];
        float mx = -1e30f;
#pragma unroll
        for (int i = 0; i < Ldim; i++) {
            float si = __shfl_sync(0xffffffffu, score, i);
            v[i] = si + tr[i];
            mx = fmaxf(mx, v[i]);
        }
        float ssum = 0.f;
#pragma unroll
        for (int i = 0; i < Ldim; i++) ssum += expf(v[i] - mx);
        float nxt = mx + logf(ssum) + e;
        if (act && m > 0) score = nxt;
    }
    float tot = act ? score + endv[j] : -1e30f;
    float mx = tot;
#pragma unroll
    for (int o = 16; o; o >>= 1) mx = fmaxf(mx, __shfl_xor_sync(0xffffffffu, mx, o));
    float ex = act ? expf(tot - mx) : 0.f;
#pragma unroll
    for (int o = 16; o; o >>= 1) ex += __shfl_xor_sync(0xffffffffu, ex, o);
    if (j == 0) logZ[b] = mx + logf(ex);
}

// ---------------- Viterbi ----------------
__global__ void viterbi_kernel(const float* __restrict__ feats, const int* __restrict__ amask,
                               const float* __restrict__ start, const float* __restrict__ endv,
                               const float* __restrict__ trans, int* __restrict__ tags) {
    __shared__ unsigned char hist[(Sdim - 1) * Ldim];
    int b = blockIdx.x;
    int j = threadIdx.x;
    bool act = j < Ldim;
    float tr[Ldim];
#pragma unroll
    for (int i = 0; i < Ldim; i++) tr[i] = act ? trans[i * Ldim + j] : 0.f;
    float score = act ? start[j] + feats[(size_t)(b * Sdim) * Ldim + j] : -1e30f;
    for (int t = 1; t < Sdim; t++) {
        float e = act ? feats[(size_t)(b * Sdim + t) * Ldim + j] : 0.f;
        int m = amask[b * Sdim + t];
        float best = -1e30f;
        int barg = 0;
#pragma unroll
        for (int i = 0; i < Ldim; i++) {
            float si = __shfl_sync(0xffffffffu, score, i);
            float v = si + tr[i];
            if (v > best) { best = v; barg = i; }
        }
        if (act) {
            hist[(t - 1) * Ldim + j] = (unsigned char)barg;
            float nxt = best + e;
            if (m > 0) score = nxt;
        }
    }
    __syncwarp();
    float tot = act ? score + endv[j] : -1e30f;
    float bb = tot;
    int bj = act ? j : 0;
#pragma unroll
    for (int o = 16; o; o >>= 1) {
        float ov = __shfl_down_sync(0xffffffffu, bb, o);
        int oj = __shfl_down_sync(0xffffffffu, bj, o);
        if (ov > bb) { bb = ov; bj = oj; }
    }
    if (j == 0) {
        int tag = bj;
        tags[b * Sdim + Sdim - 1] = tag;
        for (int t = Sdim - 2; t >= 0; t--) {
            tag = hist[t * Ldim + tag];
            tags[b * Sdim + t] = tag;
        }
    }
}

// ---------------- finalize ----------------
__global__ void finalize_kernel(const float* __restrict__ logZ, const float* __restrict__ num,
                                const int* __restrict__ tags, float* __restrict__ out,
                                int out_size) {
    int i = blockIdx.x * blockDim.x + threadIdx.x;
    if (i >= out_size) return;
    if (i == 0) {
        float s = 0.f;
        for (int b = 0; b < Bdim; b++) s += logZ[b] - num[b];
        out[0] = s * (1.f / Bdim);
    } else if (i - 1 < Bdim * Sdim) {
        out[i] = (float)tags[i - 1];
    } else {
        out[i] = 0.f;
    }
}

// ---------------- host launch ----------------
extern "C" void kernel_launch(void* const* d_in, const int* in_sizes, int n_in,
                              void* d_out, int out_size) {
    const float* word_emb = (const float*)d_in[0];
    const float* pos_emb  = (const float*)d_in[1];
    const float* type_emb = (const float*)d_in[2];
    const float* eln_s    = (const float*)d_in[3];
    const float* eln_b    = (const float*)d_in[4];
    const float* Wq = (const float*)d_in[5];
    const float* bq = (const float*)d_in[6];
    const float* Wk = (const float*)d_in[7];
    const float* bk = (const float*)d_in[8];
    const float* Wv = (const float*)d_in[9];
    const float* bv = (const float*)d_in[10];
    const float* Wo = (const float*)d_in[11];
    const float* bo = (const float*)d_in[12];
    const float* ln1s = (const float*)d_in[13];
    const float* ln1b = (const float*)d_in[14];
    const float* W1 = (const float*)d_in[15];
    const float* b1 = (const float*)d_in[16];
    const float* W2 = (const float*)d_in[17];
    const float* b2 = (const float*)d_in[18];
    const float* ln2s = (const float*)d_in[19];
    const float* ln2b = (const float*)d_in[20];
    const float* clfW = (const float*)d_in[21];
    const float* clfb = (const float*)d_in[22];
    const float* crf_start = (const float*)d_in[23];
    const float* crf_end   = (const float*)d_in[24];
    const float* crf_trans = (const float*)d_in[25];
    const int* input_ids   = (const int*)d_in[26];
    const int* token_type  = (const int*)d_in[27];
    const int* attn_mask   = (const int*)d_in[28];
    const int* labels      = (const int*)d_in[29];

    float *h, *q, *k, *v, *t, *feats, *logZ, *num;
    int* tags;
    __nv_bfloat16 *hext, *ctxext, *ffext;
    unsigned int *Wqp, *Wkp, *Wvp, *Wop, *W1p, *W2p;
    cudaGetSymbolAddress((void**)&h, g_h);
    cudaGetSymbolAddress((void**)&q, g_q);
    cudaGetSymbolAddress((void**)&k, g_k);
    cudaGetSymbolAddress((void**)&v, g_v);
    cudaGetSymbolAddress((void**)&t, g_t);
    cudaGetSymbolAddress((void**)&feats, g_feats);
    cudaGetSymbolAddress((void**)&logZ, g_logZ);
    cudaGetSymbolAddress((void**)&num, g_num);
    cudaGetSymbolAddress((void**)&tags, g_tags);
    cudaGetSymbolAddress((void**)&hext, g_hext);
    cudaGetSymbolAddress((void**)&ctxext, g_ctxext);
    cudaGetSymbolAddress((void**)&ffext, g_ffext);
    cudaGetSymbolAddress((void**)&Wqp, g_Wqp);
    cudaGetSymbolAddress((void**)&Wkp, g_Wkp);
    cudaGetSymbolAddress((void**)&Wvp, g_Wvp);
    cudaGetSymbolAddress((void**)&Wop, g_Wop);
    cudaGetSymbolAddress((void**)&W1p, g_W1p);
    cudaGetSymbolAddress((void**)&W2p, g_W2p);

    cudaFuncSetAttribute(attn_kernel, cudaFuncAttributeMaxDynamicSharedMemorySize, ATTN_SMEM);
    cudaFuncSetAttribute(gemm_k1, cudaFuncAttributeMaxDynamicSharedMemorySize, GEMM_SMEM);
    cudaFuncSetAttribute(gemm_k1w, cudaFuncAttributeMaxDynamicSharedMemorySize, GEMM_SMEM_W);
    cudaFuncSetAttribute(gemm_k3w, cudaFuncAttributeMaxDynamicSharedMemorySize, GEMM_SMEM_W);

    // weight conversion: 3D grid, no runtime division
    convP_kernel<<<dim3(Hdim / 256, PKH, NLnum), 256>>>(Wq, Wqp, Hdim, Hdim);
    convP_kernel<<<dim3(Hdim / 256, PKH, NLnum), 256>>>(Wk, Wkp, Hdim, Hdim);
    convP_kernel<<<dim3(Hdim / 256, PKH, NLnum), 256>>>(Wv, Wvp, Hdim, Hdim);
    convP_kernel<<<dim3(Hdim / 256, PKH, NLnum), 256>>>(Wo, Wop, Hdim, Hdim);
    convP_kernel<<<dim3(FFdim / 256, PKH, NLnum), 256>>>(W1, W1p, Hdim, FFdim);
    convP_kernel<<<dim3(Hdim / 256, PKF, NLnum), 256>>>(W2, W2p, FFdim, Hdim);
    embed_ln_kernel<<<Mtot, 256>>>(word_emb, pos_emb, type_emb, eln_s, eln_b,
                                   input_ids, token_type, h, hext);

    dim3 gQKV(Hdim / 256, Mtot / 128, 3);
    dim3 gFF1(FFdim / 256, Mtot / 128);
    dim3 gProj(Hdim / 128, Mtot / 128);
    dim3 gAttn(Sdim / 64, NHnum, Bdim);
    const size_t woff = (size_t)PKH * Hdim;
    const size_t w1off = (size_t)PKH * FFdim;
    const size_t w2off = (size_t)PKF * Hdim;

    for (int l = 0; l < NLnum; l++) {
        gemm_k3w<<<gQKV, 256, GEMM_SMEM_W>>>(hext, Wqp + l * woff, Wkp + l * woff,
                                             Wvp + l * woff, bq + l * Hdim, bk + l * Hdim,
                                             bv + l * Hdim, q, k, v, KE_H);
        attn_kernel<<<gAttn, 256, ATTN_SMEM>>>(q, k, v, attn_mask, ctxext);
        gemm_k1<<<gProj, 256, GEMM_SMEM>>>(ctxext, Wop + l * woff, bo + l * Hdim, h, t,
                                           nullptr, Hdim, KE_H, 0, 1, 0);
        ln_kernel<<<Mtot, 256>>>(t, ln1s + l * Hdim, ln1b + l * Hdim, h, hext);
        gemm_k1w<<<gFF1, 256, GEMM_SMEM_W>>>(hext, W1p + l * w1off, b1 + l * FFdim, nullptr,
                                             ffext, FFdim, KE_H, 1, 1);
        gemm_k1<<<gProj, 256, GEMM_SMEM>>>(ffext, W2p + l * w2off, b2 + l * Hdim, h, t,
                                           nullptr, Hdim, KE_FF, 0, 1, 0);
        ln_kernel<<<Mtot, 256>>>(t, ln2s + l * Hdim, ln2b + l * Hdim, h, hext);
    }

    clf_kernel<<<Mtot, 256>>>(h, clfW, clfb, feats);
    crf_num_kernel<<<Bdim, 256>>>(feats, attn_mask, labels, crf_start, crf_end, crf_trans, num);
    crf_fwd_kernel<<<1, 256>>>(feats, attn_mask, crf_start, crf_end, crf_trans, logZ);
    viterbi_kernel<<<Bdim, 32>>>(feats, attn_mask, crf_start, crf_end, crf_trans, tags);

    int nfin = (out_size + 255) / 256;
    if (nfin < 1) nfin = 1;
    finalize_kernel<<<nfin, 256>>>(logZ, num, tags, (float*)d_out, out_size);
}

// round 13
// speedup vs baseline: 1.2024x; 1.0342x over previous
#include <cuda_runtime.h>
#include <cuda_bf16.h>
#include <math.h>

#define Mtot  4096
#define Hdim  768
#define FFdim 3072
#define NHnum 12
#define DHdim 64
#define Sdim  512
#define Bdim  8
#define Ldim  9
#define NLnum 12

#define KE_H  (3 * Hdim)    // 2304
#define KE_FF (3 * FFdim)   // 9216

// ---------------- scratch ----------------
__device__ float g_h[Mtot * Hdim];
__device__ float g_q[Mtot * Hdim];
__device__ float g_k[Mtot * Hdim];
__device__ float g_v[Mtot * Hdim];
__device__ float g_t[Mtot * Hdim];
__device__ float g_feats[Mtot * Ldim];
__device__ float g_logZ[Bdim];
__device__ float g_num[Bdim];
__device__ int   g_tags[Bdim * Sdim];

__device__ __align__(256) __nv_bfloat16 g_hext[Mtot * KE_H];
__device__ __align__(256) __nv_bfloat16 g_ctxext[Mtot * KE_H];
__device__ __align__(256) __nv_bfloat16 g_ffext[(size_t)Mtot * KE_FF];

#define PKH (3 * Hdim / 2)    // 1152
#define PKF (3 * FFdim / 2)   // 4608
__device__ __align__(256) unsigned int g_Wqp[NLnum * PKH * Hdim];
__device__ __align__(256) unsigned int g_Wkp[NLnum * PKH * Hdim];
__device__ __align__(256) unsigned int g_Wvp[NLnum * PKH * Hdim];
__device__ __align__(256) unsigned int g_Wop[NLnum * PKH * Hdim];
__device__ __align__(256) unsigned int g_W1p[(size_t)NLnum * PKH * FFdim];
__device__ __align__(256) unsigned int g_W2p[(size_t)NLnum * PKF * Hdim];

// ---------------- helpers ----------------
__device__ __forceinline__ float blk_sum256(float v, float* red) {
    int lane = threadIdx.x & 31, w = threadIdx.x >> 5;
#pragma unroll
    for (int o = 16; o; o >>= 1) v += __shfl_xor_sync(0xffffffffu, v, o);
    __syncthreads();
    if (lane == 0) red[w] = v;
    __syncthreads();
    float s = 0.f;
#pragma unroll
    for (int i = 0; i < 8; i++) s += red[i];
    return s;
}

__device__ __forceinline__ void split2(float x, __nv_bfloat16& hi, __nv_bfloat16& lo) {
    hi = __float2bfloat16(x);
    lo = __float2bfloat16(x - __bfloat162float(hi));
}

__device__ __forceinline__ void write_ext3(__nv_bfloat16* p, float x) {
    __nv_bfloat16 h, l;
    split2(x, h, l);
    p[0] = h; p[1] = l; p[2] = h;
}

__device__ __forceinline__ float fexp(float x) {
    float t = x * 1.4426950408889634f;
    t = fmaxf(t, -126.0f);
    float fl = floorf(t);
    float f = t - fl;
    float p = 1.525273e-5f;
    p = fmaf(p, f, 1.5403530e-4f);
    p = fmaf(p, f, 1.3333558e-3f);
    p = fmaf(p, f, 9.6181291e-3f);
    p = fmaf(p, f, 5.5504109e-2f);
    p = fmaf(p, f, 2.4022651e-1f);
    p = fmaf(p, f, 6.9314718e-1f);
    p = fmaf(p, f, 1.0f);
    return p * __int_as_float(((int)fl + 127) << 23);
}

// ---------------- weight conversion (no runtime division) ----------------
__global__ void convP_kernel(const float* __restrict__ W, unsigned int* __restrict__ out,
                             int K, int N) {
    int n = blockIdx.x * 256 + threadIdx.x;
    int i = blockIdx.y;
    int l = blockIdx.z;
    int PK = 3 * K / 2;
    int s0 = 2 * i, s1 = s0 + 1;
    int k0 = s0 / 3, r0 = s0 - 3 * k0;
    int k1 = s1 / 3, r1 = s1 - 3 * k1;
    const float* Wl = W + (size_t)l * K * N;
    float w0 = Wl[(size_t)k0 * N + n];
    float w1 = Wl[(size_t)k1 * N + n];
    __nv_bfloat16 h0, l0, h1, l1;
    split2(w0, h0, l0);
    split2(w1, h1, l1);
    __nv_bfloat16 v0 = (r0 == 2) ? l0 : h0;
    __nv_bfloat16 v1 = (r1 == 2) ? l1 : h1;
    __nv_bfloat162 pr(v0, v1);
    out[((size_t)l * PK + i) * N + n] = *reinterpret_cast<unsigned int*>(&pr);
}

// ---------------- embedding + LayerNorm ----------------
__global__ void embed_ln_kernel(const float* __restrict__ we, const float* __restrict__ pe,
                                const float* __restrict__ te, const float* __restrict__ gs,
                                const float* __restrict__ gb, const int* __restrict__ ids,
                                const int* __restrict__ tts, float* __restrict__ out,
                                __nv_bfloat16* __restrict__ ext) {
    __shared__ float red[8];
    int m = blockIdx.x;
    int s = m & (Sdim - 1);
    int id = ids[m], tt = tts[m];
    float vals[3];
    float lsum = 0.f;
#pragma unroll
    for (int u = 0; u < 3; u++) {
        int j = threadIdx.x + u * 256;
        float v = we[(size_t)id * Hdim + j] + pe[(size_t)s * Hdim + j] + te[(size_t)tt * Hdim + j];
        vals[u] = v;
        lsum += v;
    }
    float mean = blk_sum256(lsum, red) * (1.f / Hdim);
    float lsq = 0.f;
#pragma unroll
    for (int u = 0; u < 3; u++) { float d = vals[u] - mean; lsq += d * d; }
    float var = blk_sum256(lsq, red) * (1.f / Hdim);
    float inv = rsqrtf(var + 1e-12f);
#pragma unroll
    for (int u = 0; u < 3; u++) {
        int j = threadIdx.x + u * 256;
        float y = (vals[u] - mean) * inv * gs[j] + gb[j];
        out[(size_t)m * Hdim + j] = y;
        write_ext3(ext + (size_t)m * KE_H + 3 * j, y);
    }
}

// ---------------- LayerNorm ----------------
__global__ void ln_kernel(const float* __restrict__ x, const float* __restrict__ gs,
                          const float* __restrict__ gb, float* __restrict__ y,
                          __nv_bfloat16* __restrict__ ext) {
    __shared__ float red[8];
    int m = blockIdx.x;
    const float* xr = x + (size_t)m * Hdim;
    float vals[3];
    float lsum = 0.f;
#pragma unroll
    for (int u = 0; u < 3; u++) {
        vals[u] = xr[threadIdx.x + u * 256];
        lsum += vals[u];
    }
    float mean = blk_sum256(lsum, red) * (1.f / Hdim);
    float lsq = 0.f;
#pragma unroll
    for (int u = 0; u < 3; u++) { float d = vals[u] - mean; lsq += d * d; }
    float var = blk_sum256(lsq, red) * (1.f / Hdim);
    float inv = rsqrtf(var + 1e-12f);
#pragma unroll
    for (int u = 0; u < 3; u++) {
        int j = threadIdx.x + u * 256;
        float yy = (vals[u] - mean) * inv * gs[j] + gb[j];
        y[(size_t)m * Hdim + j] = yy;
        write_ext3(ext + (size_t)m * KE_H + 3 * j, yy);
    }
}

// ================= shared GEMM bits =================
__device__ __forceinline__ void cp16(unsigned int saddr, const void* gptr) {
    asm volatile("cp.async.cg.shared.global [%0], [%1], 16;\n" ::"r"(saddr), "l"(gptr));
}
__device__ __forceinline__ void cp_commit() { asm volatile("cp.async.commit_group;\n"); }
__device__ __forceinline__ void cp_wait2() { asm volatile("cp.async.wait_group 2;\n"); }

#define MMA16816(d, a, b)                                                      \
    asm volatile(                                                              \
        "mma.sync.aligned.m16n8k16.row.col.f32.bf16.bf16.f32 "                 \
        "{%0,%1,%2,%3}, {%4,%5,%6,%7}, {%8,%9}, {%0,%1,%2,%3};\n"              \
        : "+f"(d[0]), "+f"(d[1]), "+f"(d[2]), "+f"(d[3])                       \
        : "r"(a[0]), "r"(a[1]), "r"(a[2]), "r"(a[3]), "r"(b[0]), "r"(b[1]))

#define BKE 48
#define BKP 24
#define AS_STRIDE 28
#define BS_STRIDE 136

// ================= 64x128 GEMM (O proj, FF2) — wave-balanced =================
#define STAGE_WORDS_H (64 * AS_STRIDE + BKP * BS_STRIDE)   // 1792+3264 = 5056
#define GEMM_SMEM_H (4 * STAGE_WORDS_H * 4)                // 80896 B

__device__ __forceinline__ void gemm_core_h(const __nv_bfloat16* __restrict__ A,
                                            const unsigned int* __restrict__ B,
                                            const float* __restrict__ bias,
                                            const float* __restrict__ res,
                                            float* __restrict__ Cf,
                                            int N, int KE, unsigned int* smem) {
    const int tid = threadIdx.x;
    const int lane = tid & 31;
    const int wid = tid >> 5;
    const int warp_m = wid >> 2;   // 0..1 (32 rows each)
    const int warp_n = wid & 3;    // 0..3 (32 cols each)
    const int m0 = blockIdx.y * 64;
    const int n0 = blockIdx.x * 128;
    const int T = KE / BKE;
    const int g = lane >> 2, t4 = lane & 3;

    float acc[2][4][4];
#pragma unroll
    for (int i = 0; i < 2; i++)
#pragma unroll
        for (int j = 0; j < 4; j++)
#pragma unroll
            for (int r = 0; r < 4; r++) acc[i][j][r] = 0.f;

    const unsigned int sbase = (unsigned int)__cvta_generic_to_shared(smem);

    auto load_stage = [&](int tile, int stg) {
        unsigned int abase = sbase + (unsigned int)(stg * STAGE_WORDS_H) * 4u;
        unsigned int bbase = abase + 64u * AS_STRIDE * 4u;
        const __nv_bfloat16* Ag = A + (size_t)m0 * KE + tile * BKE;
        // 64 rows x 6 chunks = 384 cp16
        {
            int i = tid;
            int r = i / 6, c = i % 6;
            cp16(abase + (unsigned int)(r * AS_STRIDE + c * 4) * 4u,
                 Ag + (size_t)r * KE + c * 8);
            i = tid + 256;
            if (i < 384) {
                r = i / 6; c = i % 6;
                cp16(abase + (unsigned int)(r * AS_STRIDE + c * 4) * 4u,
                     Ag + (size_t)r * KE + c * 8);
            }
        }
        const unsigned int* Bg = B + (size_t)(tile * BKP) * N + n0;
#pragma unroll
        for (int l = 0; l < 3; l++) {
            int i = tid + l * 256;
            int r = i >> 5, c = i & 31;
            cp16(bbase + (unsigned int)(r * BS_STRIDE + c * 4) * 4u,
                 Bg + (size_t)r * N + c * 4);
        }
    };

    load_stage(0, 0); cp_commit();
    load_stage(1, 1); cp_commit();
    load_stage(2, 2); cp_commit();

    for (int t = 0; t < T; t++) {
        cp_wait2();
        __syncthreads();
        if (t + 3 < T) load_stage(t + 3, (t + 3) & 3);
        cp_commit();

        const unsigned int* As = smem + (size_t)(t & 3) * STAGE_WORDS_H;
        const unsigned int* Bs = As + 64 * AS_STRIDE;
#pragma unroll
        for (int s = 0; s < 3; s++) {
            unsigned int a[2][4], b[4][2];
#pragma unroll
            for (int mi = 0; mi < 2; mi++) {
                int r = warp_m * 32 + mi * 16 + g;
                int cp = s * 8 + t4;
                a[mi][0] = As[r * AS_STRIDE + cp];
                a[mi][1] = As[(r + 8) * AS_STRIDE + cp];
                a[mi][2] = As[r * AS_STRIDE + cp + 4];
                a[mi][3] = As[(r + 8) * AS_STRIDE + cp + 4];
            }
#pragma unroll
            for (int nj = 0; nj < 4; nj++) {
                int n = warp_n * 32 + nj * 8 + g;
                b[nj][0] = Bs[(s * 8 + t4) * BS_STRIDE + n];
                b[nj][1] = Bs[(s * 8 + t4 + 4) * BS_STRIDE + n];
            }
#pragma unroll
            for (int mi = 0; mi < 2; mi++)
#pragma unroll
                for (int nj = 0; nj < 4; nj++) MMA16816(acc[mi][nj], a[mi], b[nj]);
        }
        __syncthreads();
    }

#pragma unroll
    for (int mi = 0; mi < 2; mi++) {
        int row0 = m0 + warp_m * 32 + mi * 16 + g;
#pragma unroll
        for (int nj = 0; nj < 4; nj++) {
            int col = n0 + warp_n * 32 + nj * 8 + t4 * 2;
            float b0 = bias[col], b1 = bias[col + 1];
#pragma unroll
            for (int half = 0; half < 2; half++) {
                int row = row0 + half * 8;
                float2 rr = *(const float2*)(res + (size_t)row * N + col);
                float v0 = acc[mi][nj][half * 2 + 0] + b0 + rr.x;
                float v1 = acc[mi][nj][half * 2 + 1] + b1 + rr.y;
                *(float2*)(Cf + (size_t)row * N + col) = make_float2(v0, v1);
            }
        }
    }
}

__global__ void __launch_bounds__(256, 2) gemm_kh(const __nv_bfloat16* __restrict__ A,
                                                  const unsigned int* __restrict__ B,
                                                  const float* __restrict__ bias,
                                                  const float* __restrict__ res,
                                                  float* __restrict__ Cf, int N, int KE) {
    extern __shared__ unsigned int smem[];
    gemm_core_h(A, B, bias, res, Cf, N, KE, smem);
}

// ================= 128x256 GEMM (QKV, FF1) =================
#define BSW_STRIDE 264
#define STAGE_WORDS_W (128 * AS_STRIDE + BKP * BSW_STRIDE)  // 9920
#define GEMM_SMEM_W (4 * STAGE_WORDS_W * 4)                 // 158720 B

__device__ __forceinline__ void gemm_core_w(const __nv_bfloat16* __restrict__ A,
                                            const unsigned int* __restrict__ B,
                                            const float* __restrict__ bias,
                                            float* __restrict__ Cf,
                                            __nv_bfloat16* __restrict__ Ce,
                                            int N, int KE, int act, int outp,
                                            unsigned int* smem) {
    const int tid = threadIdx.x;
    const int lane = tid & 31;
    const int wid = tid >> 5;
    const int warp_m = wid >> 2;
    const int warp_n = wid & 3;
    const int m0 = blockIdx.y * 128;
    const int n0 = blockIdx.x * 256;
    const int T = KE / BKE;
    const int g = lane >> 2, t4 = lane & 3;

    float acc[4][8][4];
#pragma unroll
    for (int i = 0; i < 4; i++)
#pragma unroll
        for (int j = 0; j < 8; j++)
#pragma unroll
            for (int r = 0; r < 4; r++) acc[i][j][r] = 0.f;

    const unsigned int sbase = (unsigned int)__cvta_generic_to_shared(smem);

    auto load_stage = [&](int tile, int stg) {
        unsigned int abase = sbase + (unsigned int)(stg * STAGE_WORDS_W) * 4u;
        unsigned int bbase = abase + 128u * AS_STRIDE * 4u;
        const __nv_bfloat16* Ag = A + (size_t)m0 * KE + tile * BKE;
#pragma unroll
        for (int l = 0; l < 3; l++) {
            int i = tid + l * 256;
            int r = i / 6, c = i % 6;
            cp16(abase + (unsigned int)(r * AS_STRIDE + c * 4) * 4u,
                 Ag + (size_t)r * KE + c * 8);
        }
        const unsigned int* Bg = B + (size_t)(tile * BKP) * N + n0;
#pragma unroll
        for (int l = 0; l < 6; l++) {
            int i = tid + l * 256;
            int r = i >> 6, c = i & 63;
            cp16(bbase + (unsigned int)(r * BSW_STRIDE + c * 4) * 4u,
                 Bg + (size_t)r * N + c * 4);
        }
    };

    load_stage(0, 0); cp_commit();
    load_stage(1, 1); cp_commit();
    load_stage(2, 2); cp_commit();

    for (int t = 0; t < T; t++) {
        cp_wait2();
        __syncthreads();
        if (t + 3 < T) load_stage(t + 3, (t + 3) & 3);
        cp_commit();

        const unsigned int* As = smem + (size_t)(t & 3) * STAGE_WORDS_W;
        const unsigned int* Bs = As + 128 * AS_STRIDE;
#pragma unroll
        for (int s = 0; s < 3; s++) {
            unsigned int a[4][4];
#pragma unroll
            for (int mi = 0; mi < 4; mi++) {
                int r = warp_m * 64 + mi * 16 + g;
                int cp = s * 8 + t4;
                a[mi][0] = As[r * AS_STRIDE + cp];
                a[mi][1] = As[(r + 8) * AS_STRIDE + cp];
                a[mi][2] = As[r * AS_STRIDE + cp + 4];
                a[mi][3] = As[(r + 8) * AS_STRIDE + cp + 4];
            }
#pragma unroll
            for (int nj = 0; nj < 8; nj++) {
                unsigned int b[2];
                int n = warp_n * 64 + nj * 8 + g;
                b[0] = Bs[(s * 8 + t4) * BSW_STRIDE + n];
                b[1] = Bs[(s * 8 + t4 + 4) * BSW_STRIDE + n];
#pragma unroll
                for (int mi = 0; mi < 4; mi++) MMA16816(acc[mi][nj], a[mi], b);
            }
        }
        __syncthreads();
    }

#pragma unroll
    for (int mi = 0; mi < 4; mi++) {
        int row0 = m0 + warp_m * 64 + mi * 16 + g;
#pragma unroll
        for (int nj = 0; nj < 8; nj++) {
            int col = n0 + warp_n * 64 + nj * 8 + t4 * 2;
            float b0 = bias[col], b1 = bias[col + 1];
#pragma unroll
            for (int half = 0; half < 2; half++) {
                int row = row0 + half * 8;
                float v0 = acc[mi][nj][half * 2 + 0] + b0;
                float v1 = acc[mi][nj][half * 2 + 1] + b1;
                if (act) {
                    v0 = 0.5f * v0 * (1.f + erff(v0 * 0.70710678118654752440f));
                    v1 = 0.5f * v1 * (1.f + erff(v1 * 0.70710678118654752440f));
                }
                if (outp == 0) {
                    *(float2*)(Cf + (size_t)row * N + col) = make_float2(v0, v1);
                } else {
                    __nv_bfloat16* p = Ce + (size_t)row * (3 * N) + 3 * col;
                    write_ext3(p, v0);
                    write_ext3(p + 3, v1);
                }
            }
        }
    }
}

__global__ void __launch_bounds__(256, 1) gemm_k1w(const __nv_bfloat16* __restrict__ A,
                                                   const unsigned int* __restrict__ B,
                                                   const float* __restrict__ bias,
                                                   float* __restrict__ Cf,
                                                   __nv_bfloat16* __restrict__ Ce,
                                                   int N, int KE, int act, int outp) {
    extern __shared__ unsigned int smem[];
    gemm_core_w(A, B, bias, Cf, Ce, N, KE, act, outp, smem);
}

__global__ void __launch_bounds__(256, 1) gemm_k3w(const __nv_bfloat16* __restrict__ A,
                                                   const unsigned int* __restrict__ B0,
                                                   const unsigned int* __restrict__ B1,
                                                   const unsigned int* __restrict__ B2,
                                                   const float* __restrict__ bias0,
                                                   const float* __restrict__ bias1,
                                                   const float* __restrict__ bias2,
                                                   float* __restrict__ C0, float* __restrict__ C1,
                                                   float* __restrict__ C2, int KE) {
    extern __shared__ unsigned int smem[];
    int z = blockIdx.z;
    const unsigned int* B = (z == 0) ? B0 : (z == 1) ? B1 : B2;
    const float* bias = (z == 0) ? bias0 : (z == 1) ? bias1 : bias2;
    float* Cf = (z == 0) ? C0 : (z == 1) ? C1 : C2;
    gemm_core_w(A, B, bias, Cf, nullptr, Hdim, KE, 0, 0, smem);
}

// ======== tensor-core attention (split-bf16 3-slot) ========
#define A_OFF_MB 0
#define A_OFF_Q  512
#define A_OFF_K  (512 + 6400)
#define A_OFF_V  (512 + 6400 + 6912)
#define A_OFF_P  (512 + 6400 + 13824)
#define A_OFF_PM (512 + 6400 + 13824 + 6400)
#define A_OFF_RM (A_OFF_PM + 128)
#define A_OFF_PS (A_OFF_RM + 64)
#define A_OFF_RS (A_OFF_PS + 128)
#define ATTN_SMEM ((A_OFF_RS + 64) * 4)

__global__ void __launch_bounds__(256) attn_kernel(const float* __restrict__ Q,
                                                   const float* __restrict__ Kp,
                                                   const float* __restrict__ Vp,
                                                   const int* __restrict__ amask,
                                                   __nv_bfloat16* __restrict__ Oext) {
    extern __shared__ unsigned int sm[];
    float* mbias = (float*)(sm + A_OFF_MB);
    unsigned int* qx = sm + A_OFF_Q;
    unsigned int* kx = sm + A_OFF_K;
    unsigned int* vx = sm + A_OFF_V;
    unsigned int* px = sm + A_OFF_P;
    float* partmax = (float*)(sm + A_OFF_PM);
    float* rowmax = (float*)(sm + A_OFF_RM);
    float* partsum = (float*)(sm + A_OFF_PS);
    float* rowsum = (float*)(sm + A_OFF_RS);
    unsigned short* qx16 = (unsigned short*)qx;
    unsigned short* kx16 = (unsigned short*)kx;
    unsigned short* vx16 = (unsigned short*)vx;
    unsigned short* px16 = (unsigned short*)px;

    const int tid = threadIdx.x, lane = tid & 31, w = tid >> 5;
    const int wm = w >> 1, wn = w & 1, g = lane >> 2, t4 = lane & 3;
    const int q0 = blockIdx.x * 64, h = blockIdx.y, b = blockIdx.z;
    const size_t base = (size_t)b * Sdim * Hdim + h * 64;
    const int r0 = wm * 16 + g, r1 = r0 + 8;

    for (int i = tid; i < Sdim; i += 256)
        mbias[i] = (1.f - (float)amask[b * Sdim + i]) * -10000.f;

    for (int i = tid; i < 4096; i += 256) {
        int r = i >> 6, d = i & 63;
        float xv = Q[base + (size_t)(q0 + r) * Hdim + d];
        __nv_bfloat16 hh, ll;
        split2(xv, hh, ll);
        unsigned short uh = *(unsigned short*)&hh, ul = *(unsigned short*)&ll;
        int o = r * 200 + 3 * d;
        qx16[o] = uh; qx16[o + 1] = ul; qx16[o + 2] = uh;
    }
    __syncthreads();

    float sacc[32][4];
#pragma unroll
    for (int i = 0; i < 32; i++)
#pragma unroll
        for (int j = 0; j < 4; j++) sacc[i][j] = 0.f;

#pragma unroll
    for (int kb = 0; kb < 8; kb++) {
        for (int i = tid; i < 4096; i += 256) {
            int kk = i >> 6, d = i & 63;
            float xv = Kp[base + (size_t)(kb * 64 + kk) * Hdim + d];
            __nv_bfloat16 hh, ll;
            split2(xv, hh, ll);
            unsigned short uh = *(unsigned short*)&hh, ul = *(unsigned short*)&ll;
            int e = 3 * d;
            kx16[(e >> 1) * 144 + kk * 2 + (e & 1)] = uh;
            kx16[((e + 1) >> 1) * 144 + kk * 2 + ((e + 1) & 1)] = uh;
            kx16[((e + 2) >> 1) * 144 + kk * 2 + ((e + 2) & 1)] = ul;
        }
        __syncthreads();
#pragma unroll
        for (int s = 0; s < 12; s++) {
            unsigned int a[4];
            int ar = r0 * 100 + s * 8 + t4;
            a[0] = qx[ar]; a[1] = qx[ar + 800]; a[2] = qx[ar + 4]; a[3] = qx[ar + 804];
#pragma unroll
            for (int j = 0; j < 4; j++) {
                unsigned int bb[2];
                int br = (s * 8 + t4) * 72 + wn * 32 + j * 8 + g;
                bb[0] = kx[br]; bb[1] = kx[br + 288];
                MMA16816(sacc[kb * 4 + j], a, bb);
            }
        }
        __syncthreads();
    }

    float rm0 = -1e30f, rm1 = -1e30f;
#pragma unroll
    for (int kb = 0; kb < 8; kb++)
#pragma unroll
        for (int j = 0; j < 4; j++) {
            int c = kb * 64 + wn * 32 + j * 8 + 2 * t4;
            float m0 = mbias[c], m1 = mbias[c + 1];
            float* A = sacc[kb * 4 + j];
            A[0] = A[0] * 0.125f + m0;
            A[1] = A[1] * 0.125f + m1;
            A[2] = A[2] * 0.125f + m0;
            A[3] = A[3] * 0.125f + m1;
            rm0 = fmaxf(rm0, fmaxf(A[0], A[1]));
            rm1 = fmaxf(rm1, fmaxf(A[2], A[3]));
        }
    rm0 = fmaxf(rm0, __shfl_xor_sync(0xffffffffu, rm0, 1));
    rm0 = fmaxf(rm0, __shfl_xor_sync(0xffffffffu, rm0, 2));
    rm1 = fmaxf(rm1, __shfl_xor_sync(0xffffffffu, rm1, 1));
    rm1 = fmaxf(rm1, __shfl_xor_sync(0xffffffffu, rm1, 2));
    if (t4 == 0) {
        partmax[r0 * 2 + wn] = rm0;
        partmax[r1 * 2 + wn] = rm1;
    }
    __syncthreads();
    if (tid < 64) rowmax[tid] = fmaxf(partmax[tid * 2], partmax[tid * 2 + 1]);
    __syncthreads();
    const float mx0 = rowmax[r0], mx1 = rowmax[r1];

    float oacc[4][4];
#pragma unroll
    for (int j = 0; j < 4; j++)
#pragma unroll
        for (int r = 0; r < 4; r++) oacc[j][r] = 0.f;
    float sum0 = 0.f, sum1 = 0.f;

#pragma unroll
    for (int kb = 0; kb < 8; kb++) {
        for (int i = tid; i < 4096; i += 256) {
            int kk = i >> 6, d = i & 63;
            float xv = Vp[base + (size_t)(kb * 64 + kk) * Hdim + d];
            __nv_bfloat16 hh, ll;
            split2(xv, hh, ll);
            unsigned short uh = *(unsigned short*)&hh, ul = *(unsigned short*)&ll;
            int e = 3 * kk;
            vx16[(e >> 1) * 144 + d * 2 + (e & 1)] = uh;
            vx16[((e + 1) >> 1) * 144 + d * 2 + ((e + 1) & 1)] = uh;
            vx16[((e + 2) >> 1) * 144 + d * 2 + ((e + 2) & 1)] = ul;
        }
#pragma unroll
        for (int j = 0; j < 4; j++) {
            float* A = sacc[kb * 4 + j];
#pragma unroll
            for (int c01 = 0; c01 < 2; c01++) {
                int lc = wn * 32 + j * 8 + 2 * t4 + c01;
                float p0 = fexp(A[c01] - mx0);
                float p1 = fexp(A[2 + c01] - mx1);
                sum0 += p0;
                sum1 += p1;
                __nv_bfloat16 hh, ll;
                split2(p0, hh, ll);
                int o0 = r0 * 200 + 3 * lc;
                px16[o0] = *(unsigned short*)&hh;
                px16[o0 + 1] = *(unsigned short*)&ll;
                px16[o0 + 2] = *(unsigned short*)&hh;
                split2(p1, hh, ll);
                int o1 = r1 * 200 + 3 * lc;
                px16[o1] = *(unsigned short*)&hh;
                px16[o1 + 1] = *(unsigned short*)&ll;
                px16[o1 + 2] = *(unsigned short*)&hh;
            }
        }
        __syncthreads();
#pragma unroll
        for (int s = 0; s < 12; s++) {
            unsigned int a[4];
            int ar = r0 * 100 + s * 8 + t4;
            a[0] = px[ar]; a[1] = px[ar + 800]; a[2] = px[ar + 4]; a[3] = px[ar + 804];
#pragma unroll
            for (int j2 = 0; j2 < 4; j2++) {
                unsigned int bb[2];
                int br = (s * 8 + t4) * 72 + wn * 32 + j2 * 8 + g;
                bb[0] = vx[br]; bb[1] = vx[br + 288];
                MMA16816(oacc[j2], a, bb);
            }
        }
        __syncthreads();
    }

    sum0 += __shfl_xor_sync(0xffffffffu, sum0, 1);
    sum0 += __shfl_xor_sync(0xffffffffu, sum0, 2);
    sum1 += __shfl_xor_sync(0xffffffffu, sum1, 1);
    sum1 += __shfl_xor_sync(0xffffffffu, sum1, 2);
    if (t4 == 0) {
        partsum[r0 * 2 + wn] = sum0;
        partsum[r1 * 2 + wn] = sum1;
    }
    __syncthreads();
    if (tid < 64) rowsum[tid] = partsum[tid * 2] + partsum[tid * 2 + 1];
    __syncthreads();
    const float inv0 = 1.f / rowsum[r0];
    const float inv1 = 1.f / rowsum[r1];

#pragma unroll
    for (int j2 = 0; j2 < 4; j2++) {
        int dcol = wn * 32 + j2 * 8 + 2 * t4;
        int mrow0 = b * Sdim + q0 + r0;
        int mrow1 = b * Sdim + q0 + r1;
        __nv_bfloat16* p0 = Oext + (size_t)mrow0 * KE_H + 3 * (h * 64 + dcol);
        write_ext3(p0, oacc[j2][0] * inv0);
        write_ext3(p0 + 3, oacc[j2][1] * inv0);
        __nv_bfloat16* p1 = Oext + (size_t)mrow1 * KE_H + 3 * (h * 64 + dcol);
        write_ext3(p1, oacc[j2][2] * inv1);
        write_ext3(p1 + 3, oacc[j2][3] * inv1);
    }
}

// ---------------- classifier ----------------
__global__ void clf_kernel(const float* __restrict__ X, const float* __restrict__ W,
                           const float* __restrict__ bias, float* __restrict__ F) {
    __shared__ float red[8][Ldim];
    int m = blockIdx.x;
    int tid = threadIdx.x;
    float acc[Ldim];
#pragma unroll
    for (int j = 0; j < Ldim; j++) acc[j] = 0.f;
    for (int k = tid; k < Hdim; k += 256) {
        float x = X[(size_t)m * Hdim + k];
#pragma unroll
        for (int j = 0; j < Ldim; j++) acc[j] += x * W[k * Ldim + j];
    }
    int lane = tid & 31, w = tid >> 5;
#pragma unroll
    for (int j = 0; j < Ldim; j++)
#pragma unroll
        for (int o = 16; o; o >>= 1) acc[j] += __shfl_down_sync(0xffffffffu, acc[j], o);
    if (lane == 0)
#pragma unroll
        for (int j = 0; j < Ldim; j++) red[w][j] = acc[j];
    __syncthreads();
    if (tid < Ldim) {
        float s = bias[tid];
#pragma unroll
        for (int ww = 0; ww < 8; ww++) s += red[ww][tid];
        F[(size_t)m * Ldim + tid] = s;
    }
}

// ---------------- CRF numerator ----------------
__global__ void crf_num_kernel(const float* __restrict__ feats, const int* __restrict__ amask,
                               const int* __restrict__ labels, const float* __restrict__ start,
                               const float* __restrict__ endv, const float* __restrict__ trans,
                               float* __restrict__ num) {
    __shared__ float red[8];
    int b = blockIdx.x;
    int tid = threadIdx.x;
    float s = 0.f, msum = 0.f;
    for (int t = tid; t < Sdim; t += 256) {
        int tag = labels[b * Sdim + t];
        float em = feats[(size_t)(b * Sdim + t) * Ldim + tag];
        float m = (float)amask[b * Sdim + t];
        msum += m;
        if (t == 0) {
            s += start[tag] + em;
        } else {
            int pt = labels[b * Sdim + t - 1];
            s += (em + trans[pt * Ldim + tag]) * m;
        }
    }
    float stotal = blk_sum256(s, red);
    float mtotal = blk_sum256(msum, red);
    if (tid == 0) {
        int last = (int)(mtotal + 0.5f) - 1;
        num[b] = stotal + endv[labels[b * Sdim + last]];
    }
}

// ---------------- CRF forward ----------------
__global__ void crf_fwd_kernel(const float* __restrict__ feats, const int* __restrict__ amask,
                               const float* __restrict__ start, const float* __restrict__ endv,
                               const float* __restrict__ trans, float* __restrict__ logZ) {
    int b = threadIdx.x >> 5;
    int j = threadIdx.x & 31;
    bool act = j < Ldim;
    float tr[Ldim];
#pragma unroll
    for (int i = 0; i < Ldim; i++) tr[i] = act ? trans[i * Ldim + j] : 0.f;
    float score = act ? start[j] + feats[(size_t)(b * Sdim) * Ldim + j] : -1e30f;
    for (int t = 1; t < Sdim; t++) {
        float e = act ? feats[(size_t)(b * Sdim + t) * Ldim + j] : 0.f;
        int m = amask[b * Sdim + t];
        float v[Ldim];
        float mx = -1e30f;
#pragma unroll
        for (int i = 0; i < Ldim; i++) {
            float si = __shfl_sync(0xffffffffu, score, i);
            v[i] = si + tr[i];
            mx = fmaxf(mx, v[i]);
        }
        float ssum = 0.f;
#pragma unroll
        for (int i = 0; i < Ldim; i++) ssum += expf(v[i] - mx);
        float nxt = mx + logf(ssum) + e;
        if (act && m > 0) score = nxt;
    }
    float tot = act ? score + endv[j] : -1e30f;
    float mx = tot;
#pragma unroll
    for (int o = 16; o; o >>= 1) mx = fmaxf(mx, __shfl_xor_sync(0xffffffffu, mx, o));
    float ex = act ? expf(tot - mx) : 0.f;
#pragma unroll
    for (int o = 16; o; o >>= 1) ex += __shfl_xor_sync(0xffffffffu, ex, o);
    if (j == 0) logZ[b] = mx + logf(ex);
}

// ---------------- Viterbi ----------------
__global__ void viterbi_kernel(const float* __restrict__ feats, const int* __restrict__ amask,
                               const float* __restrict__ start, const float* __restrict__ endv,
                               const float* __restrict__ trans, int* __restrict__ tags) {
    __shared__ unsigned char hist[(Sdim - 1) * Ldim];
    int b = blockIdx.x;
    int j = threadIdx.x;
    bool act = j < Ldim;
    float tr[Ldim];
#pragma unroll
    for (int i = 0; i < Ldim; i++) tr[i] = act ? trans[i * Ldim + j] : 0.f;
    float score = act ? start[j] + feats[(size_t)(b * Sdim) * Ldim + j] : -1e30f;
    for (int t = 1; t < Sdim; t++) {
        float e = act ? feats[(size_t)(b * Sdim + t) * Ldim + j] : 0.f;
        int m = amask[b * Sdim + t];
        float best = -1e30f;
        int barg = 0;
#pragma unroll
        for (int i = 0; i < Ldim; i++) {
            float si = __shfl_sync(0xffffffffu, score, i);
            float v = si + tr[i];
            if (v > best) { best = v; barg = i; }
        }
        if (act) {
            hist[(t - 1) * Ldim + j] = (unsigned char)barg;
            float nxt = best + e;
            if (m > 0) score = nxt;
        }
    }
    __syncwarp();
    float tot = act ? score + endv[j] : -1e30f;
    float bb = tot;
    int bj = act ? j : 0;
#pragma unroll
    for (int o = 16; o; o >>= 1) {
        float ov = __shfl_down_sync(0xffffffffu, bb, o);
        int oj = __shfl_down_sync(0xffffffffu, bj, o);
        if (ov > bb) { bb = ov; bj = oj; }
    }
    if (j == 0) {
        int tag = bj;
        tags[b * Sdim + Sdim - 1] = tag;
        for (int t = Sdim - 2; t >= 0; t--) {
            tag = hist[t * Ldim + tag];
            tags[b * Sdim + t] = tag;
        }
    }
}

// ---------------- finalize ----------------
__global__ void finalize_kernel(const float* __restrict__ logZ, const float* __restrict__ num,
                                const int* __restrict__ tags, float* __restrict__ out,
                                int out_size) {
    int i = blockIdx.x * blockDim.x + threadIdx.x;
    if (i >= out_size) return;
    if (i == 0) {
        float s = 0.f;
        for (int b = 0; b < Bdim; b++) s += logZ[b] - num[b];
        out[0] = s * (1.f / Bdim);
    } else if (i - 1 < Bdim * Sdim) {
        out[i] = (float)tags[i - 1];
    } else {
        out[i] = 0.f;
    }
}

// ---------------- host launch ----------------
extern "C" void kernel_launch(void* const* d_in, const int* in_sizes, int n_in,
                              void* d_out, int out_size) {
    const float* word_emb = (const float*)d_in[0];
    const float* pos_emb  = (const float*)d_in[1];
    const float* type_emb = (const float*)d_in[2];
    const float* eln_s    = (const float*)d_in[3];
    const float* eln_b    = (const float*)d_in[4];
    const float* Wq = (const float*)d_in[5];
    const float* bq = (const float*)d_in[6];
    const float* Wk = (const float*)d_in[7];
    const float* bk = (const float*)d_in[8];
    const float* Wv = (const float*)d_in[9];
    const float* bv = (const float*)d_in[10];
    const float* Wo = (const float*)d_in[11];
    const float* bo = (const float*)d_in[12];
    const float* ln1s = (const float*)d_in[13];
    const float* ln1b = (const float*)d_in[14];
    const float* W1 = (const float*)d_in[15];
    const float* b1 = (const float*)d_in[16];
    const float* W2 = (const float*)d_in[17];
    const float* b2 = (const float*)d_in[18];
    const float* ln2s = (const float*)d_in[19];
    const float* ln2b = (const float*)d_in[20];
    const float* clfW = (const float*)d_in[21];
    const float* clfb = (const float*)d_in[22];
    const float* crf_start = (const float*)d_in[23];
    const float* crf_end   = (const float*)d_in[24];
    const float* crf_trans = (const float*)d_in[25];
    const int* input_ids   = (const int*)d_in[26];
    const int* token_type  = (const int*)d_in[27];
    const int* attn_mask   = (const int*)d_in[28];
    const int* labels      = (const int*)d_in[29];

    float *h, *q, *k, *v, *t, *feats, *logZ, *num;
    int* tags;
    __nv_bfloat16 *hext, *ctxext, *ffext;
    unsigned int *Wqp, *Wkp, *Wvp, *Wop, *W1p, *W2p;
    cudaGetSymbolAddress((void**)&h, g_h);
    cudaGetSymbolAddress((void**)&q, g_q);
    cudaGetSymbolAddress((void**)&k, g_k);
    cudaGetSymbolAddress((void**)&v, g_v);
    cudaGetSymbolAddress((void**)&t, g_t);
    cudaGetSymbolAddress((void**)&feats, g_feats);
    cudaGetSymbolAddress((void**)&logZ, g_logZ);
    cudaGetSymbolAddress((void**)&num, g_num);
    cudaGetSymbolAddress((void**)&tags, g_tags);
    cudaGetSymbolAddress((void**)&hext, g_hext);
    cudaGetSymbolAddress((void**)&ctxext, g_ctxext);
    cudaGetSymbolAddress((void**)&ffext, g_ffext);
    cudaGetSymbolAddress((void**)&Wqp, g_Wqp);
    cudaGetSymbolAddress((void**)&Wkp, g_Wkp);
    cudaGetSymbolAddress((void**)&Wvp, g_Wvp);
    cudaGetSymbolAddress((void**)&Wop, g_Wop);
    cudaGetSymbolAddress((void**)&W1p, g_W1p);
    cudaGetSymbolAddress((void**)&W2p, g_W2p);

    cudaFuncSetAttribute(attn_kernel, cudaFuncAttributeMaxDynamicSharedMemorySize, ATTN_SMEM);
    cudaFuncSetAttribute(gemm_kh, cudaFuncAttributeMaxDynamicSharedMemorySize, GEMM_SMEM_H);
    cudaFuncSetAttribute(gemm_k1w, cudaFuncAttributeMaxDynamicSharedMemorySize, GEMM_SMEM_W);
    cudaFuncSetAttribute(gemm_k3w, cudaFuncAttributeMaxDynamicSharedMemorySize, GEMM_SMEM_W);

    convP_kernel<<<dim3(Hdim / 256, PKH, NLnum), 256>>>(Wq, Wqp, Hdim, Hdim);
    convP_kernel<<<dim3(Hdim / 256, PKH, NLnum), 256>>>(Wk, Wkp, Hdim, Hdim);
    convP_kernel<<<dim3(Hdim / 256, PKH, NLnum), 256>>>(Wv, Wvp, Hdim, Hdim);
    convP_kernel<<<dim3(Hdim / 256, PKH, NLnum), 256>>>(Wo, Wop, Hdim, Hdim);
    convP_kernel<<<dim3(FFdim / 256, PKH, NLnum), 256>>>(W1, W1p, Hdim, FFdim);
    convP_kernel<<<dim3(Hdim / 256, PKF, NLnum), 256>>>(W2, W2p, FFdim, Hdim);
    embed_ln_kernel<<<Mtot, 256>>>(word_emb, pos_emb, type_emb, eln_s, eln_b,
                                   input_ids, token_type, h, hext);

    dim3 gQKV(Hdim / 256, Mtot / 128, 3);
    dim3 gFF1(FFdim / 256, Mtot / 128);
    dim3 gHalf(Hdim / 128, Mtot / 64);       // 6 x 64 = 384 CTAs for O/FF2
    dim3 gAttn(Sdim / 64, NHnum, Bdim);
    const size_t woff = (size_t)PKH * Hdim;
    const size_t w1off = (size_t)PKH * FFdim;
    const size_t w2off = (size_t)PKF * Hdim;

    for (int l = 0; l < NLnum; l++) {
        gemm_k3w<<<gQKV, 256, GEMM_SMEM_W>>>(hext, Wqp + l * woff, Wkp + l * woff,
                                             Wvp + l * woff, bq + l * Hdim, bk + l * Hdim,
                                             bv + l * Hdim, q, k, v, KE_H);
        attn_kernel<<<gAttn, 256, ATTN_SMEM>>>(q, k, v, attn_mask, ctxext);
        gemm_kh<<<gHalf, 256, GEMM_SMEM_H>>>(ctxext, Wop + l * woff, bo + l * Hdim, h, t,
                                             Hdim, KE_H);
        ln_kernel<<<Mtot, 256>>>(t, ln1s + l * Hdim, ln1b + l * Hdim, h, hext);
        gemm_k1w<<<gFF1, 256, GEMM_SMEM_W>>>(hext, W1p + l * w1off, b1 + l * FFdim, nullptr,
                                             ffext, FFdim, KE_H, 1, 1);
        gemm_kh<<<gHalf, 256, GEMM_SMEM_H>>>(ffext, W2p + l * w2off, b2 + l * Hdim, h, t,
                                             Hdim, KE_FF);
        ln_kernel<<<Mtot, 256>>>(t, ln2s + l * Hdim, ln2b + l * Hdim, h, hext);
    }

    clf_kernel<<<Mtot, 256>>>(h, clfW, clfb, feats);
    crf_num_kernel<<<Bdim, 256>>>(feats, attn_mask, labels, crf_start, crf_end, crf_trans, num);
    crf_fwd_kernel<<<1, 256>>>(feats, attn_mask, crf_start, crf_end, crf_trans, logZ);
    viterbi_kernel<<<Bdim, 32>>>(feats, attn_mask, crf_start, crf_end, crf_trans, tags);

    int nfin = (out_size + 255) / 256;
    if (nfin < 1) nfin = 1;
    finalize_kernel<<<nfin, 256>>>(logZ, num, tags, (float*)d_out, out_size);
}

// round 14
// speedup vs baseline: 1.2027x; 1.0002x over previous
#include <cuda_runtime.h>
#include <cuda_bf16.h>
#include <math.h>

#define Mtot  4096
#define Hdim  768
#define FFdim 3072
#define NHnum 12
#define DHdim 64
#define Sdim  512
#define Bdim  8
#define Ldim  9
#define NLnum 12

#define KE_H  (3 * Hdim)    // 2304
#define KE_FF (3 * FFdim)   // 9216

// ---------------- scratch ----------------
__device__ float g_h[Mtot * Hdim];
__device__ float g_q[Mtot * Hdim];
__device__ float g_k[Mtot * Hdim];
__device__ float g_v[Mtot * Hdim];
__device__ float g_t[Mtot * Hdim];
__device__ float g_feats[Mtot * Ldim];
__device__ float g_logZ[Bdim];
__device__ float g_num[Bdim];
__device__ int   g_tags[Bdim * Sdim];

__device__ __align__(256) __nv_bfloat16 g_hext[Mtot * KE_H];
__device__ __align__(256) __nv_bfloat16 g_ctxext[Mtot * KE_H];
__device__ __align__(256) __nv_bfloat16 g_ffext[(size_t)Mtot * KE_FF];

#define PKH (3 * Hdim / 2)    // 1152
#define PKF (3 * FFdim / 2)   // 4608
__device__ __align__(256) unsigned int g_Wqp[NLnum * PKH * Hdim];
__device__ __align__(256) unsigned int g_Wkp[NLnum * PKH * Hdim];
__device__ __align__(256) unsigned int g_Wvp[NLnum * PKH * Hdim];
__device__ __align__(256) unsigned int g_Wop[NLnum * PKH * Hdim];
__device__ __align__(256) unsigned int g_W1p[(size_t)NLnum * PKH * FFdim];
__device__ __align__(256) unsigned int g_W2p[(size_t)NLnum * PKF * Hdim];

// ---------------- helpers ----------------
__device__ __forceinline__ float blk_sum256(float v, float* red) {
    int lane = threadIdx.x & 31, w = threadIdx.x >> 5;
#pragma unroll
    for (int o = 16; o; o >>= 1) v += __shfl_xor_sync(0xffffffffu, v, o);
    __syncthreads();
    if (lane == 0) red[w] = v;
    __syncthreads();
    float s = 0.f;
#pragma unroll
    for (int i = 0; i < 8; i++) s += red[i];
    return s;
}

__device__ __forceinline__ void split2(float x, __nv_bfloat16& hi, __nv_bfloat16& lo) {
    hi = __float2bfloat16(x);
    lo = __float2bfloat16(x - __bfloat162float(hi));
}

__device__ __forceinline__ void write_ext3(__nv_bfloat16* p, float x) {
    __nv_bfloat16 h, l;
    split2(x, h, l);
    p[0] = h; p[1] = l; p[2] = h;
}

__device__ __forceinline__ float fexp(float x) {
    float t = x * 1.4426950408889634f;
    t = fmaxf(t, -126.0f);
    float fl = floorf(t);
    float f = t - fl;
    float p = 1.525273e-5f;
    p = fmaf(p, f, 1.5403530e-4f);
    p = fmaf(p, f, 1.3333558e-3f);
    p = fmaf(p, f, 9.6181291e-3f);
    p = fmaf(p, f, 5.5504109e-2f);
    p = fmaf(p, f, 2.4022651e-1f);
    p = fmaf(p, f, 6.9314718e-1f);
    p = fmaf(p, f, 1.0f);
    return p * __int_as_float(((int)fl + 127) << 23);
}

// ---------------- weight conversion (no runtime division) ----------------
__global__ void convP_kernel(const float* __restrict__ W, unsigned int* __restrict__ out,
                             int K, int N) {
    int n = blockIdx.x * 256 + threadIdx.x;
    int i = blockIdx.y;
    int l = blockIdx.z;
    int PK = 3 * K / 2;
    int s0 = 2 * i, s1 = s0 + 1;
    int k0 = s0 / 3, r0 = s0 - 3 * k0;
    int k1 = s1 / 3, r1 = s1 - 3 * k1;
    const float* Wl = W + (size_t)l * K * N;
    float w0 = Wl[(size_t)k0 * N + n];
    float w1 = Wl[(size_t)k1 * N + n];
    __nv_bfloat16 h0, l0, h1, l1;
    split2(w0, h0, l0);
    split2(w1, h1, l1);
    __nv_bfloat16 v0 = (r0 == 2) ? l0 : h0;
    __nv_bfloat16 v1 = (r1 == 2) ? l1 : h1;
    __nv_bfloat162 pr(v0, v1);
    out[((size_t)l * PK + i) * N + n] = *reinterpret_cast<unsigned int*>(&pr);
}

// ---------------- embedding + LayerNorm ----------------
__global__ void embed_ln_kernel(const float* __restrict__ we, const float* __restrict__ pe,
                                const float* __restrict__ te, const float* __restrict__ gs,
                                const float* __restrict__ gb, const int* __restrict__ ids,
                                const int* __restrict__ tts, float* __restrict__ out,
                                __nv_bfloat16* __restrict__ ext) {
    __shared__ float red[8];
    int m = blockIdx.x;
    int s = m & (Sdim - 1);
    int id = ids[m], tt = tts[m];
    float vals[3];
    float lsum = 0.f;
#pragma unroll
    for (int u = 0; u < 3; u++) {
        int j = threadIdx.x + u * 256;
        float v = we[(size_t)id * Hdim + j] + pe[(size_t)s * Hdim + j] + te[(size_t)tt * Hdim + j];
        vals[u] = v;
        lsum += v;
    }
    float mean = blk_sum256(lsum, red) * (1.f / Hdim);
    float lsq = 0.f;
#pragma unroll
    for (int u = 0; u < 3; u++) { float d = vals[u] - mean; lsq += d * d; }
    float var = blk_sum256(lsq, red) * (1.f / Hdim);
    float inv = rsqrtf(var + 1e-12f);
#pragma unroll
    for (int u = 0; u < 3; u++) {
        int j = threadIdx.x + u * 256;
        float y = (vals[u] - mean) * inv * gs[j] + gb[j];
        out[(size_t)m * Hdim + j] = y;
        write_ext3(ext + (size_t)m * KE_H + 3 * j, y);
    }
}

// ---------------- LayerNorm ----------------
__global__ void ln_kernel(const float* __restrict__ x, const float* __restrict__ gs,
                          const float* __restrict__ gb, float* __restrict__ y,
                          __nv_bfloat16* __restrict__ ext) {
    __shared__ float red[8];
    int m = blockIdx.x;
    const float* xr = x + (size_t)m * Hdim;
    float vals[3];
    float lsum = 0.f;
#pragma unroll
    for (int u = 0; u < 3; u++) {
        vals[u] = xr[threadIdx.x + u * 256];
        lsum += vals[u];
    }
    float mean = blk_sum256(lsum, red) * (1.f / Hdim);
    float lsq = 0.f;
#pragma unroll
    for (int u = 0; u < 3; u++) { float d = vals[u] - mean; lsq += d * d; }
    float var = blk_sum256(lsq, red) * (1.f / Hdim);
    float inv = rsqrtf(var + 1e-12f);
#pragma unroll
    for (int u = 0; u < 3; u++) {
        int j = threadIdx.x + u * 256;
        float yy = (vals[u] - mean) * inv * gs[j] + gb[j];
        y[(size_t)m * Hdim + j] = yy;
        write_ext3(ext + (size_t)m * KE_H + 3 * j, yy);
    }
}

// ================= shared GEMM bits =================
__device__ __forceinline__ void cp16(unsigned int saddr, const void* gptr) {
    asm volatile("cp.async.cg.shared.global [%0], [%1], 16;\n" ::"r"(saddr), "l"(gptr));
}
__device__ __forceinline__ void cp_commit() { asm volatile("cp.async.commit_group;\n"); }
__device__ __forceinline__ void cp_wait2() { asm volatile("cp.async.wait_group 2;\n"); }

#define MMA16816(d, a, b)                                                      \
    asm volatile(                                                              \
        "mma.sync.aligned.m16n8k16.row.col.f32.bf16.bf16.f32 "                 \
        "{%0,%1,%2,%3}, {%4,%5,%6,%7}, {%8,%9}, {%0,%1,%2,%3};\n"              \
        : "+f"(d[0]), "+f"(d[1]), "+f"(d[2]), "+f"(d[3])                       \
        : "r"(a[0]), "r"(a[1]), "r"(a[2]), "r"(a[3]), "r"(b[0]), "r"(b[1]))

#define BKE 48
#define BKP 24
#define AS_STRIDE 28
#define BS_STRIDE 136

// ================= 64x128 GEMM (O proj, FF2) — wave-balanced =================
#define STAGE_WORDS_H (64 * AS_STRIDE + BKP * BS_STRIDE)   // 1792+3264 = 5056
#define GEMM_SMEM_H (4 * STAGE_WORDS_H * 4)                // 80896 B

__device__ __forceinline__ void gemm_core_h(const __nv_bfloat16* __restrict__ A,
                                            const unsigned int* __restrict__ B,
                                            const float* __restrict__ bias,
                                            const float* __restrict__ res,
                                            float* __restrict__ Cf,
                                            int N, int KE, unsigned int* smem) {
    const int tid = threadIdx.x;
    const int lane = tid & 31;
    const int wid = tid >> 5;
    const int warp_m = wid >> 2;   // 0..1 (32 rows each)
    const int warp_n = wid & 3;    // 0..3 (32 cols each)
    const int m0 = blockIdx.y * 64;
    const int n0 = blockIdx.x * 128;
    const int T = KE / BKE;
    const int g = lane >> 2, t4 = lane & 3;

    float acc[2][4][4];
#pragma unroll
    for (int i = 0; i < 2; i++)
#pragma unroll
        for (int j = 0; j < 4; j++)
#pragma unroll
            for (int r = 0; r < 4; r++) acc[i][j][r] = 0.f;

    const unsigned int sbase = (unsigned int)__cvta_generic_to_shared(smem);

    auto load_stage = [&](int tile, int stg) {
        unsigned int abase = sbase + (unsigned int)(stg * STAGE_WORDS_H) * 4u;
        unsigned int bbase = abase + 64u * AS_STRIDE * 4u;
        const __nv_bfloat16* Ag = A + (size_t)m0 * KE + tile * BKE;
        // 64 rows x 6 chunks = 384 cp16
        {
            int i = tid;
            int r = i / 6, c = i % 6;
            cp16(abase + (unsigned int)(r * AS_STRIDE + c * 4) * 4u,
                 Ag + (size_t)r * KE + c * 8);
            i = tid + 256;
            if (i < 384) {
                r = i / 6; c = i % 6;
                cp16(abase + (unsigned int)(r * AS_STRIDE + c * 4) * 4u,
                     Ag + (size_t)r * KE + c * 8);
            }
        }
        const unsigned int* Bg = B + (size_t)(tile * BKP) * N + n0;
#pragma unroll
        for (int l = 0; l < 3; l++) {
            int i = tid + l * 256;
            int r = i >> 5, c = i & 31;
            cp16(bbase + (unsigned int)(r * BS_STRIDE + c * 4) * 4u,
                 Bg + (size_t)r * N + c * 4);
        }
    };

    load_stage(0, 0); cp_commit();
    load_stage(1, 1); cp_commit();
    load_stage(2, 2); cp_commit();

    for (int t = 0; t < T; t++) {
        cp_wait2();
        __syncthreads();
        if (t + 3 < T) load_stage(t + 3, (t + 3) & 3);
        cp_commit();

        const unsigned int* As = smem + (size_t)(t & 3) * STAGE_WORDS_H;
        const unsigned int* Bs = As + 64 * AS_STRIDE;
#pragma unroll
        for (int s = 0; s < 3; s++) {
            unsigned int a[2][4], b[4][2];
#pragma unroll
            for (int mi = 0; mi < 2; mi++) {
                int r = warp_m * 32 + mi * 16 + g;
                int cp = s * 8 + t4;
                a[mi][0] = As[r * AS_STRIDE + cp];
                a[mi][1] = As[(r + 8) * AS_STRIDE + cp];
                a[mi][2] = As[r * AS_STRIDE + cp + 4];
                a[mi][3] = As[(r + 8) * AS_STRIDE + cp + 4];
            }
#pragma unroll
            for (int nj = 0; nj < 4; nj++) {
                int n = warp_n * 32 + nj * 8 + g;
                b[nj][0] = Bs[(s * 8 + t4) * BS_STRIDE + n];
                b[nj][1] = Bs[(s * 8 + t4 + 4) * BS_STRIDE + n];
            }
#pragma unroll
            for (int mi = 0; mi < 2; mi++)
#pragma unroll
                for (int nj = 0; nj < 4; nj++) MMA16816(acc[mi][nj], a[mi], b[nj]);
        }
        __syncthreads();
    }

#pragma unroll
    for (int mi = 0; mi < 2; mi++) {
        int row0 = m0 + warp_m * 32 + mi * 16 + g;
#pragma unroll
        for (int nj = 0; nj < 4; nj++) {
            int col = n0 + warp_n * 32 + nj * 8 + t4 * 2;
            float b0 = bias[col], b1 = bias[col + 1];
#pragma unroll
            for (int half = 0; half < 2; half++) {
                int row = row0 + half * 8;
                float2 rr = *(const float2*)(res + (size_t)row * N + col);
                float v0 = acc[mi][nj][half * 2 + 0] + b0 + rr.x;
                float v1 = acc[mi][nj][half * 2 + 1] + b1 + rr.y;
                *(float2*)(Cf + (size_t)row * N + col) = make_float2(v0, v1);
            }
        }
    }
}

__global__ void __launch_bounds__(256, 2) gemm_kh(const __nv_bfloat16* __restrict__ A,
                                                  const unsigned int* __restrict__ B,
                                                  const float* __restrict__ bias,
                                                  const float* __restrict__ res,
                                                  float* __restrict__ Cf, int N, int KE) {
    extern __shared__ unsigned int smem[];
    gemm_core_h(A, B, bias, res, Cf, N, KE, smem);
}

// ================= 128x256 GEMM (QKV, FF1) =================
#define BSW_STRIDE 264
#define STAGE_WORDS_W (128 * AS_STRIDE + BKP * BSW_STRIDE)  // 9920
#define GEMM_SMEM_W (4 * STAGE_WORDS_W * 4)                 // 158720 B

__device__ __forceinline__ void gemm_core_w(const __nv_bfloat16* __restrict__ A,
                                            const unsigned int* __restrict__ B,
                                            const float* __restrict__ bias,
                                            float* __restrict__ Cf,
                                            __nv_bfloat16* __restrict__ Ce,
                                            int N, int KE, int act, int outp,
                                            unsigned int* smem) {
    const int tid = threadIdx.x;
    const int lane = tid & 31;
    const int wid = tid >> 5;
    const int warp_m = wid >> 2;
    const int warp_n = wid & 3;
    const int m0 = blockIdx.y * 128;
    const int n0 = blockIdx.x * 256;
    const int T = KE / BKE;
    const int g = lane >> 2, t4 = lane & 3;

    float acc[4][8][4];
#pragma unroll
    for (int i = 0; i < 4; i++)
#pragma unroll
        for (int j = 0; j < 8; j++)
#pragma unroll
            for (int r = 0; r < 4; r++) acc[i][j][r] = 0.f;

    const unsigned int sbase = (unsigned int)__cvta_generic_to_shared(smem);

    auto load_stage = [&](int tile, int stg) {
        unsigned int abase = sbase + (unsigned int)(stg * STAGE_WORDS_W) * 4u;
        unsigned int bbase = abase + 128u * AS_STRIDE * 4u;
        const __nv_bfloat16* Ag = A + (size_t)m0 * KE + tile * BKE;
#pragma unroll
        for (int l = 0; l < 3; l++) {
            int i = tid + l * 256;
            int r = i / 6, c = i % 6;
            cp16(abase + (unsigned int)(r * AS_STRIDE + c * 4) * 4u,
                 Ag + (size_t)r * KE + c * 8);
        }
        const unsigned int* Bg = B + (size_t)(tile * BKP) * N + n0;
#pragma unroll
        for (int l = 0; l < 6; l++) {
            int i = tid + l * 256;
            int r = i >> 6, c = i & 63;
            cp16(bbase + (unsigned int)(r * BSW_STRIDE + c * 4) * 4u,
                 Bg + (size_t)r * N + c * 4);
        }
    };

    load_stage(0, 0); cp_commit();
    load_stage(1, 1); cp_commit();
    load_stage(2, 2); cp_commit();

    for (int t = 0; t < T; t++) {
        cp_wait2();
        __syncthreads();
        if (t + 3 < T) load_stage(t + 3, (t + 3) & 3);
        cp_commit();

        const unsigned int* As = smem + (size_t)(t & 3) * STAGE_WORDS_W;
        const unsigned int* Bs = As + 128 * AS_STRIDE;
#pragma unroll
        for (int s = 0; s < 3; s++) {
            unsigned int a[4][4];
#pragma unroll
            for (int mi = 0; mi < 4; mi++) {
                int r = warp_m * 64 + mi * 16 + g;
                int cp = s * 8 + t4;
                a[mi][0] = As[r * AS_STRIDE + cp];
                a[mi][1] = As[(r + 8) * AS_STRIDE + cp];
                a[mi][2] = As[r * AS_STRIDE + cp + 4];
                a[mi][3] = As[(r + 8) * AS_STRIDE + cp + 4];
            }
#pragma unroll
            for (int nj = 0; nj < 8; nj++) {
                unsigned int b[2];
                int n = warp_n * 64 + nj * 8 + g;
                b[0] = Bs[(s * 8 + t4) * BSW_STRIDE + n];
                b[1] = Bs[(s * 8 + t4 + 4) * BSW_STRIDE + n];
#pragma unroll
                for (int mi = 0; mi < 4; mi++) MMA16816(acc[mi][nj], a[mi], b);
            }
        }
        __syncthreads();
    }

#pragma unroll
    for (int mi = 0; mi < 4; mi++) {
        int row0 = m0 + warp_m * 64 + mi * 16 + g;
#pragma unroll
        for (int nj = 0; nj < 8; nj++) {
            int col = n0 + warp_n * 64 + nj * 8 + t4 * 2;
            float b0 = bias[col], b1 = bias[col + 1];
#pragma unroll
            for (int half = 0; half < 2; half++) {
                int row = row0 + half * 8;
                float v0 = acc[mi][nj][half * 2 + 0] + b0;
                float v1 = acc[mi][nj][half * 2 + 1] + b1;
                if (act) {
                    v0 = 0.5f * v0 * (1.f + erff(v0 * 0.70710678118654752440f));
                    v1 = 0.5f * v1 * (1.f + erff(v1 * 0.70710678118654752440f));
                }
                if (outp == 0) {
                    *(float2*)(Cf + (size_t)row * N + col) = make_float2(v0, v1);
                } else {
                    __nv_bfloat16* p = Ce + (size_t)row * (3 * N) + 3 * col;
                    write_ext3(p, v0);
                    write_ext3(p + 3, v1);
                }
            }
        }
    }
}

__global__ void __launch_bounds__(256, 1) gemm_k1w(const __nv_bfloat16* __restrict__ A,
                                                   const unsigned int* __restrict__ B,
                                                   const float* __restrict__ bias,
                                                   float* __restrict__ Cf,
                                                   __nv_bfloat16* __restrict__ Ce,
                                                   int N, int KE, int act, int outp) {
    extern __shared__ unsigned int smem[];
    gemm_core_w(A, B, bias, Cf, Ce, N, KE, act, outp, smem);
}

__global__ void __launch_bounds__(256, 1) gemm_k3w(const __nv_bfloat16* __restrict__ A,
                                                   const unsigned int* __restrict__ B0,
                                                   const unsigned int* __restrict__ B1,
                                                   const unsigned int* __restrict__ B2,
                                                   const float* __restrict__ bias0,
                                                   const float* __restrict__ bias1,
                                                   const float* __restrict__ bias2,
                                                   float* __restrict__ C0, float* __restrict__ C1,
                                                   float* __restrict__ C2, int KE) {
    extern __shared__ unsigned int smem[];
    int z = blockIdx.z;
    const unsigned int* B = (z == 0) ? B0 : (z == 1) ? B1 : B2;
    const float* bias = (z == 0) ? bias0 : (z == 1) ? bias1 : bias2;
    float* Cf = (z == 0) ? C0 : (z == 1) ? C1 : C2;
    gemm_core_w(A, B, bias, Cf, nullptr, Hdim, KE, 0, 0, smem);
}

// ======== tensor-core attention (split-bf16 3-slot) ========
#define A_OFF_MB 0
#define A_OFF_Q  512
#define A_OFF_K  (512 + 6400)
#define A_OFF_V  (512 + 6400 + 6912)
#define A_OFF_P  (512 + 6400 + 13824)
#define A_OFF_PM (512 + 6400 + 13824 + 6400)
#define A_OFF_RM (A_OFF_PM + 128)
#define A_OFF_PS (A_OFF_RM + 64)
#define A_OFF_RS (A_OFF_PS + 128)
#define ATTN_SMEM ((A_OFF_RS + 64) * 4)

__global__ void __launch_bounds__(256) attn_kernel(const float* __restrict__ Q,
                                                   const float* __restrict__ Kp,
                                                   const float* __restrict__ Vp,
                                                   const int* __restrict__ amask,
                                                   __nv_bfloat16* __restrict__ Oext) {
    extern __shared__ unsigned int sm[];
    float* mbias = (float*)(sm + A_OFF_MB);
    unsigned int* qx = sm + A_OFF_Q;
    unsigned int* kx = sm + A_OFF_K;
    unsigned int* vx = sm + A_OFF_V;
    unsigned int* px = sm + A_OFF_P;
    float* partmax = (float*)(sm + A_OFF_PM);
    float* rowmax = (float*)(sm + A_OFF_RM);
    float* partsum = (float*)(sm + A_OFF_PS);
    float* rowsum = (float*)(sm + A_OFF_RS);
    unsigned short* qx16 = (unsigned short*)qx;
    unsigned short* kx16 = (unsigned short*)kx;
    unsigned short* vx16 = (unsigned short*)vx;
    unsigned short* px16 = (unsigned short*)px;

    const int tid = threadIdx.x, lane = tid & 31, w = tid >> 5;
    const int wm = w >> 1, wn = w & 1, g = lane >> 2, t4 = lane & 3;
    const int q0 = blockIdx.x * 64, h = blockIdx.y, b = blockIdx.z;
    const size_t base = (size_t)b * Sdim * Hdim + h * 64;
    const int r0 = wm * 16 + g, r1 = r0 + 8;

    for (int i = tid; i < Sdim; i += 256)
        mbias[i] = (1.f - (float)amask[b * Sdim + i]) * -10000.f;

    for (int i = tid; i < 4096; i += 256) {
        int r = i >> 6, d = i & 63;
        float xv = Q[base + (size_t)(q0 + r) * Hdim + d];
        __nv_bfloat16 hh, ll;
        split2(xv, hh, ll);
        unsigned short uh = *(unsigned short*)&hh, ul = *(unsigned short*)&ll;
        int o = r * 200 + 3 * d;
        qx16[o] = uh; qx16[o + 1] = ul; qx16[o + 2] = uh;
    }
    __syncthreads();

    float sacc[32][4];
#pragma unroll
    for (int i = 0; i < 32; i++)
#pragma unroll
        for (int j = 0; j < 4; j++) sacc[i][j] = 0.f;

#pragma unroll
    for (int kb = 0; kb < 8; kb++) {
        for (int i = tid; i < 4096; i += 256) {
            int kk = i >> 6, d = i & 63;
            float xv = Kp[base + (size_t)(kb * 64 + kk) * Hdim + d];
            __nv_bfloat16 hh, ll;
            split2(xv, hh, ll);
            unsigned short uh = *(unsigned short*)&hh, ul = *(unsigned short*)&ll;
            int e = 3 * d;
            kx16[(e >> 1) * 144 + kk * 2 + (e & 1)] = uh;
            kx16[((e + 1) >> 1) * 144 + kk * 2 + ((e + 1) & 1)] = uh;
            kx16[((e + 2) >> 1) * 144 + kk * 2 + ((e + 2) & 1)] = ul;
        }
        __syncthreads();
#pragma unroll
        for (int s = 0; s < 12; s++) {
            unsigned int a[4];
            int ar = r0 * 100 + s * 8 + t4;
            a[0] = qx[ar]; a[1] = qx[ar + 800]; a[2] = qx[ar + 4]; a[3] = qx[ar + 804];
#pragma unroll
            for (int j = 0; j < 4; j++) {
                unsigned int bb[2];
                int br = (s * 8 + t4) * 72 + wn * 32 + j * 8 + g;
                bb[0] = kx[br]; bb[1] = kx[br + 288];
                MMA16816(sacc[kb * 4 + j], a, bb);
            }
        }
        __syncthreads();
    }

    float rm0 = -1e30f, rm1 = -1e30f;
#pragma unroll
    for (int kb = 0; kb < 8; kb++)
#pragma unroll
        for (int j = 0; j < 4; j++) {
            int c = kb * 64 + wn * 32 + j * 8 + 2 * t4;
            float m0 = mbias[c], m1 = mbias[c + 1];
            float* A = sacc[kb * 4 + j];
            A[0] = A[0] * 0.125f + m0;
            A[1] = A[1] * 0.125f + m1;
            A[2] = A[2] * 0.125f + m0;
            A[3] = A[3] * 0.125f + m1;
            rm0 = fmaxf(rm0, fmaxf(A[0], A[1]));
            rm1 = fmaxf(rm1, fmaxf(A[2], A[3]));
        }
    rm0 = fmaxf(rm0, __shfl_xor_sync(0xffffffffu, rm0, 1));
    rm0 = fmaxf(rm0, __shfl_xor_sync(0xffffffffu, rm0, 2));
    rm1 = fmaxf(rm1, __shfl_xor_sync(0xffffffffu, rm1, 1));
    rm1 = fmaxf(rm1, __shfl_xor_sync(0xffffffffu, rm1, 2));
    if (t4 == 0) {
        partmax[r0 * 2 + wn] = rm0;
        partmax[r1 * 2 + wn] = rm1;
    }
    __syncthreads();
    if (tid < 64) rowmax[tid] = fmaxf(partmax[tid * 2], partmax[tid * 2 + 1]);
    __syncthreads();
    const float mx0 = rowmax[r0], mx1 = rowmax[r1];

    float oacc[4][4];
#pragma unroll
    for (int j = 0; j < 4; j++)
#pragma unroll
        for (int r = 0; r < 4; r++) oacc[j][r] = 0.f;
    float sum0 = 0.f, sum1 = 0.f;

#pragma unroll
    for (int kb = 0; kb < 8; kb++) {
        for (int i = tid; i < 4096; i += 256) {
            int kk = i >> 6, d = i & 63;
            float xv = Vp[base + (size_t)(kb * 64 + kk) * Hdim + d];
            __nv_bfloat16 hh, ll;
            split2(xv, hh, ll);
            unsigned short uh = *(unsigned short*)&hh, ul = *(unsigned short*)&ll;
            int e = 3 * kk;
            vx16[(e >> 1) * 144 + d * 2 + (e & 1)] = uh;
            vx16[((e + 1) >> 1) * 144 + d * 2 + ((e + 1) & 1)] = uh;
            vx16[((e + 2) >> 1) * 144 + d * 2 + ((e + 2) & 1)] = ul;
        }
#pragma unroll
        for (int j = 0; j < 4; j++) {
            float* A = sacc[kb * 4 + j];
#pragma unroll
            for (int c01 = 0; c01 < 2; c01++) {
                int lc = wn * 32 + j * 8 + 2 * t4 + c01;
                float p0 = fexp(A[c01] - mx0);
                float p1 = fexp(A[2 + c01] - mx1);
                sum0 += p0;
                sum1 += p1;
                __nv_bfloat16 hh, ll;
                split2(p0, hh, ll);
                int o0 = r0 * 200 + 3 * lc;
                px16[o0] = *(unsigned short*)&hh;
                px16[o0 + 1] = *(unsigned short*)&ll;
                px16[o0 + 2] = *(unsigned short*)&hh;
                split2(p1, hh, ll);
                int o1 = r1 * 200 + 3 * lc;
                px16[o1] = *(unsigned short*)&hh;
                px16[o1 + 1] = *(unsigned short*)&ll;
                px16[o1 + 2] = *(unsigned short*)&hh;
            }
        }
        __syncthreads();
#pragma unroll
        for (int s = 0; s < 12; s++) {
            unsigned int a[4];
            int ar = r0 * 100 + s * 8 + t4;
            a[0] = px[ar]; a[1] = px[ar + 800]; a[2] = px[ar + 4]; a[3] = px[ar + 804];
#pragma unroll
            for (int j2 = 0; j2 < 4; j2++) {
                unsigned int bb[2];
                int br = (s * 8 + t4) * 72 + wn * 32 + j2 * 8 + g;
                bb[0] = vx[br]; bb[1] = vx[br + 288];
                MMA16816(oacc[j2], a, bb);
            }
        }
        __syncthreads();
    }

    sum0 += __shfl_xor_sync(0xffffffffu, sum0, 1);
    sum0 += __shfl_xor_sync(0xffffffffu, sum0, 2);
    sum1 += __shfl_xor_sync(0xffffffffu, sum1, 1);
    sum1 += __shfl_xor_sync(0xffffffffu, sum1, 2);
    if (t4 == 0) {
        partsum[r0 * 2 + wn] = sum0;
        partsum[r1 * 2 + wn] = sum1;
    }
    __syncthreads();
    if (tid < 64) rowsum[tid] = partsum[tid * 2] + partsum[tid * 2 + 1];
    __syncthreads();
    const float inv0 = 1.f / rowsum[r0];
    const float inv1 = 1.f / rowsum[r1];

#pragma unroll
    for (int j2 = 0; j2 < 4; j2++) {
        int dcol = wn * 32 + j2 * 8 + 2 * t4;
        int mrow0 = b * Sdim + q0 + r0;
        int mrow1 = b * Sdim + q0 + r1;
        __nv_bfloat16* p0 = Oext + (size_t)mrow0 * KE_H + 3 * (h * 64 + dcol);
        write_ext3(p0, oacc[j2][0] * inv0);
        write_ext3(p0 + 3, oacc[j2][1] * inv0);
        __nv_bfloat16* p1 = Oext + (size_t)mrow1 * KE_H + 3 * (h * 64 + dcol);
        write_ext3(p1, oacc[j2][2] * inv1);
        write_ext3(p1 + 3, oacc[j2][3] * inv1);
    }
}

// ---------------- classifier ----------------
__global__ void clf_kernel(const float* __restrict__ X, const float* __restrict__ W,
                           const float* __restrict__ bias, float* __restrict__ F) {
    __shared__ float red[8][Ldim];
    int m = blockIdx.x;
    int tid = threadIdx.x;
    float acc[Ldim];
#pragma unroll
    for (int j = 0; j < Ldim; j++) acc[j] = 0.f;
    for (int k = tid; k < Hdim; k += 256) {
        float x = X[(size_t)m * Hdim + k];
#pragma unroll
        for (int j = 0; j < Ldim; j++) acc[j] += x * W[k * Ldim + j];
    }
    int lane = tid & 31, w = tid >> 5;
#pragma unroll
    for (int j = 0; j < Ldim; j++)
#pragma unroll
        for (int o = 16; o; o >>= 1) acc[j] += __shfl_down_sync(0xffffffffu, acc[j], o);
    if (lane == 0)
#pragma unroll
        for (int j = 0; j < Ldim; j++) red[w][j] = acc[j];
    __syncthreads();
    if (tid < Ldim) {
        float s = bias[tid];
#pragma unroll
        for (int ww = 0; ww < 8; ww++) s += red[ww][tid];
        F[(size_t)m * Ldim + tid] = s;
    }
}

// ---------------- CRF numerator ----------------
__global__ void crf_num_kernel(const float* __restrict__ feats, const int* __restrict__ amask,
                               const int* __restrict__ labels, const float* __restrict__ start,
                               const float* __restrict__ endv, const float* __restrict__ trans,
                               float* __restrict__ num) {
    __shared__ float red[8];
    int b = blockIdx.x;
    int tid = threadIdx.x;
    float s = 0.f, msum = 0.f;
    for (int t = tid; t < Sdim; t += 256) {
        int tag = labels[b * Sdim + t];
        float em = feats[(size_t)(b * Sdim + t) * Ldim + tag];
        float m = (float)amask[b * Sdim + t];
        msum += m;
        if (t == 0) {
            s += start[tag] + em;
        } else {
            int pt = labels[b * Sdim + t - 1];
            s += (em + trans[pt * Ldim + tag]) * m;
        }
    }
    float stotal = blk_sum256(s, red);
    float mtotal = blk_sum256(msum, red);
    if (tid == 0) {
        int last = (int)(mtotal + 0.5f) - 1;
        num[b] = stotal + endv[labels[b * Sdim + last]];
    }
}

// ---------------- CRF forward ----------------
__global__ void crf_fwd_kernel(const float* __restrict__ feats, const int* __restrict__ amask,
                               const float* __restrict__ start, const float* __restrict__ endv,
                               const float* __restrict__ trans, float* __restrict__ logZ) {
    int b = threadIdx.x >> 5;
    int j = threadIdx.x & 31;
    bool act = j < Ldim;
    float tr[Ldim];
#pragma unroll
    for (int i = 0; i < Ldim; i++) tr[i] = act ? trans[i * Ldim + j] : 0.f;
    float score = act ? start[j] + feats[(size_t)(b * Sdim) * Ldim + j] : -1e30f;
    for (int t = 1; t < Sdim; t++) {
        float e = act ? feats[(size_t)(b * Sdim + t) * Ldim + j] : 0.f;
        int m = amask[b * Sdim + t];
        float v[Ldim];
        float mx = -1e30f;
#pragma unroll
        for (int i = 0; i < Ldim; i++) {
            float si = __shfl_sync(0xffffffffu, score, i);
            v[i] = si + tr[i];
            mx = fmaxf(mx, v[i]);
        }
        float ssum = 0.f;
#pragma unroll
        for (int i = 0; i < Ldim; i++) ssum += expf(v[i] - mx);
        float nxt = mx + logf(ssum) + e;
        if (act && m > 0) score = nxt;
    }
    float tot = act ? score + endv[j] : -1e30f;
    float mx = tot;
#pragma unroll
    for (int o = 16; o; o >>= 1) mx = fmaxf(mx, __shfl_xor_sync(0xffffffffu, mx, o));
    float ex = act ? expf(tot - mx) : 0.f;
#pragma unroll
    for (int o = 16; o; o >>= 1) ex += __shfl_xor_sync(0xffffffffu, ex, o);
    if (j == 0) logZ[b] = mx + logf(ex);
}

// ---------------- Viterbi ----------------
__global__ void viterbi_kernel(const float* __restrict__ feats, const int* __restrict__ amask,
                               const float* __restrict__ start, const float* __restrict__ endv,
                               const float* __restrict__ trans, int* __restrict__ tags) {
    __shared__ unsigned char hist[(Sdim - 1) * Ldim];
    int b = blockIdx.x;
    int j = threadIdx.x;
    bool act = j < Ldim;
    float tr[Ldim];
#pragma unroll
    for (int i = 0; i < Ldim; i++) tr[i] = act ? trans[i * Ldim + j] : 0.f;
    float score = act ? start[j] + feats[(size_t)(b * Sdim) * Ldim + j] : -1e30f;
    for (int t = 1; t < Sdim; t++) {
        float e = act ? feats[(size_t)(b * Sdim + t) * Ldim + j] : 0.f;
        int m = amask[b * Sdim + t];
        float best = -1e30f;
        int barg = 0;
#pragma unroll
        for (int i = 0; i < Ldim; i++) {
            float si = __shfl_sync(0xffffffffu, score, i);
            float v = si + tr[i];
            if (v > best) { best = v; barg = i; }
        }
        if (act) {
            hist[(t - 1) * Ldim + j] = (unsigned char)barg;
            float nxt = best + e;
            if (m > 0) score = nxt;
        }
    }
    __syncwarp();
    float tot = act ? score + endv[j] : -1e30f;
    float bb = tot;
    int bj = act ? j : 0;
#pragma unroll
    for (int o = 16; o; o >>= 1) {
        float ov = __shfl_down_sync(0xffffffffu, bb, o);
        int oj = __shfl_down_sync(0xffffffffu, bj, o);
        if (ov > bb) { bb = ov; bj = oj; }
    }
    if (j == 0) {
        int tag = bj;
        tags[b * Sdim + Sdim - 1] = tag;
        for (int t = Sdim - 2; t >= 0; t--) {
            tag = hist[t * Ldim + tag];
            tags[b * Sdim + t] = tag;
        }
    }
}

// ---------------- finalize ----------------
__global__ void finalize_kernel(const float* __restrict__ logZ, const float* __restrict__ num,
                                const int* __restrict__ tags, float* __restrict__ out,
                                int out_size) {
    int i = blockIdx.x * blockDim.x + threadIdx.x;
    if (i >= out_size) return;
    if (i == 0) {
        float s = 0.f;
        for (int b = 0; b < Bdim; b++) s += logZ[b] - num[b];
        out[0] = s * (1.f / Bdim);
    } else if (i - 1 < Bdim * Sdim) {
        out[i] = (float)tags[i - 1];
    } else {
        out[i] = 0.f;
    }
}

// ---------------- host launch ----------------
extern "C" void kernel_launch(void* const* d_in, const int* in_sizes, int n_in,
                              void* d_out, int out_size) {
    const float* word_emb = (const float*)d_in[0];
    const float* pos_emb  = (const float*)d_in[1];
    const float* type_emb = (const float*)d_in[2];
    const float* eln_s    = (const float*)d_in[3];
    const float* eln_b    = (const float*)d_in[4];
    const float* Wq = (const float*)d_in[5];
    const float* bq = (const float*)d_in[6];
    const float* Wk = (const float*)d_in[7];
    const float* bk = (const float*)d_in[8];
    const float* Wv = (const float*)d_in[9];
    const float* bv = (const float*)d_in[10];
    const float* Wo = (const float*)d_in[11];
    const float* bo = (const float*)d_in[12];
    const float* ln1s = (const float*)d_in[13];
    const float* ln1b = (const float*)d_in[14];
    const float* W1 = (const float*)d_in[15];
    const float* b1 = (const float*)d_in[16];
    const float* W2 = (const float*)d_in[17];
    const float* b2 = (const float*)d_in[18];
    const float* ln2s = (const float*)d_in[19];
    const float* ln2b = (const float*)d_in[20];
    const float* clfW = (const float*)d_in[21];
    const float* clfb = (const float*)d_in[22];
    const float* crf_start = (const float*)d_in[23];
    const float* crf_end   = (const float*)d_in[24];
    const float* crf_trans = (const float*)d_in[25];
    const int* input_ids   = (const int*)d_in[26];
    const int* token_type  = (const int*)d_in[27];
    const int* attn_mask   = (const int*)d_in[28];
    const int* labels      = (const int*)d_in[29];

    float *h, *q, *k, *v, *t, *feats, *logZ, *num;
    int* tags;
    __nv_bfloat16 *hext, *ctxext, *ffext;
    unsigned int *Wqp, *Wkp, *Wvp, *Wop, *W1p, *W2p;
    cudaGetSymbolAddress((void**)&h, g_h);
    cudaGetSymbolAddress((void**)&q, g_q);
    cudaGetSymbolAddress((void**)&k, g_k);
    cudaGetSymbolAddress((void**)&v, g_v);
    cudaGetSymbolAddress((void**)&t, g_t);
    cudaGetSymbolAddress((void**)&feats, g_feats);
    cudaGetSymbolAddress((void**)&logZ, g_logZ);
    cudaGetSymbolAddress((void**)&num, g_num);
    cudaGetSymbolAddress((void**)&tags, g_tags);
    cudaGetSymbolAddress((void**)&hext, g_hext);
    cudaGetSymbolAddress((void**)&ctxext, g_ctxext);
    cudaGetSymbolAddress((void**)&ffext, g_ffext);
    cudaGetSymbolAddress((void**)&Wqp, g_Wqp);
    cudaGetSymbolAddress((void**)&Wkp, g_Wkp);
    cudaGetSymbolAddress((void**)&Wvp, g_Wvp);
    cudaGetSymbolAddress((void**)&Wop, g_Wop);
    cudaGetSymbolAddress((void**)&W1p, g_W1p);
    cudaGetSymbolAddress((void**)&W2p, g_W2p);

    cudaFuncSetAttribute(attn_kernel, cudaFuncAttributeMaxDynamicSharedMemorySize, ATTN_SMEM);
    cudaFuncSetAttribute(gemm_kh, cudaFuncAttributeMaxDynamicSharedMemorySize, GEMM_SMEM_H);
    cudaFuncSetAttribute(gemm_k1w, cudaFuncAttributeMaxDynamicSharedMemorySize, GEMM_SMEM_W);
    cudaFuncSetAttribute(gemm_k3w, cudaFuncAttributeMaxDynamicSharedMemorySize, GEMM_SMEM_W);

    convP_kernel<<<dim3(Hdim / 256, PKH, NLnum), 256>>>(Wq, Wqp, Hdim, Hdim);
    convP_kernel<<<dim3(Hdim / 256, PKH, NLnum), 256>>>(Wk, Wkp, Hdim, Hdim);
    convP_kernel<<<dim3(Hdim / 256, PKH, NLnum), 256>>>(Wv, Wvp, Hdim, Hdim);
    convP_kernel<<<dim3(Hdim / 256, PKH, NLnum), 256>>>(Wo, Wop, Hdim, Hdim);
    convP_kernel<<<dim3(FFdim / 256, PKH, NLnum), 256>>>(W1, W1p, Hdim, FFdim);
    convP_kernel<<<dim3(Hdim / 256, PKF, NLnum), 256>>>(W2, W2p, FFdim, Hdim);
    embed_ln_kernel<<<Mtot, 256>>>(word_emb, pos_emb, type_emb, eln_s, eln_b,
                                   input_ids, token_type, h, hext);

    dim3 gQKV(Hdim / 256, Mtot / 128, 3);
    dim3 gFF1(FFdim / 256, Mtot / 128);
    dim3 gHalf(Hdim / 128, Mtot / 64);       // 6 x 64 = 384 CTAs for O/FF2
    dim3 gAttn(Sdim / 64, NHnum, Bdim);
    const size_t woff = (size_t)PKH * Hdim;
    const size_t w1off = (size_t)PKH * FFdim;
    const size_t w2off = (size_t)PKF * Hdim;

    for (int l = 0; l < NLnum; l++) {
        gemm_k3w<<<gQKV, 256, GEMM_SMEM_W>>>(hext, Wqp + l * woff, Wkp + l * woff,
                                             Wvp + l * woff, bq + l * Hdim, bk + l * Hdim,
                                             bv + l * Hdim, q, k, v, KE_H);
        attn_kernel<<<gAttn, 256, ATTN_SMEM>>>(q, k, v, attn_mask, ctxext);
        gemm_kh<<<gHalf, 256, GEMM_SMEM_H>>>(ctxext, Wop + l * woff, bo + l * Hdim, h, t,
                                             Hdim, KE_H);
        ln_kernel<<<Mtot, 256>>>(t, ln1s + l * Hdim, ln1b + l * Hdim, h, hext);
        gemm_k1w<<<gFF1, 256, GEMM_SMEM_W>>>(hext, W1p + l * w1off, b1 + l * FFdim, nullptr,
                                             ffext, FFdim, KE_H, 1, 1);
        gemm_kh<<<gHalf, 256, GEMM_SMEM_H>>>(ffext, W2p + l * w2off, b2 + l * Hdim, h, t,
                                             Hdim, KE_FF);
        ln_kernel<<<Mtot, 256>>>(t, ln2s + l * Hdim, ln2b + l * Hdim, h, hext);
    }

    clf_kernel<<<Mtot, 256>>>(h, clfW, clfb, feats);
    crf_num_kernel<<<Bdim, 256>>>(feats, attn_mask, labels, crf_start, crf_end, crf_trans, num);
    crf_fwd_kernel<<<1, 256>>>(feats, attn_mask, crf_start, crf_end, crf_trans, logZ);
    viterbi_kernel<<<Bdim, 32>>>(feats, attn_mask, crf_start, crf_end, crf_trans, tags);

    int nfin = (out_size + 255) / 256;
    if (nfin < 1) nfin = 1;
    finalize_kernel<<<nfin, 256>>>(logZ, num, tags, (float*)d_out, out_size);
}

// round 15
// speedup vs baseline: 1.2265x; 1.0198x over previous
#include <cuda_runtime.h>
#include <cuda_bf16.h>
#include <math.h>

#define Mtot  4096
#define Hdim  768
#define FFdim 3072
#define NHnum 12
#define DHdim 64
#define Sdim  512
#define Bdim  8
#define Ldim  9
#define NLnum 12

#define KE_H  (3 * Hdim)    // 2304
#define KE_FF (3 * FFdim)   // 9216

// ---------------- scratch ----------------
__device__ float g_h[Mtot * Hdim];
__device__ float g_q[Mtot * Hdim];
__device__ float g_k[Mtot * Hdim];
__device__ float g_v[Mtot * Hdim];
__device__ float g_t[Mtot * Hdim];
__device__ float g_feats[Mtot * Ldim];
__device__ float g_logZ[Bdim];
__device__ float g_num[Bdim];
__device__ int   g_tags[Bdim * Sdim];

__device__ __align__(256) __nv_bfloat16 g_hext[Mtot * KE_H];
__device__ __align__(256) __nv_bfloat16 g_ctxext[Mtot * KE_H];
__device__ __align__(256) __nv_bfloat16 g_ffext[(size_t)Mtot * KE_FF];

#define PKH (3 * Hdim / 2)    // 1152
#define PKF (3 * FFdim / 2)   // 4608
__device__ __align__(256) unsigned int g_Wqp[NLnum * PKH * Hdim];
__device__ __align__(256) unsigned int g_Wkp[NLnum * PKH * Hdim];
__device__ __align__(256) unsigned int g_Wvp[NLnum * PKH * Hdim];
__device__ __align__(256) unsigned int g_Wop[NLnum * PKH * Hdim];
__device__ __align__(256) unsigned int g_W1p[(size_t)NLnum * PKH * FFdim];
__device__ __align__(256) unsigned int g_W2p[(size_t)NLnum * PKF * Hdim];

// ---------------- helpers ----------------
__device__ __forceinline__ float blk_sum256(float v, float* red) {
    int lane = threadIdx.x & 31, w = threadIdx.x >> 5;
#pragma unroll
    for (int o = 16; o; o >>= 1) v += __shfl_xor_sync(0xffffffffu, v, o);
    __syncthreads();
    if (lane == 0) red[w] = v;
    __syncthreads();
    float s = 0.f;
#pragma unroll
    for (int i = 0; i < 8; i++) s += red[i];
    return s;
}

__device__ __forceinline__ void split2(float x, __nv_bfloat16& hi, __nv_bfloat16& lo) {
    hi = __float2bfloat16(x);
    lo = __float2bfloat16(x - __bfloat162float(hi));
}

__device__ __forceinline__ void write_ext3(__nv_bfloat16* p, float x) {
    __nv_bfloat16 h, l;
    split2(x, h, l);
    p[0] = h; p[1] = l; p[2] = h;
}

__device__ __forceinline__ float fexp(float x) {
    float t = x * 1.4426950408889634f;
    t = fmaxf(t, -126.0f);
    float fl = floorf(t);
    float f = t - fl;
    float p = 1.525273e-5f;
    p = fmaf(p, f, 1.5403530e-4f);
    p = fmaf(p, f, 1.3333558e-3f);
    p = fmaf(p, f, 9.6181291e-3f);
    p = fmaf(p, f, 5.5504109e-2f);
    p = fmaf(p, f, 2.4022651e-1f);
    p = fmaf(p, f, 6.9314718e-1f);
    p = fmaf(p, f, 1.0f);
    return p * __int_as_float(((int)fl + 127) << 23);
}

// ---------------- weight conversion (no runtime division) ----------------
__global__ void convP_kernel(const float* __restrict__ W, unsigned int* __restrict__ out,
                             int K, int N) {
    int n = blockIdx.x * 256 + threadIdx.x;
    int i = blockIdx.y;
    int l = blockIdx.z;
    int PK = 3 * K / 2;
    int s0 = 2 * i, s1 = s0 + 1;
    int k0 = s0 / 3, r0 = s0 - 3 * k0;
    int k1 = s1 / 3, r1 = s1 - 3 * k1;
    const float* Wl = W + (size_t)l * K * N;
    float w0 = Wl[(size_t)k0 * N + n];
    float w1 = Wl[(size_t)k1 * N + n];
    __nv_bfloat16 h0, l0, h1, l1;
    split2(w0, h0, l0);
    split2(w1, h1, l1);
    __nv_bfloat16 v0 = (r0 == 2) ? l0 : h0;
    __nv_bfloat16 v1 = (r1 == 2) ? l1 : h1;
    __nv_bfloat162 pr(v0, v1);
    out[((size_t)l * PK + i) * N + n] = *reinterpret_cast<unsigned int*>(&pr);
}

// ---------------- embedding + LayerNorm ----------------
__global__ void embed_ln_kernel(const float* __restrict__ we, const float* __restrict__ pe,
                                const float* __restrict__ te, const float* __restrict__ gs,
                                const float* __restrict__ gb, const int* __restrict__ ids,
                                const int* __restrict__ tts, float* __restrict__ out,
                                __nv_bfloat16* __restrict__ ext) {
    __shared__ float red[8];
    int m = blockIdx.x;
    int s = m & (Sdim - 1);
    int id = ids[m], tt = tts[m];
    float vals[3];
    float lsum = 0.f;
#pragma unroll
    for (int u = 0; u < 3; u++) {
        int j = threadIdx.x + u * 256;
        float v = we[(size_t)id * Hdim + j] + pe[(size_t)s * Hdim + j] + te[(size_t)tt * Hdim + j];
        vals[u] = v;
        lsum += v;
    }
    float mean = blk_sum256(lsum, red) * (1.f / Hdim);
    float lsq = 0.f;
#pragma unroll
    for (int u = 0; u < 3; u++) { float d = vals[u] - mean; lsq += d * d; }
    float var = blk_sum256(lsq, red) * (1.f / Hdim);
    float inv = rsqrtf(var + 1e-12f);
#pragma unroll
    for (int u = 0; u < 3; u++) {
        int j = threadIdx.x + u * 256;
        float y = (vals[u] - mean) * inv * gs[j] + gb[j];
        out[(size_t)m * Hdim + j] = y;
        write_ext3(ext + (size_t)m * KE_H + 3 * j, y);
    }
}

// ---------------- LayerNorm ----------------
__global__ void ln_kernel(const float* __restrict__ x, const float* __restrict__ gs,
                          const float* __restrict__ gb, float* __restrict__ y,
                          __nv_bfloat16* __restrict__ ext) {
    __shared__ float red[8];
    int m = blockIdx.x;
    const float* xr = x + (size_t)m * Hdim;
    float vals[3];
    float lsum = 0.f;
#pragma unroll
    for (int u = 0; u < 3; u++) {
        vals[u] = xr[threadIdx.x + u * 256];
        lsum += vals[u];
    }
    float mean = blk_sum256(lsum, red) * (1.f / Hdim);
    float lsq = 0.f;
#pragma unroll
    for (int u = 0; u < 3; u++) { float d = vals[u] - mean; lsq += d * d; }
    float var = blk_sum256(lsq, red) * (1.f / Hdim);
    float inv = rsqrtf(var + 1e-12f);
#pragma unroll
    for (int u = 0; u < 3; u++) {
        int j = threadIdx.x + u * 256;
        float yy = (vals[u] - mean) * inv * gs[j] + gb[j];
        y[(size_t)m * Hdim + j] = yy;
        write_ext3(ext + (size_t)m * KE_H + 3 * j, yy);
    }
}

// ================= shared GEMM bits =================
__device__ __forceinline__ void cp16(unsigned int saddr, const void* gptr) {
    asm volatile("cp.async.cg.shared.global [%0], [%1], 16;\n" ::"r"(saddr), "l"(gptr));
}
__device__ __forceinline__ void cp_commit() { asm volatile("cp.async.commit_group;\n"); }
__device__ __forceinline__ void cp_wait2() { asm volatile("cp.async.wait_group 2;\n"); }

#define MMA16816(d, a, b)                                                      \
    asm volatile(                                                              \
        "mma.sync.aligned.m16n8k16.row.col.f32.bf16.bf16.f32 "                 \
        "{%0,%1,%2,%3}, {%4,%5,%6,%7}, {%8,%9}, {%0,%1,%2,%3};\n"              \
        : "+f"(d[0]), "+f"(d[1]), "+f"(d[2]), "+f"(d[3])                       \
        : "r"(a[0]), "r"(a[1]), "r"(a[2]), "r"(a[3]), "r"(b[0]), "r"(b[1]))

__device__ __forceinline__ void ldm_x4(unsigned int* a, unsigned int saddr) {
    asm volatile("ldmatrix.sync.aligned.m8n8.x4.shared.b16 {%0,%1,%2,%3}, [%4];"
                 : "=r"(a[0]), "=r"(a[1]), "=r"(a[2]), "=r"(a[3]) : "r"(saddr));
}

#define BKE 48
#define BKP 24
#define AS_STRIDE 28
#define BS_STRIDE 136

// ================= 64x128 GEMM (O proj, FF2) =================
#define STAGE_WORDS_H (64 * AS_STRIDE + BKP * BS_STRIDE)   // 5056
#define GEMM_SMEM_H (4 * STAGE_WORDS_H * 4)                // 80896 B

__device__ __forceinline__ void gemm_core_h(const __nv_bfloat16* __restrict__ A,
                                            const unsigned int* __restrict__ B,
                                            const float* __restrict__ bias,
                                            const float* __restrict__ res,
                                            float* __restrict__ Cf,
                                            int N, int KE, unsigned int* smem) {
    const int tid = threadIdx.x;
    const int lane = tid & 31;
    const int wid = tid >> 5;
    const int warp_m = wid >> 2;
    const int warp_n = wid & 3;
    const int m0 = blockIdx.y * 64;
    const int n0 = blockIdx.x * 128;
    const int T = KE / BKE;
    const int g = lane >> 2, t4 = lane & 3;
    // ldmatrix per-lane address parts
    const int lrow = warp_m * 32 + (lane & 15);
    const int lcol = (lane >> 4) << 2;

    float acc[2][4][4];
#pragma unroll
    for (int i = 0; i < 2; i++)
#pragma unroll
        for (int j = 0; j < 4; j++)
#pragma unroll
            for (int r = 0; r < 4; r++) acc[i][j][r] = 0.f;

    const unsigned int sbase = (unsigned int)__cvta_generic_to_shared(smem);

    auto load_stage = [&](int tile, int stg) {
        unsigned int abase = sbase + (unsigned int)(stg * STAGE_WORDS_H) * 4u;
        unsigned int bbase = abase + 64u * AS_STRIDE * 4u;
        const __nv_bfloat16* Ag = A + (size_t)m0 * KE + tile * BKE;
        {
            int i = tid;
            int r = i / 6, c = i % 6;
            cp16(abase + (unsigned int)(r * AS_STRIDE + c * 4) * 4u,
                 Ag + (size_t)r * KE + c * 8);
            i = tid + 256;
            if (i < 384) {
                r = i / 6; c = i % 6;
                cp16(abase + (unsigned int)(r * AS_STRIDE + c * 4) * 4u,
                     Ag + (size_t)r * KE + c * 8);
            }
        }
        const unsigned int* Bg = B + (size_t)(tile * BKP) * N + n0;
#pragma unroll
        for (int l = 0; l < 3; l++) {
            int i = tid + l * 256;
            int r = i >> 5, c = i & 31;
            cp16(bbase + (unsigned int)(r * BS_STRIDE + c * 4) * 4u,
                 Bg + (size_t)r * N + c * 4);
        }
    };

    load_stage(0, 0); cp_commit();
    load_stage(1, 1); cp_commit();
    load_stage(2, 2); cp_commit();

    for (int t = 0; t < T; t++) {
        cp_wait2();
        __syncthreads();
        if (t + 3 < T) load_stage(t + 3, (t + 3) & 3);
        cp_commit();

        const unsigned int abase = sbase + (unsigned int)((t & 3) * STAGE_WORDS_H) * 4u;
        const unsigned int* Bs = smem + (size_t)(t & 3) * STAGE_WORDS_H + 64 * AS_STRIDE;
#pragma unroll
        for (int s = 0; s < 3; s++) {
            unsigned int a[2][4], b[4][2];
#pragma unroll
            for (int mi = 0; mi < 2; mi++)
                ldm_x4(a[mi], abase + (unsigned int)(((lrow + mi * 16) * AS_STRIDE) +
                                                     s * 8 + lcol) * 4u);
#pragma unroll
            for (int nj = 0; nj < 4; nj++) {
                int n = warp_n * 32 + nj * 8 + g;
                b[nj][0] = Bs[(s * 8 + t4) * BS_STRIDE + n];
                b[nj][1] = Bs[(s * 8 + t4 + 4) * BS_STRIDE + n];
            }
#pragma unroll
            for (int mi = 0; mi < 2; mi++)
#pragma unroll
                for (int nj = 0; nj < 4; nj++) MMA16816(acc[mi][nj], a[mi], b[nj]);
        }
        __syncthreads();
    }

#pragma unroll
    for (int mi = 0; mi < 2; mi++) {
        int row0 = m0 + warp_m * 32 + mi * 16 + g;
#pragma unroll
        for (int nj = 0; nj < 4; nj++) {
            int col = n0 + warp_n * 32 + nj * 8 + t4 * 2;
            float b0 = bias[col], b1 = bias[col + 1];
#pragma unroll
            for (int half = 0; half < 2; half++) {
                int row = row0 + half * 8;
                float2 rr = *(const float2*)(res + (size_t)row * N + col);
                float v0 = acc[mi][nj][half * 2 + 0] + b0 + rr.x;
                float v1 = acc[mi][nj][half * 2 + 1] + b1 + rr.y;
                *(float2*)(Cf + (size_t)row * N + col) = make_float2(v0, v1);
            }
        }
    }
}

__global__ void __launch_bounds__(256, 2) gemm_kh(const __nv_bfloat16* __restrict__ A,
                                                  const unsigned int* __restrict__ B,
                                                  const float* __restrict__ bias,
                                                  const float* __restrict__ res,
                                                  float* __restrict__ Cf, int N, int KE) {
    extern __shared__ unsigned int smem[];
    gemm_core_h(A, B, bias, res, Cf, N, KE, smem);
}

// ================= 128x256 GEMM (QKV, FF1) =================
#define BSW_STRIDE 264
#define STAGE_WORDS_W (128 * AS_STRIDE + BKP * BSW_STRIDE)  // 9920
#define GEMM_SMEM_W (4 * STAGE_WORDS_W * 4)                 // 158720 B

__device__ __forceinline__ void gemm_core_w(const __nv_bfloat16* __restrict__ A,
                                            const unsigned int* __restrict__ B,
                                            const float* __restrict__ bias,
                                            float* __restrict__ Cf,
                                            __nv_bfloat16* __restrict__ Ce,
                                            int N, int KE, int act, int outp,
                                            unsigned int* smem) {
    const int tid = threadIdx.x;
    const int lane = tid & 31;
    const int wid = tid >> 5;
    const int warp_m = wid >> 2;
    const int warp_n = wid & 3;
    const int m0 = blockIdx.y * 128;
    const int n0 = blockIdx.x * 256;
    const int T = KE / BKE;
    const int g = lane >> 2, t4 = lane & 3;
    const int lrow = warp_m * 64 + (lane & 15);
    const int lcol = (lane >> 4) << 2;

    float acc[4][8][4];
#pragma unroll
    for (int i = 0; i < 4; i++)
#pragma unroll
        for (int j = 0; j < 8; j++)
#pragma unroll
            for (int r = 0; r < 4; r++) acc[i][j][r] = 0.f;

    const unsigned int sbase = (unsigned int)__cvta_generic_to_shared(smem);

    auto load_stage = [&](int tile, int stg) {
        unsigned int abase = sbase + (unsigned int)(stg * STAGE_WORDS_W) * 4u;
        unsigned int bbase = abase + 128u * AS_STRIDE * 4u;
        const __nv_bfloat16* Ag = A + (size_t)m0 * KE + tile * BKE;
#pragma unroll
        for (int l = 0; l < 3; l++) {
            int i = tid + l * 256;
            int r = i / 6, c = i % 6;
            cp16(abase + (unsigned int)(r * AS_STRIDE + c * 4) * 4u,
                 Ag + (size_t)r * KE + c * 8);
        }
        const unsigned int* Bg = B + (size_t)(tile * BKP) * N + n0;
#pragma unroll
        for (int l = 0; l < 6; l++) {
            int i = tid + l * 256;
            int r = i >> 6, c = i & 63;
            cp16(bbase + (unsigned int)(r * BSW_STRIDE + c * 4) * 4u,
                 Bg + (size_t)r * N + c * 4);
        }
    };

    load_stage(0, 0); cp_commit();
    load_stage(1, 1); cp_commit();
    load_stage(2, 2); cp_commit();

    for (int t = 0; t < T; t++) {
        cp_wait2();
        __syncthreads();
        if (t + 3 < T) load_stage(t + 3, (t + 3) & 3);
        cp_commit();

        const unsigned int abase = sbase + (unsigned int)((t & 3) * STAGE_WORDS_W) * 4u;
        const unsigned int* Bs = smem + (size_t)(t & 3) * STAGE_WORDS_W + 128 * AS_STRIDE;
#pragma unroll
        for (int s = 0; s < 3; s++) {
            unsigned int a[4][4];
#pragma unroll
            for (int mi = 0; mi < 4; mi++)
                ldm_x4(a[mi], abase + (unsigned int)(((lrow + mi * 16) * AS_STRIDE) +
                                                     s * 8 + lcol) * 4u);
#pragma unroll
            for (int nj = 0; nj < 8; nj++) {
                unsigned int b[2];
                int n = warp_n * 64 + nj * 8 + g;
                b[0] = Bs[(s * 8 + t4) * BSW_STRIDE + n];
                b[1] = Bs[(s * 8 + t4 + 4) * BSW_STRIDE + n];
#pragma unroll
                for (int mi = 0; mi < 4; mi++) MMA16816(acc[mi][nj], a[mi], b);
            }
        }
        __syncthreads();
    }

#pragma unroll
    for (int mi = 0; mi < 4; mi++) {
        int row0 = m0 + warp_m * 64 + mi * 16 + g;
#pragma unroll
        for (int nj = 0; nj < 8; nj++) {
            int col = n0 + warp_n * 64 + nj * 8 + t4 * 2;
            float b0 = bias[col], b1 = bias[col + 1];
#pragma unroll
            for (int half = 0; half < 2; half++) {
                int row = row0 + half * 8;
                float v0 = acc[mi][nj][half * 2 + 0] + b0;
                float v1 = acc[mi][nj][half * 2 + 1] + b1;
                if (act) {
                    v0 = 0.5f * v0 * (1.f + erff(v0 * 0.70710678118654752440f));
                    v1 = 0.5f * v1 * (1.f + erff(v1 * 0.70710678118654752440f));
                }
                if (outp == 0) {
                    *(float2*)(Cf + (size_t)row * N + col) = make_float2(v0, v1);
                } else {
                    __nv_bfloat16* p = Ce + (size_t)row * (3 * N) + 3 * col;
                    write_ext3(p, v0);
                    write_ext3(p + 3, v1);
                }
            }
        }
    }
}

__global__ void __launch_bounds__(256, 1) gemm_k1w(const __nv_bfloat16* __restrict__ A,
                                                   const unsigned int* __restrict__ B,
                                                   const float* __restrict__ bias,
                                                   float* __restrict__ Cf,
                                                   __nv_bfloat16* __restrict__ Ce,
                                                   int N, int KE, int act, int outp) {
    extern __shared__ unsigned int smem[];
    gemm_core_w(A, B, bias, Cf, Ce, N, KE, act, outp, smem);
}

__global__ void __launch_bounds__(256, 1) gemm_k3w(const __nv_bfloat16* __restrict__ A,
                                                   const unsigned int* __restrict__ B0,
                                                   const unsigned int* __restrict__ B1,
                                                   const unsigned int* __restrict__ B2,
                                                   const float* __restrict__ bias0,
                                                   const float* __restrict__ bias1,
                                                   const float* __restrict__ bias2,
                                                   float* __restrict__ C0, float* __restrict__ C1,
                                                   float* __restrict__ C2, int KE) {
    extern __shared__ unsigned int smem[];
    int z = blockIdx.z;
    const unsigned int* B = (z == 0) ? B0 : (z == 1) ? B1 : B2;
    const float* bias = (z == 0) ? bias0 : (z == 1) ? bias1 : bias2;
    float* Cf = (z == 0) ? C0 : (z == 1) ? C1 : C2;
    gemm_core_w(A, B, bias, Cf, nullptr, Hdim, KE, 0, 0, smem);
}

// ======== tensor-core attention (split-bf16 3-slot) ========
#define A_OFF_MB 0
#define A_OFF_Q  512
#define A_OFF_K  (512 + 6400)
#define A_OFF_V  (512 + 6400 + 6912)
#define A_OFF_P  (512 + 6400 + 13824)
#define A_OFF_PM (512 + 6400 + 13824 + 6400)
#define A_OFF_RM (A_OFF_PM + 128)
#define A_OFF_PS (A_OFF_RM + 64)
#define A_OFF_RS (A_OFF_PS + 128)
#define ATTN_SMEM ((A_OFF_RS + 64) * 4)

__global__ void __launch_bounds__(256) attn_kernel(const float* __restrict__ Q,
                                                   const float* __restrict__ Kp,
                                                   const float* __restrict__ Vp,
                                                   const int* __restrict__ amask,
                                                   __nv_bfloat16* __restrict__ Oext) {
    extern __shared__ unsigned int sm[];
    float* mbias = (float*)(sm + A_OFF_MB);
    unsigned int* qx = sm + A_OFF_Q;
    unsigned int* kx = sm + A_OFF_K;
    unsigned int* vx = sm + A_OFF_V;
    unsigned int* px = sm + A_OFF_P;
    float* partmax = (float*)(sm + A_OFF_PM);
    float* rowmax = (float*)(sm + A_OFF_RM);
    float* partsum = (float*)(sm + A_OFF_PS);
    float* rowsum = (float*)(sm + A_OFF_RS);
    unsigned short* qx16 = (unsigned short*)qx;
    unsigned short* kx16 = (unsigned short*)kx;
    unsigned short* vx16 = (unsigned short*)vx;
    unsigned short* px16 = (unsigned short*)px;

    const int tid = threadIdx.x, lane = tid & 31, w = tid >> 5;
    const int wm = w >> 1, wn = w & 1, g = lane >> 2, t4 = lane & 3;
    const int q0 = blockIdx.x * 64, h = blockIdx.y, b = blockIdx.z;
    const size_t base = (size_t)b * Sdim * Hdim + h * 64;
    const int r0 = wm * 16 + g, r1 = r0 + 8;

    for (int i = tid; i < Sdim; i += 256)
        mbias[i] = (1.f - (float)amask[b * Sdim + i]) * -10000.f;

    for (int i = tid; i < 4096; i += 256) {
        int r = i >> 6, d = i & 63;
        float xv = Q[base + (size_t)(q0 + r) * Hdim + d];
        __nv_bfloat16 hh, ll;
        split2(xv, hh, ll);
        unsigned short uh = *(unsigned short*)&hh, ul = *(unsigned short*)&ll;
        int o = r * 200 + 3 * d;
        qx16[o] = uh; qx16[o + 1] = ul; qx16[o + 2] = uh;
    }
    __syncthreads();

    float sacc[32][4];
#pragma unroll
    for (int i = 0; i < 32; i++)
#pragma unroll
        for (int j = 0; j < 4; j++) sacc[i][j] = 0.f;

#pragma unroll
    for (int kb = 0; kb < 8; kb++) {
        for (int i = tid; i < 4096; i += 256) {
            int kk = i >> 6, d = i & 63;
            float xv = Kp[base + (size_t)(kb * 64 + kk) * Hdim + d];
            __nv_bfloat16 hh, ll;
            split2(xv, hh, ll);
            unsigned short uh = *(unsigned short*)&hh, ul = *(unsigned short*)&ll;
            int e = 3 * d;
            kx16[(e >> 1) * 144 + kk * 2 + (e & 1)] = uh;
            kx16[((e + 1) >> 1) * 144 + kk * 2 + ((e + 1) & 1)] = uh;
            kx16[((e + 2) >> 1) * 144 + kk * 2 + ((e + 2) & 1)] = ul;
        }
        __syncthreads();
#pragma unroll
        for (int s = 0; s < 12; s++) {
            unsigned int a[4];
            int ar = r0 * 100 + s * 8 + t4;
            a[0] = qx[ar]; a[1] = qx[ar + 800]; a[2] = qx[ar + 4]; a[3] = qx[ar + 804];
#pragma unroll
            for (int j = 0; j < 4; j++) {
                unsigned int bb[2];
                int br = (s * 8 + t4) * 72 + wn * 32 + j * 8 + g;
                bb[0] = kx[br]; bb[1] = kx[br + 288];
                MMA16816(sacc[kb * 4 + j], a, bb);
            }
        }
        __syncthreads();
    }

    float rm0 = -1e30f, rm1 = -1e30f;
#pragma unroll
    for (int kb = 0; kb < 8; kb++)
#pragma unroll
        for (int j = 0; j < 4; j++) {
            int c = kb * 64 + wn * 32 + j * 8 + 2 * t4;
            float m0 = mbias[c], m1 = mbias[c + 1];
            float* A = sacc[kb * 4 + j];
            A[0] = A[0] * 0.125f + m0;
            A[1] = A[1] * 0.125f + m1;
            A[2] = A[2] * 0.125f + m0;
            A[3] = A[3] * 0.125f + m1;
            rm0 = fmaxf(rm0, fmaxf(A[0], A[1]));
            rm1 = fmaxf(rm1, fmaxf(A[2], A[3]));
        }
    rm0 = fmaxf(rm0, __shfl_xor_sync(0xffffffffu, rm0, 1));
    rm0 = fmaxf(rm0, __shfl_xor_sync(0xffffffffu, rm0, 2));
    rm1 = fmaxf(rm1, __shfl_xor_sync(0xffffffffu, rm1, 1));
    rm1 = fmaxf(rm1, __shfl_xor_sync(0xffffffffu, rm1, 2));
    if (t4 == 0) {
        partmax[r0 * 2 + wn] = rm0;
        partmax[r1 * 2 + wn] = rm1;
    }
    __syncthreads();
    if (tid < 64) rowmax[tid] = fmaxf(partmax[tid * 2], partmax[tid * 2 + 1]);
    __syncthreads();
    const float mx0 = rowmax[r0], mx1 = rowmax[r1];

    float oacc[4][4];
#pragma unroll
    for (int j = 0; j < 4; j++)
#pragma unroll
        for (int r = 0; r < 4; r++) oacc[j][r] = 0.f;
    float sum0 = 0.f, sum1 = 0.f;

#pragma unroll
    for (int kb = 0; kb < 8; kb++) {
        for (int i = tid; i < 4096; i += 256) {
            int kk = i >> 6, d = i & 63;
            float xv = Vp[base + (size_t)(kb * 64 + kk) * Hdim + d];
            __nv_bfloat16 hh, ll;
            split2(xv, hh, ll);
            unsigned short uh = *(unsigned short*)&hh, ul = *(unsigned short*)&ll;
            int e = 3 * kk;
            vx16[(e >> 1) * 144 + d * 2 + (e & 1)] = uh;
            vx16[((e + 1) >> 1) * 144 + d * 2 + ((e + 1) & 1)] = uh;
            vx16[((e + 2) >> 1) * 144 + d * 2 + ((e + 2) & 1)] = ul;
        }
#pragma unroll
        for (int j = 0; j < 4; j++) {
            float* A = sacc[kb * 4 + j];
#pragma unroll
            for (int c01 = 0; c01 < 2; c01++) {
                int lc = wn * 32 + j * 8 + 2 * t4 + c01;
                float p0 = fexp(A[c01] - mx0);
                float p1 = fexp(A[2 + c01] - mx1);
                sum0 += p0;
                sum1 += p1;
                __nv_bfloat16 hh, ll;
                split2(p0, hh, ll);
                int o0 = r0 * 200 + 3 * lc;
                px16[o0] = *(unsigned short*)&hh;
                px16[o0 + 1] = *(unsigned short*)&ll;
                px16[o0 + 2] = *(unsigned short*)&hh;
                split2(p1, hh, ll);
                int o1 = r1 * 200 + 3 * lc;
                px16[o1] = *(unsigned short*)&hh;
                px16[o1 + 1] = *(unsigned short*)&ll;
                px16[o1 + 2] = *(unsigned short*)&hh;
            }
        }
        __syncthreads();
#pragma unroll
        for (int s = 0; s < 12; s++) {
            unsigned int a[4];
            int ar = r0 * 100 + s * 8 + t4;
            a[0] = px[ar]; a[1] = px[ar + 800]; a[2] = px[ar + 4]; a[3] = px[ar + 804];
#pragma unroll
            for (int j2 = 0; j2 < 4; j2++) {
                unsigned int bb[2];
                int br = (s * 8 + t4) * 72 + wn * 32 + j2 * 8 + g;
                bb[0] = vx[br]; bb[1] = vx[br + 288];
                MMA16816(oacc[j2], a, bb);
            }
        }
        __syncthreads();
    }

    sum0 += __shfl_xor_sync(0xffffffffu, sum0, 1);
    sum0 += __shfl_xor_sync(0xffffffffu, sum0, 2);
    sum1 += __shfl_xor_sync(0xffffffffu, sum1, 1);
    sum1 += __shfl_xor_sync(0xffffffffu, sum1, 2);
    if (t4 == 0) {
        partsum[r0 * 2 + wn] = sum0;
        partsum[r1 * 2 + wn] = sum1;
    }
    __syncthreads();
    if (tid < 64) rowsum[tid] = partsum[tid * 2] + partsum[tid * 2 + 1];
    __syncthreads();
    const float inv0 = 1.f / rowsum[r0];
    const float inv1 = 1.f / rowsum[r1];

#pragma unroll
    for (int j2 = 0; j2 < 4; j2++) {
        int dcol = wn * 32 + j2 * 8 + 2 * t4;
        int mrow0 = b * Sdim + q0 + r0;
        int mrow1 = b * Sdim + q0 + r1;
        __nv_bfloat16* p0 = Oext + (size_t)mrow0 * KE_H + 3 * (h * 64 + dcol);
        write_ext3(p0, oacc[j2][0] * inv0);
        write_ext3(p0 + 3, oacc[j2][1] * inv0);
        __nv_bfloat16* p1 = Oext + (size_t)mrow1 * KE_H + 3 * (h * 64 + dcol);
        write_ext3(p1, oacc[j2][2] * inv1);
        write_ext3(p1 + 3, oacc[j2][3] * inv1);
    }
}

// ---------------- classifier ----------------
__global__ void clf_kernel(const float* __restrict__ X, const float* __restrict__ W,
                           const float* __restrict__ bias, float* __restrict__ F) {
    __shared__ float red[8][Ldim];
    int m = blockIdx.x;
    int tid = threadIdx.x;
    float acc[Ldim];
#pragma unroll
    for (int j = 0; j < Ldim; j++) acc[j] = 0.f;
    for (int k = tid; k < Hdim; k += 256) {
        float x = X[(size_t)m * Hdim + k];
#pragma unroll
        for (int j = 0; j < Ldim; j++) acc[j] += x * W[k * Ldim + j];
    }
    int lane = tid & 31, w = tid >> 5;
#pragma unroll
    for (int j = 0; j < Ldim; j++)
#pragma unroll
        for (int o = 16; o; o >>= 1) acc[j] += __shfl_down_sync(0xffffffffu, acc[j], o);
    if (lane == 0)
#pragma unroll
        for (int j = 0; j < Ldim; j++) red[w][j] = acc[j];
    __syncthreads();
    if (tid < Ldim) {
        float s = bias[tid];
#pragma unroll
        for (int ww = 0; ww < 8; ww++) s += red[ww][tid];
        F[(size_t)m * Ldim + tid] = s;
    }
}

// ---------------- CRF numerator ----------------
__global__ void crf_num_kernel(const float* __restrict__ feats, const int* __restrict__ amask,
                               const int* __restrict__ labels, const float* __restrict__ start,
                               const float* __restrict__ endv, const float* __restrict__ trans,
                               float* __restrict__ num) {
    __shared__ float red[8];
    int b = blockIdx.x;
    int tid = threadIdx.x;
    float s = 0.f, msum = 0.f;
    for (int t = tid; t < Sdim; t += 256) {
        int tag = labels[b * Sdim + t];
        float em = feats[(size_t)(b * Sdim + t) * Ldim + tag];
        float m = (float)amask[b * Sdim + t];
        msum += m;
        if (t == 0) {
            s += start[tag] + em;
        } else {
            int pt = labels[b * Sdim + t - 1];
            s += (em + trans[pt * Ldim + tag]) * m;
        }
    }
    float stotal = blk_sum256(s, red);
    float mtotal = blk_sum256(msum, red);
    if (tid == 0) {
        int last = (int)(mtotal + 0.5f) - 1;
        num[b] = stotal + endv[labels[b * Sdim + last]];
    }
}

// ---------------- CRF forward ----------------
__global__ void crf_fwd_kernel(const float* __restrict__ feats, const int* __restrict__ amask,
                               const float* __restrict__ start, const float* __restrict__ endv,
                               const float* __restrict__ trans, float* __restrict__ logZ) {
    int b = threadIdx.x >> 5;
    int j = threadIdx.x & 31;
    bool act = j < Ldim;
    float tr[Ldim];
#pragma unroll
    for (int i = 0; i < Ldim; i++) tr[i] = act ? trans[i * Ldim + j] : 0.f;
    float score = act ? start[j] + feats[(size_t)(b * Sdim) * Ldim + j] : -1e30f;
    for (int t = 1; t < Sdim; t++) {
        float e = act ? feats[(size_t)(b * Sdim + t) * Ldim + j] : 0.f;
        int m = amask[b * Sdim + t];
        float v[Ldim];
        float mx = -1e30f;
#pragma unroll
        for (int i = 0; i < Ldim; i++) {
            float si = __shfl_sync(0xffffffffu, score, i);
            v[i] = si + tr[i];
            mx = fmaxf(mx, v[i]);
        }
        float ssum = 0.f;
#pragma unroll
        for (int i = 0; i < Ldim; i++) ssum += expf(v[i] - mx);
        float nxt = mx + logf(ssum) + e;
        if (act && m > 0) score = nxt;
    }
    float tot = act ? score + endv[j] : -1e30f;
    float mx = tot;
#pragma unroll
    for (int o = 16; o; o >>= 1) mx = fmaxf(mx, __shfl_xor_sync(0xffffffffu, mx, o));
    float ex = act ? expf(tot - mx) : 0.f;
#pragma unroll
    for (int o = 16; o; o >>= 1) ex += __shfl_xor_sync(0xffffffffu, ex, o);
    if (j == 0) logZ[b] = mx + logf(ex);
}

// ---------------- Viterbi ----------------
__global__ void viterbi_kernel(const float* __restrict__ feats, const int* __restrict__ amask,
                               const float* __restrict__ start, const float* __restrict__ endv,
                               const float* __restrict__ trans, int* __restrict__ tags) {
    __shared__ unsigned char hist[(Sdim - 1) * Ldim];
    int b = blockIdx.x;
    int j = threadIdx.x;
    bool act = j < Ldim;
    float tr[Ldim];
#pragma unroll
    for (int i = 0; i < Ldim; i++) tr[i] = act ? trans[i * Ldim + j] : 0.f;
    float score = act ? start[j] + feats[(size_t)(b * Sdim) * Ldim + j] : -1e30f;
    for (int t = 1; t < Sdim; t++) {
        float e = act ? feats[(size_t)(b * Sdim + t) * Ldim + j] : 0.f;
        int m = amask[b * Sdim + t];
        float best = -1e30f;
        int barg = 0;
#pragma unroll
        for (int i = 0; i < Ldim; i++) {
            float si = __shfl_sync(0xffffffffu, score, i);
            float v = si + tr[i];
            if (v > best) { best = v; barg = i; }
        }
        if (act) {
            hist[(t - 1) * Ldim + j] = (unsigned char)barg;
            float nxt = best + e;
            if (m > 0) score = nxt;
        }
    }
    __syncwarp();
    float tot = act ? score + endv[j] : -1e30f;
    float bb = tot;
    int bj = act ? j : 0;
#pragma unroll
    for (int o = 16; o; o >>= 1) {
        float ov = __shfl_down_sync(0xffffffffu, bb, o);
        int oj = __shfl_down_sync(0xffffffffu, bj, o);
        if (ov > bb) { bb = ov; bj = oj; }
    }
    if (j == 0) {
        int tag = bj;
        tags[b * Sdim + Sdim - 1] = tag;
        for (int t = Sdim - 2; t >= 0; t--) {
            tag = hist[t * Ldim + tag];
            tags[b * Sdim + t] = tag;
        }
    }
}

// ---------------- finalize ----------------
__global__ void finalize_kernel(const float* __restrict__ logZ, const float* __restrict__ num,
                                const int* __restrict__ tags, float* __restrict__ out,
                                int out_size) {
    int i = blockIdx.x * blockDim.x + threadIdx.x;
    if (i >= out_size) return;
    if (i == 0) {
        float s = 0.f;
        for (int b = 0; b < Bdim; b++) s += logZ[b] - num[b];
        out[0] = s * (1.f / Bdim);
    } else if (i - 1 < Bdim * Sdim) {
        out[i] = (float)tags[i - 1];
    } else {
        out[i] = 0.f;
    }
}

// ---------------- host launch ----------------
extern "C" void kernel_launch(void* const* d_in, const int* in_sizes, int n_in,
                              void* d_out, int out_size) {
    const float* word_emb = (const float*)d_in[0];
    const float* pos_emb  = (const float*)d_in[1];
    const float* type_emb = (const float*)d_in[2];
    const float* eln_s    = (const float*)d_in[3];
    const float* eln_b    = (const float*)d_in[4];
    const float* Wq = (const float*)d_in[5];
    const float* bq = (const float*)d_in[6];
    const float* Wk = (const float*)d_in[7];
    const float* bk = (const float*)d_in[8];
    const float* Wv = (const float*)d_in[9];
    const float* bv = (const float*)d_in[10];
    const float* Wo = (const float*)d_in[11];
    const float* bo = (const float*)d_in[12];
    const float* ln1s = (const float*)d_in[13];
    const float* ln1b = (const float*)d_in[14];
    const float* W1 = (const float*)d_in[15];
    const float* b1 = (const float*)d_in[16];
    const float* W2 = (const float*)d_in[17];
    const float* b2 = (const float*)d_in[18];
    const float* ln2s = (const float*)d_in[19];
    const float* ln2b = (const float*)d_in[20];
    const float* clfW = (const float*)d_in[21];
    const float* clfb = (const float*)d_in[22];
    const float* crf_start = (const float*)d_in[23];
    const float* crf_end   = (const float*)d_in[24];
    const float* crf_trans = (const float*)d_in[25];
    const int* input_ids   = (const int*)d_in[26];
    const int* token_type  = (const int*)d_in[27];
    const int* attn_mask   = (const int*)d_in[28];
    const int* labels      = (const int*)d_in[29];

    float *h, *q, *k, *v, *t, *feats, *logZ, *num;
    int* tags;
    __nv_bfloat16 *hext, *ctxext, *ffext;
    unsigned int *Wqp, *Wkp, *Wvp, *Wop, *W1p, *W2p;
    cudaGetSymbolAddress((void**)&h, g_h);
    cudaGetSymbolAddress((void**)&q, g_q);
    cudaGetSymbolAddress((void**)&k, g_k);
    cudaGetSymbolAddress((void**)&v, g_v);
    cudaGetSymbolAddress((void**)&t, g_t);
    cudaGetSymbolAddress((void**)&feats, g_feats);
    cudaGetSymbolAddress((void**)&logZ, g_logZ);
    cudaGetSymbolAddress((void**)&num, g_num);
    cudaGetSymbolAddress((void**)&tags, g_tags);
    cudaGetSymbolAddress((void**)&hext, g_hext);
    cudaGetSymbolAddress((void**)&ctxext, g_ctxext);
    cudaGetSymbolAddress((void**)&ffext, g_ffext);
    cudaGetSymbolAddress((void**)&Wqp, g_Wqp);
    cudaGetSymbolAddress((void**)&Wkp, g_Wkp);
    cudaGetSymbolAddress((void**)&Wvp, g_Wvp);
    cudaGetSymbolAddress((void**)&Wop, g_Wop);
    cudaGetSymbolAddress((void**)&W1p, g_W1p);
    cudaGetSymbolAddress((void**)&W2p, g_W2p);

    cudaFuncSetAttribute(attn_kernel, cudaFuncAttributeMaxDynamicSharedMemorySize, ATTN_SMEM);
    cudaFuncSetAttribute(gemm_kh, cudaFuncAttributeMaxDynamicSharedMemorySize, GEMM_SMEM_H);
    cudaFuncSetAttribute(gemm_k1w, cudaFuncAttributeMaxDynamicSharedMemorySize, GEMM_SMEM_W);
    cudaFuncSetAttribute(gemm_k3w, cudaFuncAttributeMaxDynamicSharedMemorySize, GEMM_SMEM_W);

    convP_kernel<<<dim3(Hdim / 256, PKH, NLnum), 256>>>(Wq, Wqp, Hdim, Hdim);
    convP_kernel<<<dim3(Hdim / 256, PKH, NLnum), 256>>>(Wk, Wkp, Hdim, Hdim);
    convP_kernel<<<dim3(Hdim / 256, PKH, NLnum), 256>>>(Wv, Wvp, Hdim, Hdim);
    convP_kernel<<<dim3(Hdim / 256, PKH, NLnum), 256>>>(Wo, Wop, Hdim, Hdim);
    convP_kernel<<<dim3(FFdim / 256, PKH, NLnum), 256>>>(W1, W1p, Hdim, FFdim);
    convP_kernel<<<dim3(Hdim / 256, PKF, NLnum), 256>>>(W2, W2p, FFdim, Hdim);
    embed_ln_kernel<<<Mtot, 256>>>(word_emb, pos_emb, type_emb, eln_s, eln_b,
                                   input_ids, token_type, h, hext);

    dim3 gQKV(Hdim / 256, Mtot / 128, 3);
    dim3 gFF1(FFdim / 256, Mtot / 128);
    dim3 gHalf(Hdim / 128, Mtot / 64);
    dim3 gAttn(Sdim / 64, NHnum, Bdim);
    const size_t woff = (size_t)PKH * Hdim;
    const size_t w1off = (size_t)PKH * FFdim;
    const size_t w2off = (size_t)PKF * Hdim;

    for (int l = 0; l < NLnum; l++) {
        gemm_k3w<<<gQKV, 256, GEMM_SMEM_W>>>(hext, Wqp + l * woff, Wkp + l * woff,
                                             Wvp + l * woff, bq + l * Hdim, bk + l * Hdim,
                                             bv + l * Hdim, q, k, v, KE_H);
        attn_kernel<<<gAttn, 256, ATTN_SMEM>>>(q, k, v, attn_mask, ctxext);
        gemm_kh<<<gHalf, 256, GEMM_SMEM_H>>>(ctxext, Wop + l * woff, bo + l * Hdim, h, t,
                                             Hdim, KE_H);
        ln_kernel<<<Mtot, 256>>>(t, ln1s + l * Hdim, ln1b + l * Hdim, h, hext);
        gemm_k1w<<<gFF1, 256, GEMM_SMEM_W>>>(hext, W1p + l * w1off, b1 + l * FFdim, nullptr,
                                             ffext, FFdim, KE_H, 1, 1);
        gemm_kh<<<gHalf, 256, GEMM_SMEM_H>>>(ffext, W2p + l * w2off, b2 + l * Hdim, h, t,
                                             Hdim, KE_FF);
        ln_kernel<<<Mtot, 256>>>(t, ln2s + l * Hdim, ln2b + l * Hdim, h, hext);
    }

    clf_kernel<<<Mtot, 256>>>(h, clfW, clfb, feats);
    crf_num_kernel<<<Bdim, 256>>>(feats, attn_mask, labels, crf_start, crf_end, crf_trans, num);
    crf_fwd_kernel<<<1, 256>>>(feats, attn_mask, crf_start, crf_end, crf_trans, logZ);
    viterbi_kernel<<<Bdim, 32>>>(feats, attn_mask, crf_start, crf_end, crf_trans, tags);

    int nfin = (out_size + 255) / 256;
    if (nfin < 1) nfin = 1;
    finalize_kernel<<<nfin, 256>>>(logZ, num, tags, (float*)d_out, out_size);
}

// round 16
// speedup vs baseline: 1.2310x; 1.0037x over previous
#include <cuda_runtime.h>
#include <cuda_bf16.h>
#include <math.h>

#define Mtot  4096
#define Hdim  768
#define FFdim 3072
#define NHnum 12
#define DHdim 64
#define Sdim  512
#define Bdim  8
#define Ldim  9
#define NLnum 12

#define KE_H  (3 * Hdim)    // 2304
#define KE_FF (3 * FFdim)   // 9216

// ---------------- scratch ----------------
__device__ float g_h[Mtot * Hdim];
__device__ float g_q[Mtot * Hdim];
__device__ float g_k[Mtot * Hdim];
__device__ float g_v[Mtot * Hdim];
__device__ float g_t[Mtot * Hdim];
__device__ float g_feats[Mtot * Ldim];
__device__ float g_logZ[Bdim];
__device__ float g_num[Bdim];
__device__ int   g_tags[Bdim * Sdim];

__device__ __align__(256) __nv_bfloat16 g_hext[Mtot * KE_H];
__device__ __align__(256) __nv_bfloat16 g_ctxext[Mtot * KE_H];
__device__ __align__(256) __nv_bfloat16 g_ffext[(size_t)Mtot * KE_FF];

#define PKH (3 * Hdim / 2)    // 1152
#define PKF (3 * FFdim / 2)   // 4608
__device__ __align__(256) unsigned int g_Wqp[NLnum * PKH * Hdim];
__device__ __align__(256) unsigned int g_Wkp[NLnum * PKH * Hdim];
__device__ __align__(256) unsigned int g_Wvp[NLnum * PKH * Hdim];
__device__ __align__(256) unsigned int g_Wop[NLnum * PKH * Hdim];
__device__ __align__(256) unsigned int g_W1p[(size_t)NLnum * PKH * FFdim];
__device__ __align__(256) unsigned int g_W2p[(size_t)NLnum * PKF * Hdim];

// ---------------- helpers ----------------
__device__ __forceinline__ float blk_sum256(float v, float* red) {
    int lane = threadIdx.x & 31, w = threadIdx.x >> 5;
#pragma unroll
    for (int o = 16; o; o >>= 1) v += __shfl_xor_sync(0xffffffffu, v, o);
    __syncthreads();
    if (lane == 0) red[w] = v;
    __syncthreads();
    float s = 0.f;
#pragma unroll
    for (int i = 0; i < 8; i++) s += red[i];
    return s;
}

__device__ __forceinline__ void split2(float x, __nv_bfloat16& hi, __nv_bfloat16& lo) {
    hi = __float2bfloat16(x);
    lo = __float2bfloat16(x - __bfloat162float(hi));
}

__device__ __forceinline__ void write_ext3(__nv_bfloat16* p, float x) {
    __nv_bfloat16 h, l;
    split2(x, h, l);
    p[0] = h; p[1] = l; p[2] = h;
}

__device__ __forceinline__ float fexp(float x) {
    float t = x * 1.4426950408889634f;
    t = fmaxf(t, -126.0f);
    float fl = floorf(t);
    float f = t - fl;
    float p = 1.525273e-5f;
    p = fmaf(p, f, 1.5403530e-4f);
    p = fmaf(p, f, 1.3333558e-3f);
    p = fmaf(p, f, 9.6181291e-3f);
    p = fmaf(p, f, 5.5504109e-2f);
    p = fmaf(p, f, 2.4022651e-1f);
    p = fmaf(p, f, 6.9314718e-1f);
    p = fmaf(p, f, 1.0f);
    return p * __int_as_float(((int)fl + 127) << 23);
}

// ---------------- weight conversion (vectorized: 1 thread = 4 cols) ----------------
__device__ __forceinline__ unsigned int packpair(float w0, float w1, int r0, int r1) {
    __nv_bfloat16 h0, l0, h1, l1;
    split2(w0, h0, l0);
    split2(w1, h1, l1);
    __nv_bfloat16 v0 = (r0 == 2) ? l0 : h0;
    __nv_bfloat16 v1 = (r1 == 2) ? l1 : h1;
    __nv_bfloat162 pr(v0, v1);
    return *reinterpret_cast<unsigned int*>(&pr);
}

__global__ void convP4_kernel(const float* __restrict__ W, unsigned int* __restrict__ out,
                              int K, int N) {
    int n4 = blockIdx.x * 256 + threadIdx.x;
    int n = n4 * 4;
    if (n >= N) return;
    int i = blockIdx.y;
    int l = blockIdx.z;
    int PK = 3 * K / 2;
    int s0 = 2 * i, s1 = s0 + 1;
    int k0 = s0 / 3, r0 = s0 - 3 * k0;
    int k1 = s1 / 3, r1 = s1 - 3 * k1;
    const float* Wl = W + (size_t)l * K * N;
    float4 w0 = *(const float4*)(Wl + (size_t)k0 * N + n);
    float4 w1 = *(const float4*)(Wl + (size_t)k1 * N + n);
    uint4 o;
    o.x = packpair(w0.x, w1.x, r0, r1);
    o.y = packpair(w0.y, w1.y, r0, r1);
    o.z = packpair(w0.z, w1.z, r0, r1);
    o.w = packpair(w0.w, w1.w, r0, r1);
    *(uint4*)(out + ((size_t)l * PK + i) * N + n) = o;
}

// ---------------- embedding + LayerNorm ----------------
__global__ void embed_ln_kernel(const float* __restrict__ we, const float* __restrict__ pe,
                                const float* __restrict__ te, const float* __restrict__ gs,
                                const float* __restrict__ gb, const int* __restrict__ ids,
                                const int* __restrict__ tts, float* __restrict__ out,
                                __nv_bfloat16* __restrict__ ext) {
    __shared__ float red[8];
    int m = blockIdx.x;
    int s = m & (Sdim - 1);
    int id = ids[m], tt = tts[m];
    float vals[3];
    float lsum = 0.f;
#pragma unroll
    for (int u = 0; u < 3; u++) {
        int j = threadIdx.x + u * 256;
        float v = we[(size_t)id * Hdim + j] + pe[(size_t)s * Hdim + j] + te[(size_t)tt * Hdim + j];
        vals[u] = v;
        lsum += v;
    }
    float mean = blk_sum256(lsum, red) * (1.f / Hdim);
    float lsq = 0.f;
#pragma unroll
    for (int u = 0; u < 3; u++) { float d = vals[u] - mean; lsq += d * d; }
    float var = blk_sum256(lsq, red) * (1.f / Hdim);
    float inv = rsqrtf(var + 1e-12f);
#pragma unroll
    for (int u = 0; u < 3; u++) {
        int j = threadIdx.x + u * 256;
        float y = (vals[u] - mean) * inv * gs[j] + gb[j];
        out[(size_t)m * Hdim + j] = y;
        write_ext3(ext + (size_t)m * KE_H + 3 * j, y);
    }
}

// ---------------- LayerNorm ----------------
__global__ void ln_kernel(const float* __restrict__ x, const float* __restrict__ gs,
                          const float* __restrict__ gb, float* __restrict__ y,
                          __nv_bfloat16* __restrict__ ext) {
    __shared__ float red[8];
    int m = blockIdx.x;
    const float* xr = x + (size_t)m * Hdim;
    float vals[3];
    float lsum = 0.f;
#pragma unroll
    for (int u = 0; u < 3; u++) {
        vals[u] = xr[threadIdx.x + u * 256];
        lsum += vals[u];
    }
    float mean = blk_sum256(lsum, red) * (1.f / Hdim);
    float lsq = 0.f;
#pragma unroll
    for (int u = 0; u < 3; u++) { float d = vals[u] - mean; lsq += d * d; }
    float var = blk_sum256(lsq, red) * (1.f / Hdim);
    float inv = rsqrtf(var + 1e-12f);
#pragma unroll
    for (int u = 0; u < 3; u++) {
        int j = threadIdx.x + u * 256;
        float yy = (vals[u] - mean) * inv * gs[j] + gb[j];
        y[(size_t)m * Hdim + j] = yy;
        write_ext3(ext + (size_t)m * KE_H + 3 * j, yy);
    }
}

// ================= shared GEMM bits =================
__device__ __forceinline__ void cp16(unsigned int saddr, const void* gptr) {
    asm volatile("cp.async.cg.shared.global [%0], [%1], 16;\n" ::"r"(saddr), "l"(gptr));
}
__device__ __forceinline__ void cp_commit() { asm volatile("cp.async.commit_group;\n"); }
__device__ __forceinline__ void cp_wait2() { asm volatile("cp.async.wait_group 2;\n"); }

#define MMA16816(d, a, b)                                                      \
    asm volatile(                                                              \
        "mma.sync.aligned.m16n8k16.row.col.f32.bf16.bf16.f32 "                 \
        "{%0,%1,%2,%3}, {%4,%5,%6,%7}, {%8,%9}, {%0,%1,%2,%3};\n"              \
        : "+f"(d[0]), "+f"(d[1]), "+f"(d[2]), "+f"(d[3])                       \
        : "r"(a[0]), "r"(a[1]), "r"(a[2]), "r"(a[3]), "r"(b[0]), "r"(b[1]))

__device__ __forceinline__ void ldm_x4(unsigned int* a, unsigned int saddr) {
    asm volatile("ldmatrix.sync.aligned.m8n8.x4.shared.b16 {%0,%1,%2,%3}, [%4];"
                 : "=r"(a[0]), "=r"(a[1]), "=r"(a[2]), "=r"(a[3]) : "r"(saddr));
}

#define BKE 48
#define BKP 24
#define AS_STRIDE 28
#define BS_STRIDE 136

// ================= 64x128 GEMM (O proj, FF2) =================
#define STAGE_WORDS_H (64 * AS_STRIDE + BKP * BS_STRIDE)   // 5056
#define GEMM_SMEM_H (4 * STAGE_WORDS_H * 4)                // 80896 B

__device__ __forceinline__ void gemm_core_h(const __nv_bfloat16* __restrict__ A,
                                            const unsigned int* __restrict__ B,
                                            const float* __restrict__ bias,
                                            const float* __restrict__ res,
                                            float* __restrict__ Cf,
                                            int N, int KE, unsigned int* smem) {
    const int tid = threadIdx.x;
    const int lane = tid & 31;
    const int wid = tid >> 5;
    const int warp_m = wid >> 2;
    const int warp_n = wid & 3;
    const int m0 = blockIdx.y * 64;
    const int n0 = blockIdx.x * 128;
    const int T = KE / BKE;
    const int g = lane >> 2, t4 = lane & 3;
    const int lrow = warp_m * 32 + (lane & 15);
    const int lcol = (lane >> 4) << 2;

    float acc[2][4][4];
#pragma unroll
    for (int i = 0; i < 2; i++)
#pragma unroll
        for (int j = 0; j < 4; j++)
#pragma unroll
            for (int r = 0; r < 4; r++) acc[i][j][r] = 0.f;

    const unsigned int sbase = (unsigned int)__cvta_generic_to_shared(smem);

    auto load_stage = [&](int tile, int stg) {
        unsigned int abase = sbase + (unsigned int)(stg * STAGE_WORDS_H) * 4u;
        unsigned int bbase = abase + 64u * AS_STRIDE * 4u;
        const __nv_bfloat16* Ag = A + (size_t)m0 * KE + tile * BKE;
        {
            int i = tid;
            int r = i / 6, c = i % 6;
            cp16(abase + (unsigned int)(r * AS_STRIDE + c * 4) * 4u,
                 Ag + (size_t)r * KE + c * 8);
            i = tid + 256;
            if (i < 384) {
                r = i / 6; c = i % 6;
                cp16(abase + (unsigned int)(r * AS_STRIDE + c * 4) * 4u,
                     Ag + (size_t)r * KE + c * 8);
            }
        }
        const unsigned int* Bg = B + (size_t)(tile * BKP) * N + n0;
#pragma unroll
        for (int l = 0; l < 3; l++) {
            int i = tid + l * 256;
            int r = i >> 5, c = i & 31;
            cp16(bbase + (unsigned int)(r * BS_STRIDE + c * 4) * 4u,
                 Bg + (size_t)r * N + c * 4);
        }
    };

    load_stage(0, 0); cp_commit();
    load_stage(1, 1); cp_commit();
    load_stage(2, 2); cp_commit();

    for (int t = 0; t < T; t++) {
        cp_wait2();
        __syncthreads();
        if (t + 3 < T) load_stage(t + 3, (t + 3) & 3);
        cp_commit();

        const unsigned int abase = sbase + (unsigned int)((t & 3) * STAGE_WORDS_H) * 4u;
        const unsigned int* Bs = smem + (size_t)(t & 3) * STAGE_WORDS_H + 64 * AS_STRIDE;
#pragma unroll
        for (int s = 0; s < 3; s++) {
            unsigned int a[2][4], b[4][2];
#pragma unroll
            for (int mi = 0; mi < 2; mi++)
                ldm_x4(a[mi], abase + (unsigned int)(((lrow + mi * 16) * AS_STRIDE) +
                                                     s * 8 + lcol) * 4u);
#pragma unroll
            for (int nj = 0; nj < 4; nj++) {
                int n = warp_n * 32 + nj * 8 + g;
                b[nj][0] = Bs[(s * 8 + t4) * BS_STRIDE + n];
                b[nj][1] = Bs[(s * 8 + t4 + 4) * BS_STRIDE + n];
            }
#pragma unroll
            for (int mi = 0; mi < 2; mi++)
#pragma unroll
                for (int nj = 0; nj < 4; nj++) MMA16816(acc[mi][nj], a[mi], b[nj]);
        }
        __syncthreads();
    }

#pragma unroll
    for (int mi = 0; mi < 2; mi++) {
        int row0 = m0 + warp_m * 32 + mi * 16 + g;
#pragma unroll
        for (int nj = 0; nj < 4; nj++) {
            int col = n0 + warp_n * 32 + nj * 8 + t4 * 2;
            float b0 = bias[col], b1 = bias[col + 1];
#pragma unroll
            for (int half = 0; half < 2; half++) {
                int row = row0 + half * 8;
                float2 rr = *(const float2*)(res + (size_t)row * N + col);
                float v0 = acc[mi][nj][half * 2 + 0] + b0 + rr.x;
                float v1 = acc[mi][nj][half * 2 + 1] + b1 + rr.y;
                *(float2*)(Cf + (size_t)row * N + col) = make_float2(v0, v1);
            }
        }
    }
}

__global__ void __launch_bounds__(256, 2) gemm_kh(const __nv_bfloat16* __restrict__ A,
                                                  const unsigned int* __restrict__ B,
                                                  const float* __restrict__ bias,
                                                  const float* __restrict__ res,
                                                  float* __restrict__ Cf, int N, int KE) {
    extern __shared__ unsigned int smem[];
    gemm_core_h(A, B, bias, res, Cf, N, KE, smem);
}

// ================= templated wide GEMM: 128xBN (QKV: BN=256, FF1: BN=192) =====
template <int BN, int NJ, int BST>
__device__ __forceinline__ void gemm_core_wt(const __nv_bfloat16* __restrict__ A,
                                             const unsigned int* __restrict__ B,
                                             const float* __restrict__ bias,
                                             float* __restrict__ Cf,
                                             __nv_bfloat16* __restrict__ Ce,
                                             int N, int KE, int act, int outp,
                                             unsigned int* smem) {
    const int STW = 128 * AS_STRIDE + BKP * BST;
    const int tid = threadIdx.x;
    const int lane = tid & 31;
    const int wid = tid >> 5;
    const int warp_m = wid >> 2;
    const int warp_n = wid & 3;
    const int m0 = blockIdx.y * 128;
    const int n0 = blockIdx.x * BN;
    const int T = KE / BKE;
    const int g = lane >> 2, t4 = lane & 3;
    const int lrow = warp_m * 64 + (lane & 15);
    const int lcol = (lane >> 4) << 2;

    float acc[4][NJ][4];
#pragma unroll
    for (int i = 0; i < 4; i++)
#pragma unroll
        for (int j = 0; j < NJ; j++)
#pragma unroll
            for (int r = 0; r < 4; r++) acc[i][j][r] = 0.f;

    const unsigned int sbase = (unsigned int)__cvta_generic_to_shared(smem);

    auto load_stage = [&](int tile, int stg) {
        unsigned int abase = sbase + (unsigned int)(stg * STW) * 4u;
        unsigned int bbase = abase + 128u * AS_STRIDE * 4u;
        const __nv_bfloat16* Ag = A + (size_t)m0 * KE + tile * BKE;
#pragma unroll
        for (int l = 0; l < 3; l++) {
            int i = tid + l * 256;
            int r = i / 6, c = i % 6;
            cp16(abase + (unsigned int)(r * AS_STRIDE + c * 4) * 4u,
                 Ag + (size_t)r * KE + c * 8);
        }
        const unsigned int* Bg = B + (size_t)(tile * BKP) * N + n0;
        const int CH = BN / 4;                 // 16B chunks per row
        for (int i = tid; i < 24 * CH; i += 256) {
            int r = i / CH, c = i - r * CH;
            cp16(bbase + (unsigned int)(r * BST + c * 4) * 4u,
                 Bg + (size_t)r * N + c * 4);
        }
    };

    load_stage(0, 0); cp_commit();
    load_stage(1, 1); cp_commit();
    load_stage(2, 2); cp_commit();

    for (int t = 0; t < T; t++) {
        cp_wait2();
        __syncthreads();
        if (t + 3 < T) load_stage(t + 3, (t + 3) & 3);
        cp_commit();

        const unsigned int abase = sbase + (unsigned int)((t & 3) * STW) * 4u;
        const unsigned int* Bs = smem + (size_t)(t & 3) * STW + 128 * AS_STRIDE;
#pragma unroll
        for (int s = 0; s < 3; s++) {
            unsigned int a[4][4];
#pragma unroll
            for (int mi = 0; mi < 4; mi++)
                ldm_x4(a[mi], abase + (unsigned int)(((lrow + mi * 16) * AS_STRIDE) +
                                                     s * 8 + lcol) * 4u);
#pragma unroll
            for (int nj = 0; nj < NJ; nj++) {
                unsigned int b[2];
                int n = warp_n * (NJ * 8) + nj * 8 + g;
                b[0] = Bs[(s * 8 + t4) * BST + n];
                b[1] = Bs[(s * 8 + t4 + 4) * BST + n];
#pragma unroll
                for (int mi = 0; mi < 4; mi++) MMA16816(acc[mi][nj], a[mi], b);
            }
        }
        __syncthreads();
    }

#pragma unroll
    for (int mi = 0; mi < 4; mi++) {
        int row0 = m0 + warp_m * 64 + mi * 16 + g;
#pragma unroll
        for (int nj = 0; nj < NJ; nj++) {
            int col = n0 + warp_n * (NJ * 8) + nj * 8 + t4 * 2;
            float b0 = bias[col], b1 = bias[col + 1];
#pragma unroll
            for (int half = 0; half < 2; half++) {
                int row = row0 + half * 8;
                float v0 = acc[mi][nj][half * 2 + 0] + b0;
                float v1 = acc[mi][nj][half * 2 + 1] + b1;
                if (act) {
                    v0 = 0.5f * v0 * (1.f + erff(v0 * 0.70710678118654752440f));
                    v1 = 0.5f * v1 * (1.f + erff(v1 * 0.70710678118654752440f));
                }
                if (outp == 0) {
                    *(float2*)(Cf + (size_t)row * N + col) = make_float2(v0, v1);
                } else {
                    __nv_bfloat16* p = Ce + (size_t)row * (3 * N) + 3 * col;
                    write_ext3(p, v0);
                    write_ext3(p + 3, v1);
                }
            }
        }
    }
}

#define BSW_STRIDE 264
#define STAGE_WORDS_W (128 * AS_STRIDE + BKP * BSW_STRIDE)   // 9920
#define GEMM_SMEM_W (4 * STAGE_WORDS_W * 4)                  // 158720 B
#define BSW_STRIDE_192 200
#define STAGE_WORDS_W192 (128 * AS_STRIDE + BKP * BSW_STRIDE_192)  // 8384
#define GEMM_SMEM_W192 (4 * STAGE_WORDS_W192 * 4)                  // 134144 B

__global__ void __launch_bounds__(256, 1) gemm_k1w192(const __nv_bfloat16* __restrict__ A,
                                                      const unsigned int* __restrict__ B,
                                                      const float* __restrict__ bias,
                                                      float* __restrict__ Cf,
                                                      __nv_bfloat16* __restrict__ Ce,
                                                      int N, int KE, int act, int outp) {
    extern __shared__ unsigned int smem[];
    gemm_core_wt<192, 6, BSW_STRIDE_192>(A, B, bias, Cf, Ce, N, KE, act, outp, smem);
}

__global__ void __launch_bounds__(256, 1) gemm_k3w(const __nv_bfloat16* __restrict__ A,
                                                   const unsigned int* __restrict__ B0,
                                                   const unsigned int* __restrict__ B1,
                                                   const unsigned int* __restrict__ B2,
                                                   const float* __restrict__ bias0,
                                                   const float* __restrict__ bias1,
                                                   const float* __restrict__ bias2,
                                                   float* __restrict__ C0, float* __restrict__ C1,
                                                   float* __restrict__ C2, int KE) {
    extern __shared__ unsigned int smem[];
    int z = blockIdx.z;
    const unsigned int* B = (z == 0) ? B0 : (z == 1) ? B1 : B2;
    const float* bias = (z == 0) ? bias0 : (z == 1) ? bias1 : bias2;
    float* Cf = (z == 0) ? C0 : (z == 1) ? C1 : C2;
    gemm_core_wt<256, 8, BSW_STRIDE>(A, B, bias, Cf, nullptr, Hdim, KE, 0, 0, smem);
}

// ======== tensor-core attention (split-bf16 3-slot) ========
#define A_OFF_MB 0
#define A_OFF_Q  512
#define A_OFF_K  (512 + 6400)
#define A_OFF_V  (512 + 6400 + 6912)
#define A_OFF_P  (512 + 6400 + 13824)
#define A_OFF_PM (512 + 6400 + 13824 + 6400)
#define A_OFF_RM (A_OFF_PM + 128)
#define A_OFF_PS (A_OFF_RM + 64)
#define A_OFF_RS (A_OFF_PS + 128)
#define ATTN_SMEM ((A_OFF_RS + 64) * 4)

__global__ void __launch_bounds__(256) attn_kernel(const float* __restrict__ Q,
                                                   const float* __restrict__ Kp,
                                                   const float* __restrict__ Vp,
                                                   const int* __restrict__ amask,
                                                   __nv_bfloat16* __restrict__ Oext) {
    extern __shared__ unsigned int sm[];
    float* mbias = (float*)(sm + A_OFF_MB);
    unsigned int* qx = sm + A_OFF_Q;
    unsigned int* kx = sm + A_OFF_K;
    unsigned int* vx = sm + A_OFF_V;
    unsigned int* px = sm + A_OFF_P;
    float* partmax = (float*)(sm + A_OFF_PM);
    float* rowmax = (float*)(sm + A_OFF_RM);
    float* partsum = (float*)(sm + A_OFF_PS);
    float* rowsum = (float*)(sm + A_OFF_RS);
    unsigned short* qx16 = (unsigned short*)qx;
    unsigned short* kx16 = (unsigned short*)kx;
    unsigned short* vx16 = (unsigned short*)vx;
    unsigned short* px16 = (unsigned short*)px;

    const int tid = threadIdx.x, lane = tid & 31, w = tid >> 5;
    const int wm = w >> 1, wn = w & 1, g = lane >> 2, t4 = lane & 3;
    const int q0 = blockIdx.x * 64, h = blockIdx.y, b = blockIdx.z;
    const size_t base = (size_t)b * Sdim * Hdim + h * 64;
    const int r0 = wm * 16 + g, r1 = r0 + 8;

    for (int i = tid; i < Sdim; i += 256)
        mbias[i] = (1.f - (float)amask[b * Sdim + i]) * -10000.f;

    for (int i = tid; i < 4096; i += 256) {
        int r = i >> 6, d = i & 63;
        float xv = Q[base + (size_t)(q0 + r) * Hdim + d];
        __nv_bfloat16 hh, ll;
        split2(xv, hh, ll);
        unsigned short uh = *(unsigned short*)&hh, ul = *(unsigned short*)&ll;
        int o = r * 200 + 3 * d;
        qx16[o] = uh; qx16[o + 1] = ul; qx16[o + 2] = uh;
    }
    __syncthreads();

    float sacc[32][4];
#pragma unroll
    for (int i = 0; i < 32; i++)
#pragma unroll
        for (int j = 0; j < 4; j++) sacc[i][j] = 0.f;

#pragma unroll
    for (int kb = 0; kb < 8; kb++) {
        for (int i = tid; i < 4096; i += 256) {
            int kk = i >> 6, d = i & 63;
            float xv = Kp[base + (size_t)(kb * 64 + kk) * Hdim + d];
            __nv_bfloat16 hh, ll;
            split2(xv, hh, ll);
            unsigned short uh = *(unsigned short*)&hh, ul = *(unsigned short*)&ll;
            int e = 3 * d;
            kx16[(e >> 1) * 144 + kk * 2 + (e & 1)] = uh;
            kx16[((e + 1) >> 1) * 144 + kk * 2 + ((e + 1) & 1)] = uh;
            kx16[((e + 2) >> 1) * 144 + kk * 2 + ((e + 2) & 1)] = ul;
        }
        __syncthreads();
#pragma unroll
        for (int s = 0; s < 12; s++) {
            unsigned int a[4];
            int ar = r0 * 100 + s * 8 + t4;
            a[0] = qx[ar]; a[1] = qx[ar + 800]; a[2] = qx[ar + 4]; a[3] = qx[ar + 804];
#pragma unroll
            for (int j = 0; j < 4; j++) {
                unsigned int bb[2];
                int br = (s * 8 + t4) * 72 + wn * 32 + j * 8 + g;
                bb[0] = kx[br]; bb[1] = kx[br + 288];
                MMA16816(sacc[kb * 4 + j], a, bb);
            }
        }
        __syncthreads();
    }

    float rm0 = -1e30f, rm1 = -1e30f;
#pragma unroll
    for (int kb = 0; kb < 8; kb++)
#pragma unroll
        for (int j = 0; j < 4; j++) {
            int c = kb * 64 + wn * 32 + j * 8 + 2 * t4;
            float m0 = mbias[c], m1 = mbias[c + 1];
            float* A = sacc[kb * 4 + j];
            A[0] = A[0] * 0.125f + m0;
            A[1] = A[1] * 0.125f + m1;
            A[2] = A[2] * 0.125f + m0;
            A[3] = A[3] * 0.125f + m1;
            rm0 = fmaxf(rm0, fmaxf(A[0], A[1]));
            rm1 = fmaxf(rm1, fmaxf(A[2], A[3]));
        }
    rm0 = fmaxf(rm0, __shfl_xor_sync(0xffffffffu, rm0, 1));
    rm0 = fmaxf(rm0, __shfl_xor_sync(0xffffffffu, rm0, 2));
    rm1 = fmaxf(rm1, __shfl_xor_sync(0xffffffffu, rm1, 1));
    rm1 = fmaxf(rm1, __shfl_xor_sync(0xffffffffu, rm1, 2));
    if (t4 == 0) {
        partmax[r0 * 2 + wn] = rm0;
        partmax[r1 * 2 + wn] = rm1;
    }
    __syncthreads();
    if (tid < 64) rowmax[tid] = fmaxf(partmax[tid * 2], partmax[tid * 2 + 1]);
    __syncthreads();
    const float mx0 = rowmax[r0], mx1 = rowmax[r1];

    float oacc[4][4];
#pragma unroll
    for (int j = 0; j < 4; j++)
#pragma unroll
        for (int r = 0; r < 4; r++) oacc[j][r] = 0.f;
    float sum0 = 0.f, sum1 = 0.f;

#pragma unroll
    for (int kb = 0; kb < 8; kb++) {
        for (int i = tid; i < 4096; i += 256) {
            int kk = i >> 6, d = i & 63;
            float xv = Vp[base + (size_t)(kb * 64 + kk) * Hdim + d];
            __nv_bfloat16 hh, ll;
            split2(xv, hh, ll);
            unsigned short uh = *(unsigned short*)&hh, ul = *(unsigned short*)&ll;
            int e = 3 * kk;
            vx16[(e >> 1) * 144 + d * 2 + (e & 1)] = uh;
            vx16[((e + 1) >> 1) * 144 + d * 2 + ((e + 1) & 1)] = uh;
            vx16[((e + 2) >> 1) * 144 + d * 2 + ((e + 2) & 1)] = ul;
        }
#pragma unroll
        for (int j = 0; j < 4; j++) {
            float* A = sacc[kb * 4 + j];
#pragma unroll
            for (int c01 = 0; c01 < 2; c01++) {
                int lc = wn * 32 + j * 8 + 2 * t4 + c01;
                float p0 = fexp(A[c01] - mx0);
                float p1 = fexp(A[2 + c01] - mx1);
                sum0 += p0;
                sum1 += p1;
                __nv_bfloat16 hh, ll;
                split2(p0, hh, ll);
                int o0 = r0 * 200 + 3 * lc;
                px16[o0] = *(unsigned short*)&hh;
                px16[o0 + 1] = *(unsigned short*)&ll;
                px16[o0 + 2] = *(unsigned short*)&hh;
                split2(p1, hh, ll);
                int o1 = r1 * 200 + 3 * lc;
                px16[o1] = *(unsigned short*)&hh;
                px16[o1 + 1] = *(unsigned short*)&ll;
                px16[o1 + 2] = *(unsigned short*)&hh;
            }
        }
        __syncthreads();
#pragma unroll
        for (int s = 0; s < 12; s++) {
            unsigned int a[4];
            int ar = r0 * 100 + s * 8 + t4;
            a[0] = px[ar]; a[1] = px[ar + 800]; a[2] = px[ar + 4]; a[3] = px[ar + 804];
#pragma unroll
            for (int j2 = 0; j2 < 4; j2++) {
                unsigned int bb[2];
                int br = (s * 8 + t4) * 72 + wn * 32 + j2 * 8 + g;
                bb[0] = vx[br]; bb[1] = vx[br + 288];
                MMA16816(oacc[j2], a, bb);
            }
        }
        __syncthreads();
    }

    sum0 += __shfl_xor_sync(0xffffffffu, sum0, 1);
    sum0 += __shfl_xor_sync(0xffffffffu, sum0, 2);
    sum1 += __shfl_xor_sync(0xffffffffu, sum1, 1);
    sum1 += __shfl_xor_sync(0xffffffffu, sum1, 2);
    if (t4 == 0) {
        partsum[r0 * 2 + wn] = sum0;
        partsum[r1 * 2 + wn] = sum1;
    }
    __syncthreads();
    if (tid < 64) rowsum[tid] = partsum[tid * 2] + partsum[tid * 2 + 1];
    __syncthreads();
    const float inv0 = 1.f / rowsum[r0];
    const float inv1 = 1.f / rowsum[r1];

#pragma unroll
    for (int j2 = 0; j2 < 4; j2++) {
        int dcol = wn * 32 + j2 * 8 + 2 * t4;
        int mrow0 = b * Sdim + q0 + r0;
        int mrow1 = b * Sdim + q0 + r1;
        __nv_bfloat16* p0 = Oext + (size_t)mrow0 * KE_H + 3 * (h * 64 + dcol);
        write_ext3(p0, oacc[j2][0] * inv0);
        write_ext3(p0 + 3, oacc[j2][1] * inv0);
        __nv_bfloat16* p1 = Oext + (size_t)mrow1 * KE_H + 3 * (h * 64 + dcol);
        write_ext3(p1, oacc[j2][2] * inv1);
        write_ext3(p1 + 3, oacc[j2][3] * inv1);
    }
}

// ---------------- classifier ----------------
__global__ void clf_kernel(const float* __restrict__ X, const float* __restrict__ W,
                           const float* __restrict__ bias, float* __restrict__ F) {
    __shared__ float red[8][Ldim];
    int m = blockIdx.x;
    int tid = threadIdx.x;
    float acc[Ldim];
#pragma unroll
    for (int j = 0; j < Ldim; j++) acc[j] = 0.f;
    for (int k = tid; k < Hdim; k += 256) {
        float x = X[(size_t)m * Hdim + k];
#pragma unroll
        for (int j = 0; j < Ldim; j++) acc[j] += x * W[k * Ldim + j];
    }
    int lane = tid & 31, w = tid >> 5;
#pragma unroll
    for (int j = 0; j < Ldim; j++)
#pragma unroll
        for (int o = 16; o; o >>= 1) acc[j] += __shfl_down_sync(0xffffffffu, acc[j], o);
    if (lane == 0)
#pragma unroll
        for (int j = 0; j < Ldim; j++) red[w][j] = acc[j];
    __syncthreads();
    if (tid < Ldim) {
        float s = bias[tid];
#pragma unroll
        for (int ww = 0; ww < 8; ww++) s += red[ww][tid];
        F[(size_t)m * Ldim + tid] = s;
    }
}

// ---------------- CRF numerator ----------------
__global__ void crf_num_kernel(const float* __restrict__ feats, const int* __restrict__ amask,
                               const int* __restrict__ labels, const float* __restrict__ start,
                               const float* __restrict__ endv, const float* __restrict__ trans,
                               float* __restrict__ num) {
    __shared__ float red[8];
    int b = blockIdx.x;
    int tid = threadIdx.x;
    float s = 0.f, msum = 0.f;
    for (int t = tid; t < Sdim; t += 256) {
        int tag = labels[b * Sdim + t];
        float em = feats[(size_t)(b * Sdim + t) * Ldim + tag];
        float m = (float)amask[b * Sdim + t];
        msum += m;
        if (t == 0) {
            s += start[tag] + em;
        } else {
            int pt = labels[b * Sdim + t - 1];
            s += (em + trans[pt * Ldim + tag]) * m;
        }
    }
    float stotal = blk_sum256(s, red);
    float mtotal = blk_sum256(msum, red);
    if (tid == 0) {
        int last = (int)(mtotal + 0.5f) - 1;
        num[b] = stotal + endv[labels[b * Sdim + last]];
    }
}

// ---------------- CRF forward ----------------
__global__ void crf_fwd_kernel(const float* __restrict__ feats, const int* __restrict__ amask,
                               const float* __restrict__ start, const float* __restrict__ endv,
                               const float* __restrict__ trans, float* __restrict__ logZ) {
    int b = threadIdx.x >> 5;
    int j = threadIdx.x & 31;
    bool act = j < Ldim;
    float tr[Ldim];
#pragma unroll
    for (int i = 0; i < Ldim; i++) tr[i] = act ? trans[i * Ldim + j] : 0.f;
    float score = act ? start[j] + feats[(size_t)(b * Sdim) * Ldim + j] : -1e30f;
    for (int t = 1; t < Sdim; t++) {
        float e = act ? feats[(size_t)(b * Sdim + t) * Ldim + j] : 0.f;
        int m = amask[b * Sdim + t];
        float v[Ldim];
        float mx = -1e30f;
#pragma unroll
        for (int i = 0; i < Ldim; i++) {
            float si = __shfl_sync(0xffffffffu, score, i);
            v[i] = si + tr[i];
            mx = fmaxf(mx, v[i]);
        }
        float ssum = 0.f;
#pragma unroll
        for (int i = 0; i < Ldim; i++) ssum += expf(v[i] - mx);
        float nxt = mx + logf(ssum) + e;
        if (act && m > 0) score = nxt;
    }
    float tot = act ? score + endv[j] : -1e30f;
    float mx = tot;
#pragma unroll
    for (int o = 16; o; o >>= 1) mx = fmaxf(mx, __shfl_xor_sync(0xffffffffu, mx, o));
    float ex = act ? expf(tot - mx) : 0.f;
#pragma unroll
    for (int o = 16; o; o >>= 1) ex += __shfl_xor_sync(0xffffffffu, ex, o);
    if (j == 0) logZ[b] = mx + logf(ex);
}

// ---------------- Viterbi ----------------
__global__ void viterbi_kernel(const float* __restrict__ feats, const int* __restrict__ amask,
                               const float* __restrict__ start, const float* __restrict__ endv,
                               const float* __restrict__ trans, int* __restrict__ tags) {
    __shared__ unsigned char hist[(Sdim - 1) * Ldim];
    int b = blockIdx.x;
    int j = threadIdx.x;
    bool act = j < Ldim;
    float tr[Ldim];
#pragma unroll
    for (int i = 0; i < Ldim; i++) tr[i] = act ? trans[i * Ldim + j] : 0.f;
    float score = act ? start[j] + feats[(size_t)(b * Sdim) * Ldim + j] : -1e30f;
    for (int t = 1; t < Sdim; t++) {
        float e = act ? feats[(size_t)(b * Sdim + t) * Ldim + j] : 0.f;
        int m = amask[b * Sdim + t];
        float best = -1e30f;
        int barg = 0;
#pragma unroll
        for (int i = 0; i < Ldim; i++) {
            float si = __shfl_sync(0xffffffffu, score, i);
            float v = si + tr[i];
            if (v > best) { best = v; barg = i; }
        }
        if (act) {
            hist[(t - 1) * Ldim + j] = (unsigned char)barg;
            float nxt = best + e;
            if (m > 0) score = nxt;
        }
    }
    __syncwarp();
    float tot = act ? score + endv[j] : -1e30f;
    float bb = tot;
    int bj = act ? j : 0;
#pragma unroll
    for (int o = 16; o; o >>= 1) {
        float ov = __shfl_down_sync(0xffffffffu, bb, o);
        int oj = __shfl_down_sync(0xffffffffu, bj, o);
        if (ov > bb) { bb = ov; bj = oj; }
    }
    if (j == 0) {
        int tag = bj;
        tags[b * Sdim + Sdim - 1] = tag;
        for (int t = Sdim - 2; t >= 0; t--) {
            tag = hist[t * Ldim + tag];
            tags[b * Sdim + t] = tag;
        }
    }
}

// ---------------- finalize ----------------
__global__ void finalize_kernel(const float* __restrict__ logZ, const float* __restrict__ num,
                                const int* __restrict__ tags, float* __restrict__ out,
                                int out_size) {
    int i = blockIdx.x * blockDim.x + threadIdx.x;
    if (i >= out_size) return;
    if (i == 0) {
        float s = 0.f;
        for (int b = 0; b < Bdim; b++) s += logZ[b] - num[b];
        out[0] = s * (1.f / Bdim);
    } else if (i - 1 < Bdim * Sdim) {
        out[i] = (float)tags[i - 1];
    } else {
        out[i] = 0.f;
    }
}

// ---------------- host launch ----------------
extern "C" void kernel_launch(void* const* d_in, const int* in_sizes, int n_in,
                              void* d_out, int out_size) {
    const float* word_emb = (const float*)d_in[0];
    const float* pos_emb  = (const float*)d_in[1];
    const float* type_emb = (const float*)d_in[2];
    const float* eln_s    = (const float*)d_in[3];
    const float* eln_b    = (const float*)d_in[4];
    const float* Wq = (const float*)d_in[5];
    const float* bq = (const float*)d_in[6];
    const float* Wk = (const float*)d_in[7];
    const float* bk = (const float*)d_in[8];
    const float* Wv = (const float*)d_in[9];
    const float* bv = (const float*)d_in[10];
    const float* Wo = (const float*)d_in[11];
    const float* bo = (const float*)d_in[12];
    const float* ln1s = (const float*)d_in[13];
    const float* ln1b = (const float*)d_in[14];
    const float* W1 = (const float*)d_in[15];
    const float* b1 = (const float*)d_in[16];
    const float* W2 = (const float*)d_in[17];
    const float* b2 = (const float*)d_in[18];
    const float* ln2s = (const float*)d_in[19];
    const float* ln2b = (const float*)d_in[20];
    const float* clfW = (const float*)d_in[21];
    const float* clfb = (const float*)d_in[22];
    const float* crf_start = (const float*)d_in[23];
    const float* crf_end   = (const float*)d_in[24];
    const float* crf_trans = (const float*)d_in[25];
    const int* input_ids   = (const int*)d_in[26];
    const int* token_type  = (const int*)d_in[27];
    const int* attn_mask   = (const int*)d_in[28];
    const int* labels      = (const int*)d_in[29];

    float *h, *q, *k, *v, *t, *feats, *logZ, *num;
    int* tags;
    __nv_bfloat16 *hext, *ctxext, *ffext;
    unsigned int *Wqp, *Wkp, *Wvp, *Wop, *W1p, *W2p;
    cudaGetSymbolAddress((void**)&h, g_h);
    cudaGetSymbolAddress((void**)&q, g_q);
    cudaGetSymbolAddress((void**)&k, g_k);
    cudaGetSymbolAddress((void**)&v, g_v);
    cudaGetSymbolAddress((void**)&t, g_t);
    cudaGetSymbolAddress((void**)&feats, g_feats);
    cudaGetSymbolAddress((void**)&logZ, g_logZ);
    cudaGetSymbolAddress((void**)&num, g_num);
    cudaGetSymbolAddress((void**)&tags, g_tags);
    cudaGetSymbolAddress((void**)&hext, g_hext);
    cudaGetSymbolAddress((void**)&ctxext, g_ctxext);
    cudaGetSymbolAddress((void**)&ffext, g_ffext);
    cudaGetSymbolAddress((void**)&Wqp, g_Wqp);
    cudaGetSymbolAddress((void**)&Wkp, g_Wkp);
    cudaGetSymbolAddress((void**)&Wvp, g_Wvp);
    cudaGetSymbolAddress((void**)&Wop, g_Wop);
    cudaGetSymbolAddress((void**)&W1p, g_W1p);
    cudaGetSymbolAddress((void**)&W2p, g_W2p);

    cudaFuncSetAttribute(attn_kernel, cudaFuncAttributeMaxDynamicSharedMemorySize, ATTN_SMEM);
    cudaFuncSetAttribute(gemm_kh, cudaFuncAttributeMaxDynamicSharedMemorySize, GEMM_SMEM_H);
    cudaFuncSetAttribute(gemm_k1w192, cudaFuncAttributeMaxDynamicSharedMemorySize, GEMM_SMEM_W192);
    cudaFuncSetAttribute(gemm_k3w, cudaFuncAttributeMaxDynamicSharedMemorySize, GEMM_SMEM_W);

    // vectorized weight conversion (1 thread = 4 cols)
    convP4_kernel<<<dim3(1, PKH, NLnum), 256>>>(Wq, Wqp, Hdim, Hdim);
    convP4_kernel<<<dim3(1, PKH, NLnum), 256>>>(Wk, Wkp, Hdim, Hdim);
    convP4_kernel<<<dim3(1, PKH, NLnum), 256>>>(Wv, Wvp, Hdim, Hdim);
    convP4_kernel<<<dim3(1, PKH, NLnum), 256>>>(Wo, Wop, Hdim, Hdim);
    convP4_kernel<<<dim3(3, PKH, NLnum), 256>>>(W1, W1p, Hdim, FFdim);
    convP4_kernel<<<dim3(1, PKF, NLnum), 256>>>(W2, W2p, FFdim, Hdim);
    embed_ln_kernel<<<Mtot, 256>>>(word_emb, pos_emb, type_emb, eln_s, eln_b,
                                   input_ids, token_type, h, hext);

    dim3 gQKV(Hdim / 256, Mtot / 128, 3);
    dim3 gFF1(FFdim / 192, Mtot / 128);      // 16 x 32 = 512 CTAs
    dim3 gHalf(Hdim / 128, Mtot / 64);
    dim3 gAttn(Sdim / 64, NHnum, Bdim);
    const size_t woff = (size_t)PKH * Hdim;
    const size_t w1off = (size_t)PKH * FFdim;
    const size_t w2off = (size_t)PKF * Hdim;

    for (int l = 0; l < NLnum; l++) {
        gemm_k3w<<<gQKV, 256, GEMM_SMEM_W>>>(hext, Wqp + l * woff, Wkp + l * woff,
                                             Wvp + l * woff, bq + l * Hdim, bk + l * Hdim,
                                             bv + l * Hdim, q, k, v, KE_H);
        attn_kernel<<<gAttn, 256, ATTN_SMEM>>>(q, k, v, attn_mask, ctxext);
        gemm_kh<<<gHalf, 256, GEMM_SMEM_H>>>(ctxext, Wop + l * woff, bo + l * Hdim, h, t,
                                             Hdim, KE_H);
        ln_kernel<<<Mtot, 256>>>(t, ln1s + l * Hdim, ln1b + l * Hdim, h, hext);
        gemm_k1w192<<<gFF1, 256, GEMM_SMEM_W192>>>(hext, W1p + l * w1off, b1 + l * FFdim,
                                                   nullptr, ffext, FFdim, KE_H, 1, 1);
        gemm_kh<<<gHalf, 256, GEMM_SMEM_H>>>(ffext, W2p + l * w2off, b2 + l * Hdim, h, t,
                                             Hdim, KE_FF);
        ln_kernel<<<Mtot, 256>>>(t, ln2s + l * Hdim, ln2b + l * Hdim, h, hext);
    }

    clf_kernel<<<Mtot, 256>>>(h, clfW, clfb, feats);
    crf_num_kernel<<<Bdim, 256>>>(feats, attn_mask, labels, crf_start, crf_end, crf_trans, num);
    crf_fwd_kernel<<<1, 256>>>(feats, attn_mask, crf_start, crf_end, crf_trans, logZ);
    viterbi_kernel<<<Bdim, 32>>>(feats, attn_mask, crf_start, crf_end, crf_trans, tags);

    int nfin = (out_size + 255) / 256;
    if (nfin < 1) nfin = 1;
    finalize_kernel<<<nfin, 256>>>(logZ, num, tags, (float*)d_out, out_size);
}

// round 17
// speedup vs baseline: 1.2367x; 1.0046x over previous
#include <cuda_runtime.h>
#include <cuda_bf16.h>
#include <math.h>

#define Mtot  4096
#define Hdim  768
#define FFdim 3072
#define NHnum 12
#define DHdim 64
#define Sdim  512
#define Bdim  8
#define Ldim  9
#define NLnum 12

#define KE_H  (3 * Hdim)    // 2304
#define KE_FF (3 * FFdim)   // 9216

// ---------------- scratch ----------------
__device__ float g_h[Mtot * Hdim];
__device__ float g_q[Mtot * Hdim];
__device__ float g_k[Mtot * Hdim];
__device__ float g_v[Mtot * Hdim];
__device__ float g_t[Mtot * Hdim];
__device__ float g_feats[Mtot * Ldim];
__device__ float g_logZ[Bdim];
__device__ float g_num[Bdim];
__device__ int   g_tags[Bdim * Sdim];

__device__ __align__(256) __nv_bfloat16 g_hext[Mtot * KE_H];
__device__ __align__(256) __nv_bfloat16 g_ctxext[Mtot * KE_H];
__device__ __align__(256) __nv_bfloat16 g_ffext[(size_t)Mtot * KE_FF];

#define PKH (3 * Hdim / 2)    // 1152
#define PKF (3 * FFdim / 2)   // 4608
__device__ __align__(256) unsigned int g_Wqp[NLnum * PKH * Hdim];
__device__ __align__(256) unsigned int g_Wkp[NLnum * PKH * Hdim];
__device__ __align__(256) unsigned int g_Wvp[NLnum * PKH * Hdim];
__device__ __align__(256) unsigned int g_Wop[NLnum * PKH * Hdim];
__device__ __align__(256) unsigned int g_W1p[(size_t)NLnum * PKH * FFdim];
__device__ __align__(256) unsigned int g_W2p[(size_t)NLnum * PKF * Hdim];

// ---------------- helpers ----------------
__device__ __forceinline__ float blk_sum256(float v, float* red) {
    int lane = threadIdx.x & 31, w = threadIdx.x >> 5;
#pragma unroll
    for (int o = 16; o; o >>= 1) v += __shfl_xor_sync(0xffffffffu, v, o);
    __syncthreads();
    if (lane == 0) red[w] = v;
    __syncthreads();
    float s = 0.f;
#pragma unroll
    for (int i = 0; i < 8; i++) s += red[i];
    return s;
}

__device__ __forceinline__ void split2(float x, __nv_bfloat16& hi, __nv_bfloat16& lo) {
    hi = __float2bfloat16(x);
    lo = __float2bfloat16(x - __bfloat162float(hi));
}

__device__ __forceinline__ void write_ext3(__nv_bfloat16* p, float x) {
    __nv_bfloat16 h, l;
    split2(x, h, l);
    p[0] = h; p[1] = l; p[2] = h;
}

__device__ __forceinline__ float fexp(float x) {
    float t = x * 1.4426950408889634f;
    t = fmaxf(t, -126.0f);
    float fl = floorf(t);
    float f = t - fl;
    float p = 1.525273e-5f;
    p = fmaf(p, f, 1.5403530e-4f);
    p = fmaf(p, f, 1.3333558e-3f);
    p = fmaf(p, f, 9.6181291e-3f);
    p = fmaf(p, f, 5.5504109e-2f);
    p = fmaf(p, f, 2.4022651e-1f);
    p = fmaf(p, f, 6.9314718e-1f);
    p = fmaf(p, f, 1.0f);
    return p * __int_as_float(((int)fl + 127) << 23);
}

// ---------------- weight conversion (vectorized) ----------------
__device__ __forceinline__ unsigned int packpair(float w0, float w1, int r0, int r1) {
    __nv_bfloat16 h0, l0, h1, l1;
    split2(w0, h0, l0);
    split2(w1, h1, l1);
    __nv_bfloat16 v0 = (r0 == 2) ? l0 : h0;
    __nv_bfloat16 v1 = (r1 == 2) ? l1 : h1;
    __nv_bfloat162 pr(v0, v1);
    return *reinterpret_cast<unsigned int*>(&pr);
}

__global__ void convP4_kernel(const float* __restrict__ W, unsigned int* __restrict__ out,
                              int K, int N) {
    int n4 = blockIdx.x * 256 + threadIdx.x;
    int n = n4 * 4;
    if (n >= N) return;
    int i = blockIdx.y;
    int l = blockIdx.z;
    int PK = 3 * K / 2;
    int s0 = 2 * i, s1 = s0 + 1;
    int k0 = s0 / 3, r0 = s0 - 3 * k0;
    int k1 = s1 / 3, r1 = s1 - 3 * k1;
    const float* Wl = W + (size_t)l * K * N;
    float4 w0 = *(const float4*)(Wl + (size_t)k0 * N + n);
    float4 w1 = *(const float4*)(Wl + (size_t)k1 * N + n);
    uint4 o;
    o.x = packpair(w0.x, w1.x, r0, r1);
    o.y = packpair(w0.y, w1.y, r0, r1);
    o.z = packpair(w0.z, w1.z, r0, r1);
    o.w = packpair(w0.w, w1.w, r0, r1);
    *(uint4*)(out + ((size_t)l * PK + i) * N + n) = o;
}

// ---------------- embedding + LayerNorm ----------------
__global__ void embed_ln_kernel(const float* __restrict__ we, const float* __restrict__ pe,
                                const float* __restrict__ te, const float* __restrict__ gs,
                                const float* __restrict__ gb, const int* __restrict__ ids,
                                const int* __restrict__ tts, float* __restrict__ out,
                                __nv_bfloat16* __restrict__ ext) {
    __shared__ float red[8];
    int m = blockIdx.x;
    int s = m & (Sdim - 1);
    int id = ids[m], tt = tts[m];
    float vals[3];
    float lsum = 0.f;
#pragma unroll
    for (int u = 0; u < 3; u++) {
        int j = threadIdx.x + u * 256;
        float v = we[(size_t)id * Hdim + j] + pe[(size_t)s * Hdim + j] + te[(size_t)tt * Hdim + j];
        vals[u] = v;
        lsum += v;
    }
    float mean = blk_sum256(lsum, red) * (1.f / Hdim);
    float lsq = 0.f;
#pragma unroll
    for (int u = 0; u < 3; u++) { float d = vals[u] - mean; lsq += d * d; }
    float var = blk_sum256(lsq, red) * (1.f / Hdim);
    float inv = rsqrtf(var + 1e-12f);
#pragma unroll
    for (int u = 0; u < 3; u++) {
        int j = threadIdx.x + u * 256;
        float y = (vals[u] - mean) * inv * gs[j] + gb[j];
        out[(size_t)m * Hdim + j] = y;
        write_ext3(ext + (size_t)m * KE_H + 3 * j, y);
    }
}

// ---------------- LayerNorm ----------------
__global__ void ln_kernel(const float* __restrict__ x, const float* __restrict__ gs,
                          const float* __restrict__ gb, float* __restrict__ y,
                          __nv_bfloat16* __restrict__ ext) {
    __shared__ float red[8];
    int m = blockIdx.x;
    const float* xr = x + (size_t)m * Hdim;
    float vals[3];
    float lsum = 0.f;
#pragma unroll
    for (int u = 0; u < 3; u++) {
        vals[u] = xr[threadIdx.x + u * 256];
        lsum += vals[u];
    }
    float mean = blk_sum256(lsum, red) * (1.f / Hdim);
    float lsq = 0.f;
#pragma unroll
    for (int u = 0; u < 3; u++) { float d = vals[u] - mean; lsq += d * d; }
    float var = blk_sum256(lsq, red) * (1.f / Hdim);
    float inv = rsqrtf(var + 1e-12f);
#pragma unroll
    for (int u = 0; u < 3; u++) {
        int j = threadIdx.x + u * 256;
        float yy = (vals[u] - mean) * inv * gs[j] + gb[j];
        y[(size_t)m * Hdim + j] = yy;
        write_ext3(ext + (size_t)m * KE_H + 3 * j, yy);
    }
}

// ================= shared GEMM bits =================
__device__ __forceinline__ void cp16(unsigned int saddr, const void* gptr) {
    asm volatile("cp.async.cg.shared.global [%0], [%1], 16;\n" ::"r"(saddr), "l"(gptr));
}
__device__ __forceinline__ void cp_commit() { asm volatile("cp.async.commit_group;\n"); }
__device__ __forceinline__ void cp_wait2() { asm volatile("cp.async.wait_group 2;\n"); }

#define MMA16816(d, a, b)                                                      \
    asm volatile(                                                              \
        "mma.sync.aligned.m16n8k16.row.col.f32.bf16.bf16.f32 "                 \
        "{%0,%1,%2,%3}, {%4,%5,%6,%7}, {%8,%9}, {%0,%1,%2,%3};\n"              \
        : "+f"(d[0]), "+f"(d[1]), "+f"(d[2]), "+f"(d[3])                       \
        : "r"(a[0]), "r"(a[1]), "r"(a[2]), "r"(a[3]), "r"(b[0]), "r"(b[1]))

__device__ __forceinline__ void ldm_x4(unsigned int* a, unsigned int saddr) {
    asm volatile("ldmatrix.sync.aligned.m8n8.x4.shared.b16 {%0,%1,%2,%3}, [%4];"
                 : "=r"(a[0]), "=r"(a[1]), "=r"(a[2]), "=r"(a[3]) : "r"(saddr));
}

#define BKE 48
#define BKP 24
#define AS_STRIDE 28
#define BS_STRIDE 136

// ================= 64x128 GEMM (O proj, FF2, FF1) =================
// EPI 0: +bias +res -> fp32 ;  EPI 1: +bias, GELU -> ext3
#define STAGE_WORDS_H (64 * AS_STRIDE + BKP * BS_STRIDE)   // 5056
#define GEMM_SMEM_H (4 * STAGE_WORDS_H * 4)                // 80896 B

template <int EPI>
__device__ __forceinline__ void gemm_core_h(const __nv_bfloat16* __restrict__ A,
                                            const unsigned int* __restrict__ B,
                                            const float* __restrict__ bias,
                                            const float* __restrict__ res,
                                            float* __restrict__ Cf,
                                            __nv_bfloat16* __restrict__ Ce,
                                            int N, int KE, unsigned int* smem) {
    const int tid = threadIdx.x;
    const int lane = tid & 31;
    const int wid = tid >> 5;
    const int warp_m = wid >> 2;
    const int warp_n = wid & 3;
    const int m0 = blockIdx.y * 64;
    const int n0 = blockIdx.x * 128;
    const int T = KE / BKE;
    const int g = lane >> 2, t4 = lane & 3;
    const int lrow = warp_m * 32 + (lane & 15);
    const int lcol = (lane >> 4) << 2;

    float acc[2][4][4];
#pragma unroll
    for (int i = 0; i < 2; i++)
#pragma unroll
        for (int j = 0; j < 4; j++)
#pragma unroll
            for (int r = 0; r < 4; r++) acc[i][j][r] = 0.f;

    const unsigned int sbase = (unsigned int)__cvta_generic_to_shared(smem);

    auto load_stage = [&](int tile, int stg) {
        unsigned int abase = sbase + (unsigned int)(stg * STAGE_WORDS_H) * 4u;
        unsigned int bbase = abase + 64u * AS_STRIDE * 4u;
        const __nv_bfloat16* Ag = A + (size_t)m0 * KE + tile * BKE;
        {
            int i = tid;
            int r = i / 6, c = i % 6;
            cp16(abase + (unsigned int)(r * AS_STRIDE + c * 4) * 4u,
                 Ag + (size_t)r * KE + c * 8);
            i = tid + 256;
            if (i < 384) {
                r = i / 6; c = i % 6;
                cp16(abase + (unsigned int)(r * AS_STRIDE + c * 4) * 4u,
                     Ag + (size_t)r * KE + c * 8);
            }
        }
        const unsigned int* Bg = B + (size_t)(tile * BKP) * N + n0;
#pragma unroll
        for (int l = 0; l < 3; l++) {
            int i = tid + l * 256;
            int r = i >> 5, c = i & 31;
            cp16(bbase + (unsigned int)(r * BS_STRIDE + c * 4) * 4u,
                 Bg + (size_t)r * N + c * 4);
        }
    };

    load_stage(0, 0); cp_commit();
    load_stage(1, 1); cp_commit();
    load_stage(2, 2); cp_commit();

    for (int t = 0; t < T; t++) {
        cp_wait2();
        __syncthreads();
        if (t + 3 < T) load_stage(t + 3, (t + 3) & 3);
        cp_commit();

        const unsigned int abase = sbase + (unsigned int)((t & 3) * STAGE_WORDS_H) * 4u;
        const unsigned int* Bs = smem + (size_t)(t & 3) * STAGE_WORDS_H + 64 * AS_STRIDE;
#pragma unroll
        for (int s = 0; s < 3; s++) {
            unsigned int a[2][4], b[4][2];
#pragma unroll
            for (int mi = 0; mi < 2; mi++)
                ldm_x4(a[mi], abase + (unsigned int)(((lrow + mi * 16) * AS_STRIDE) +
                                                     s * 8 + lcol) * 4u);
#pragma unroll
            for (int nj = 0; nj < 4; nj++) {
                int n = warp_n * 32 + nj * 8 + g;
                b[nj][0] = Bs[(s * 8 + t4) * BS_STRIDE + n];
                b[nj][1] = Bs[(s * 8 + t4 + 4) * BS_STRIDE + n];
            }
#pragma unroll
            for (int mi = 0; mi < 2; mi++)
#pragma unroll
                for (int nj = 0; nj < 4; nj++) MMA16816(acc[mi][nj], a[mi], b[nj]);
        }
        __syncthreads();
    }

#pragma unroll
    for (int mi = 0; mi < 2; mi++) {
        int row0 = m0 + warp_m * 32 + mi * 16 + g;
#pragma unroll
        for (int nj = 0; nj < 4; nj++) {
            int col = n0 + warp_n * 32 + nj * 8 + t4 * 2;
            float b0 = bias[col], b1 = bias[col + 1];
#pragma unroll
            for (int half = 0; half < 2; half++) {
                int row = row0 + half * 8;
                float v0 = acc[mi][nj][half * 2 + 0] + b0;
                float v1 = acc[mi][nj][half * 2 + 1] + b1;
                if (EPI == 0) {
                    float2 rr = *(const float2*)(res + (size_t)row * N + col);
                    v0 += rr.x;
                    v1 += rr.y;
                    *(float2*)(Cf + (size_t)row * N + col) = make_float2(v0, v1);
                } else {
                    v0 = 0.5f * v0 * (1.f + erff(v0 * 0.70710678118654752440f));
                    v1 = 0.5f * v1 * (1.f + erff(v1 * 0.70710678118654752440f));
                    __nv_bfloat16* p = Ce + (size_t)row * (3 * N) + 3 * col;
                    write_ext3(p, v0);
                    write_ext3(p + 3, v1);
                }
            }
        }
    }
}

__global__ void __launch_bounds__(256, 2) gemm_kh(const __nv_bfloat16* __restrict__ A,
                                                  const unsigned int* __restrict__ B,
                                                  const float* __restrict__ bias,
                                                  const float* __restrict__ res,
                                                  float* __restrict__ Cf, int N, int KE) {
    extern __shared__ unsigned int smem[];
    gemm_core_h<0>(A, B, bias, res, Cf, nullptr, N, KE, smem);
}

__global__ void __launch_bounds__(256, 2) gemm_khg(const __nv_bfloat16* __restrict__ A,
                                                   const unsigned int* __restrict__ B,
                                                   const float* __restrict__ bias,
                                                   __nv_bfloat16* __restrict__ Ce,
                                                   int N, int KE) {
    extern __shared__ unsigned int smem[];
    gemm_core_h<1>(A, B, bias, nullptr, nullptr, Ce, N, KE, smem);
}

// ================= 128x256 GEMM (QKV) =================
#define BSW_STRIDE 264
#define STAGE_WORDS_W (128 * AS_STRIDE + BKP * BSW_STRIDE)   // 9920
#define GEMM_SMEM_W (4 * STAGE_WORDS_W * 4)                  // 158720 B

__device__ __forceinline__ void gemm_core_w(const __nv_bfloat16* __restrict__ A,
                                            const unsigned int* __restrict__ B,
                                            const float* __restrict__ bias,
                                            float* __restrict__ Cf,
                                            int N, int KE, unsigned int* smem) {
    const int tid = threadIdx.x;
    const int lane = tid & 31;
    const int wid = tid >> 5;
    const int warp_m = wid >> 2;
    const int warp_n = wid & 3;
    const int m0 = blockIdx.y * 128;
    const int n0 = blockIdx.x * 256;
    const int T = KE / BKE;
    const int g = lane >> 2, t4 = lane & 3;
    const int lrow = warp_m * 64 + (lane & 15);
    const int lcol = (lane >> 4) << 2;

    float acc[4][8][4];
#pragma unroll
    for (int i = 0; i < 4; i++)
#pragma unroll
        for (int j = 0; j < 8; j++)
#pragma unroll
            for (int r = 0; r < 4; r++) acc[i][j][r] = 0.f;

    const unsigned int sbase = (unsigned int)__cvta_generic_to_shared(smem);

    auto load_stage = [&](int tile, int stg) {
        unsigned int abase = sbase + (unsigned int)(stg * STAGE_WORDS_W) * 4u;
        unsigned int bbase = abase + 128u * AS_STRIDE * 4u;
        const __nv_bfloat16* Ag = A + (size_t)m0 * KE + tile * BKE;
#pragma unroll
        for (int l = 0; l < 3; l++) {
            int i = tid + l * 256;
            int r = i / 6, c = i % 6;
            cp16(abase + (unsigned int)(r * AS_STRIDE + c * 4) * 4u,
                 Ag + (size_t)r * KE + c * 8);
        }
        const unsigned int* Bg = B + (size_t)(tile * BKP) * N + n0;
#pragma unroll
        for (int l = 0; l < 6; l++) {
            int i = tid + l * 256;
            int r = i >> 6, c = i & 63;
            cp16(bbase + (unsigned int)(r * BSW_STRIDE + c * 4) * 4u,
                 Bg + (size_t)r * N + c * 4);
        }
    };

    load_stage(0, 0); cp_commit();
    load_stage(1, 1); cp_commit();
    load_stage(2, 2); cp_commit();

    for (int t = 0; t < T; t++) {
        cp_wait2();
        __syncthreads();
        if (t + 3 < T) load_stage(t + 3, (t + 3) & 3);
        cp_commit();

        const unsigned int abase = sbase + (unsigned int)((t & 3) * STAGE_WORDS_W) * 4u;
        const unsigned int* Bs = smem + (size_t)(t & 3) * STAGE_WORDS_W + 128 * AS_STRIDE;
#pragma unroll
        for (int s = 0; s < 3; s++) {
            unsigned int a[4][4];
#pragma unroll
            for (int mi = 0; mi < 4; mi++)
                ldm_x4(a[mi], abase + (unsigned int)(((lrow + mi * 16) * AS_STRIDE) +
                                                     s * 8 + lcol) * 4u);
#pragma unroll
            for (int nj = 0; nj < 8; nj++) {
                unsigned int b[2];
                int n = warp_n * 64 + nj * 8 + g;
                b[0] = Bs[(s * 8 + t4) * BSW_STRIDE + n];
                b[1] = Bs[(s * 8 + t4 + 4) * BSW_STRIDE + n];
#pragma unroll
                for (int mi = 0; mi < 4; mi++) MMA16816(acc[mi][nj], a[mi], b);
            }
        }
        __syncthreads();
    }

#pragma unroll
    for (int mi = 0; mi < 4; mi++) {
        int row0 = m0 + warp_m * 64 + mi * 16 + g;
#pragma unroll
        for (int nj = 0; nj < 8; nj++) {
            int col = n0 + warp_n * 64 + nj * 8 + t4 * 2;
            float b0 = bias[col], b1 = bias[col + 1];
#pragma unroll
            for (int half = 0; half < 2; half++) {
                int row = row0 + half * 8;
                float v0 = acc[mi][nj][half * 2 + 0] + b0;
                float v1 = acc[mi][nj][half * 2 + 1] + b1;
                *(float2*)(Cf + (size_t)row * N + col) = make_float2(v0, v1);
            }
        }
    }
}

__global__ void __launch_bounds__(256, 1) gemm_k3w(const __nv_bfloat16* __restrict__ A,
                                                   const unsigned int* __restrict__ B0,
                                                   const unsigned int* __restrict__ B1,
                                                   const unsigned int* __restrict__ B2,
                                                   const float* __restrict__ bias0,
                                                   const float* __restrict__ bias1,
                                                   const float* __restrict__ bias2,
                                                   float* __restrict__ C0, float* __restrict__ C1,
                                                   float* __restrict__ C2, int KE) {
    extern __shared__ unsigned int smem[];
    int z = blockIdx.z;
    const unsigned int* B = (z == 0) ? B0 : (z == 1) ? B1 : B2;
    const float* bias = (z == 0) ? bias0 : (z == 1) ? bias1 : bias2;
    float* Cf = (z == 0) ? C0 : (z == 1) ? C1 : C2;
    gemm_core_w(A, B, bias, Cf, Hdim, KE, smem);
}

// ======== tensor-core attention (split-bf16 3-slot) ========
#define A_OFF_MB 0
#define A_OFF_Q  512
#define A_OFF_K  (512 + 6400)
#define A_OFF_V  (512 + 6400 + 6912)
#define A_OFF_P  (512 + 6400 + 13824)
#define A_OFF_PM (512 + 6400 + 13824 + 6400)
#define A_OFF_RM (A_OFF_PM + 128)
#define A_OFF_PS (A_OFF_RM + 64)
#define A_OFF_RS (A_OFF_PS + 128)
#define ATTN_SMEM ((A_OFF_RS + 64) * 4)

__global__ void __launch_bounds__(256) attn_kernel(const float* __restrict__ Q,
                                                   const float* __restrict__ Kp,
                                                   const float* __restrict__ Vp,
                                                   const int* __restrict__ amask,
                                                   __nv_bfloat16* __restrict__ Oext) {
    extern __shared__ unsigned int sm[];
    float* mbias = (float*)(sm + A_OFF_MB);
    unsigned int* qx = sm + A_OFF_Q;
    unsigned int* kx = sm + A_OFF_K;
    unsigned int* vx = sm + A_OFF_V;
    unsigned int* px = sm + A_OFF_P;
    float* partmax = (float*)(sm + A_OFF_PM);
    float* rowmax = (float*)(sm + A_OFF_RM);
    float* partsum = (float*)(sm + A_OFF_PS);
    float* rowsum = (float*)(sm + A_OFF_RS);
    unsigned short* qx16 = (unsigned short*)qx;
    unsigned short* kx16 = (unsigned short*)kx;
    unsigned short* vx16 = (unsigned short*)vx;
    unsigned short* px16 = (unsigned short*)px;

    const int tid = threadIdx.x, lane = tid & 31, w = tid >> 5;
    const int wm = w >> 1, wn = w & 1, g = lane >> 2, t4 = lane & 3;
    const int q0 = blockIdx.x * 64, h = blockIdx.y, b = blockIdx.z;
    const size_t base = (size_t)b * Sdim * Hdim + h * 64;
    const int r0 = wm * 16 + g, r1 = r0 + 8;

    for (int i = tid; i < Sdim; i += 256)
        mbias[i] = (1.f - (float)amask[b * Sdim + i]) * -10000.f;

    for (int i = tid; i < 4096; i += 256) {
        int r = i >> 6, d = i & 63;
        float xv = Q[base + (size_t)(q0 + r) * Hdim + d];
        __nv_bfloat16 hh, ll;
        split2(xv, hh, ll);
        unsigned short uh = *(unsigned short*)&hh, ul = *(unsigned short*)&ll;
        int o = r * 200 + 3 * d;
        qx16[o] = uh; qx16[o + 1] = ul; qx16[o + 2] = uh;
    }
    __syncthreads();

    float sacc[32][4];
#pragma unroll
    for (int i = 0; i < 32; i++)
#pragma unroll
        for (int j = 0; j < 4; j++) sacc[i][j] = 0.f;

#pragma unroll
    for (int kb = 0; kb < 8; kb++) {
        for (int i = tid; i < 4096; i += 256) {
            int kk = i >> 6, d = i & 63;
            float xv = Kp[base + (size_t)(kb * 64 + kk) * Hdim + d];
            __nv_bfloat16 hh, ll;
            split2(xv, hh, ll);
            unsigned short uh = *(unsigned short*)&hh, ul = *(unsigned short*)&ll;
            int e = 3 * d;
            kx16[(e >> 1) * 144 + kk * 2 + (e & 1)] = uh;
            kx16[((e + 1) >> 1) * 144 + kk * 2 + ((e + 1) & 1)] = uh;
            kx16[((e + 2) >> 1) * 144 + kk * 2 + ((e + 2) & 1)] = ul;
        }
        __syncthreads();
#pragma unroll
        for (int s = 0; s < 12; s++) {
            unsigned int a[4];
            int ar = r0 * 100 + s * 8 + t4;
            a[0] = qx[ar]; a[1] = qx[ar + 800]; a[2] = qx[ar + 4]; a[3] = qx[ar + 804];
#pragma unroll
            for (int j = 0; j < 4; j++) {
                unsigned int bb[2];
                int br = (s * 8 + t4) * 72 + wn * 32 + j * 8 + g;
                bb[0] = kx[br]; bb[1] = kx[br + 288];
                MMA16816(sacc[kb * 4 + j], a, bb);
            }
        }
        __syncthreads();
    }

    float rm0 = -1e30f, rm1 = -1e30f;
#pragma unroll
    for (int kb = 0; kb < 8; kb++)
#pragma unroll
        for (int j = 0; j < 4; j++) {
            int c = kb * 64 + wn * 32 + j * 8 + 2 * t4;
            float m0 = mbias[c], m1 = mbias[c + 1];
            float* A = sacc[kb * 4 + j];
            A[0] = A[0] * 0.125f + m0;
            A[1] = A[1] * 0.125f + m1;
            A[2] = A[2] * 0.125f + m0;
            A[3] = A[3] * 0.125f + m1;
            rm0 = fmaxf(rm0, fmaxf(A[0], A[1]));
            rm1 = fmaxf(rm1, fmaxf(A[2], A[3]));
        }
    rm0 = fmaxf(rm0, __shfl_xor_sync(0xffffffffu, rm0, 1));
    rm0 = fmaxf(rm0, __shfl_xor_sync(0xffffffffu, rm0, 2));
    rm1 = fmaxf(rm1, __shfl_xor_sync(0xffffffffu, rm1, 1));
    rm1 = fmaxf(rm1, __shfl_xor_sync(0xffffffffu, rm1, 2));
    if (t4 == 0) {
        partmax[r0 * 2 + wn] = rm0;
        partmax[r1 * 2 + wn] = rm1;
    }
    __syncthreads();
    if (tid < 64) rowmax[tid] = fmaxf(partmax[tid * 2], partmax[tid * 2 + 1]);
    __syncthreads();
    const float mx0 = rowmax[r0], mx1 = rowmax[r1];

    float oacc[4][4];
#pragma unroll
    for (int j = 0; j < 4; j++)
#pragma unroll
        for (int r = 0; r < 4; r++) oacc[j][r] = 0.f;
    float sum0 = 0.f, sum1 = 0.f;

#pragma unroll
    for (int kb = 0; kb < 8; kb++) {
        for (int i = tid; i < 4096; i += 256) {
            int kk = i >> 6, d = i & 63;
            float xv = Vp[base + (size_t)(kb * 64 + kk) * Hdim + d];
            __nv_bfloat16 hh, ll;
            split2(xv, hh, ll);
            unsigned short uh = *(unsigned short*)&hh, ul = *(unsigned short*)&ll;
            int e = 3 * kk;
            vx16[(e >> 1) * 144 + d * 2 + (e & 1)] = uh;
            vx16[((e + 1) >> 1) * 144 + d * 2 + ((e + 1) & 1)] = uh;
            vx16[((e + 2) >> 1) * 144 + d * 2 + ((e + 2) & 1)] = ul;
        }
#pragma unroll
        for (int j = 0; j < 4; j++) {
            float* A = sacc[kb * 4 + j];
#pragma unroll
            for (int c01 = 0; c01 < 2; c01++) {
                int lc = wn * 32 + j * 8 + 2 * t4 + c01;
                float p0 = fexp(A[c01] - mx0);
                float p1 = fexp(A[2 + c01] - mx1);
                sum0 += p0;
                sum1 += p1;
                __nv_bfloat16 hh, ll;
                split2(p0, hh, ll);
                int o0 = r0 * 200 + 3 * lc;
                px16[o0] = *(unsigned short*)&hh;
                px16[o0 + 1] = *(unsigned short*)&ll;
                px16[o0 + 2] = *(unsigned short*)&hh;
                split2(p1, hh, ll);
                int o1 = r1 * 200 + 3 * lc;
                px16[o1] = *(unsigned short*)&hh;
                px16[o1 + 1] = *(unsigned short*)&ll;
                px16[o1 + 2] = *(unsigned short*)&hh;
            }
        }
        __syncthreads();
#pragma unroll
        for (int s = 0; s < 12; s++) {
            unsigned int a[4];
            int ar = r0 * 100 + s * 8 + t4;
            a[0] = px[ar]; a[1] = px[ar + 800]; a[2] = px[ar + 4]; a[3] = px[ar + 804];
#pragma unroll
            for (int j2 = 0; j2 < 4; j2++) {
                unsigned int bb[2];
                int br = (s * 8 + t4) * 72 + wn * 32 + j2 * 8 + g;
                bb[0] = vx[br]; bb[1] = vx[br + 288];
                MMA16816(oacc[j2], a, bb);
            }
        }
        __syncthreads();
    }

    sum0 += __shfl_xor_sync(0xffffffffu, sum0, 1);
    sum0 += __shfl_xor_sync(0xffffffffu, sum0, 2);
    sum1 += __shfl_xor_sync(0xffffffffu, sum1, 1);
    sum1 += __shfl_xor_sync(0xffffffffu, sum1, 2);
    if (t4 == 0) {
        partsum[r0 * 2 + wn] = sum0;
        partsum[r1 * 2 + wn] = sum1;
    }
    __syncthreads();
    if (tid < 64) rowsum[tid] = partsum[tid * 2] + partsum[tid * 2 + 1];
    __syncthreads();
    const float inv0 = 1.f / rowsum[r0];
    const float inv1 = 1.f / rowsum[r1];

#pragma unroll
    for (int j2 = 0; j2 < 4; j2++) {
        int dcol = wn * 32 + j2 * 8 + 2 * t4;
        int mrow0 = b * Sdim + q0 + r0;
        int mrow1 = b * Sdim + q0 + r1;
        __nv_bfloat16* p0 = Oext + (size_t)mrow0 * KE_H + 3 * (h * 64 + dcol);
        write_ext3(p0, oacc[j2][0] * inv0);
        write_ext3(p0 + 3, oacc[j2][1] * inv0);
        __nv_bfloat16* p1 = Oext + (size_t)mrow1 * KE_H + 3 * (h * 64 + dcol);
        write_ext3(p1, oacc[j2][2] * inv1);
        write_ext3(p1 + 3, oacc[j2][3] * inv1);
    }
}

// ---------------- classifier ----------------
__global__ void clf_kernel(const float* __restrict__ X, const float* __restrict__ W,
                           const float* __restrict__ bias, float* __restrict__ F) {
    __shared__ float red[8][Ldim];
    int m = blockIdx.x;
    int tid = threadIdx.x;
    float acc[Ldim];
#pragma unroll
    for (int j = 0; j < Ldim; j++) acc[j] = 0.f;
    for (int k = tid; k < Hdim; k += 256) {
        float x = X[(size_t)m * Hdim + k];
#pragma unroll
        for (int j = 0; j < Ldim; j++) acc[j] += x * W[k * Ldim + j];
    }
    int lane = tid & 31, w = tid >> 5;
#pragma unroll
    for (int j = 0; j < Ldim; j++)
#pragma unroll
        for (int o = 16; o; o >>= 1) acc[j] += __shfl_down_sync(0xffffffffu, acc[j], o);
    if (lane == 0)
#pragma unroll
        for (int j = 0; j < Ldim; j++) red[w][j] = acc[j];
    __syncthreads();
    if (tid < Ldim) {
        float s = bias[tid];
#pragma unroll
        for (int ww = 0; ww < 8; ww++) s += red[ww][tid];
        F[(size_t)m * Ldim + tid] = s;
    }
}

// ---------------- CRF numerator ----------------
__global__ void crf_num_kernel(const float* __restrict__ feats, const int* __restrict__ amask,
                               const int* __restrict__ labels, const float* __restrict__ start,
                               const float* __restrict__ endv, const float* __restrict__ trans,
                               float* __restrict__ num) {
    __shared__ float red[8];
    int b = blockIdx.x;
    int tid = threadIdx.x;
    float s = 0.f, msum = 0.f;
    for (int t = tid; t < Sdim; t += 256) {
        int tag = labels[b * Sdim + t];
        float em = feats[(size_t)(b * Sdim + t) * Ldim + tag];
        float m = (float)amask[b * Sdim + t];
        msum += m;
        if (t == 0) {
            s += start[tag] + em;
        } else {
            int pt = labels[b * Sdim + t - 1];
            s += (em + trans[pt * Ldim + tag]) * m;
        }
    }
    float stotal = blk_sum256(s, red);
    float mtotal = blk_sum256(msum, red);
    if (tid == 0) {
        int last = (int)(mtotal + 0.5f) - 1;
        num[b] = stotal + endv[labels[b * Sdim + last]];
    }
}

// ---------------- CRF forward ----------------
__global__ void crf_fwd_kernel(const float* __restrict__ feats, const int* __restrict__ amask,
                               const float* __restrict__ start, const float* __restrict__ endv,
                               const float* __restrict__ trans, float* __restrict__ logZ) {
    int b = threadIdx.x >> 5;
    int j = threadIdx.x & 31;
    bool act = j < Ldim;
    float tr[Ldim];
#pragma unroll
    for (int i = 0; i < Ldim; i++) tr[i] = act ? trans[i * Ldim + j] : 0.f;
    float score = act ? start[j] + feats[(size_t)(b * Sdim) * Ldim + j] : -1e30f;
    for (int t = 1; t < Sdim; t++) {
        float e = act ? feats[(size_t)(b * Sdim + t) * Ldim + j] : 0.f;
        int m = amask[b * Sdim + t];
        float v[Ldim];
        float mx = -1e30f;
#pragma unroll
        for (int i = 0; i < Ldim; i++) {
            float si = __shfl_sync(0xffffffffu, score, i);
            v[i] = si + tr[i];
            mx = fmaxf(mx, v[i]);
        }
        float ssum = 0.f;
#pragma unroll
        for (int i = 0; i < Ldim; i++) ssum += expf(v[i] - mx);
        float nxt = mx + logf(ssum) + e;
        if (act && m > 0) score = nxt;
    }
    float tot = act ? score + endv[j] : -1e30f;
    float mx = tot;
#pragma unroll
    for (int o = 16; o; o >>= 1) mx = fmaxf(mx, __shfl_xor_sync(0xffffffffu, mx, o));
    float ex = act ? expf(tot - mx) : 0.f;
#pragma unroll
    for (int o = 16; o; o >>= 1) ex += __shfl_xor_sync(0xffffffffu, ex, o);
    if (j == 0) logZ[b] = mx + logf(ex);
}

// ---------------- Viterbi ----------------
__global__ void viterbi_kernel(const float* __restrict__ feats, const int* __restrict__ amask,
                               const float* __restrict__ start, const float* __restrict__ endv,
                               const float* __restrict__ trans, int* __restrict__ tags) {
    __shared__ unsigned char hist[(Sdim - 1) * Ldim];
    int b = blockIdx.x;
    int j = threadIdx.x;
    bool act = j < Ldim;
    float tr[Ldim];
#pragma unroll
    for (int i = 0; i < Ldim; i++) tr[i] = act ? trans[i * Ldim + j] : 0.f;
    float score = act ? start[j] + feats[(size_t)(b * Sdim) * Ldim + j] : -1e30f;
    for (int t = 1; t < Sdim; t++) {
        float e = act ? feats[(size_t)(b * Sdim + t) * Ldim + j] : 0.f;
        int m = amask[b * Sdim + t];
        float best = -1e30f;
        int barg = 0;
#pragma unroll
        for (int i = 0; i < Ldim; i++) {
            float si = __shfl_sync(0xffffffffu, score, i);
            float v = si + tr[i];
            if (v > best) { best = v; barg = i; }
        }
        if (act) {
            hist[(t - 1) * Ldim + j] = (unsigned char)barg;
            float nxt = best + e;
            if (m > 0) score = nxt;
        }
    }
    __syncwarp();
    float tot = act ? score + endv[j] : -1e30f;
    float bb = tot;
    int bj = act ? j : 0;
#pragma unroll
    for (int o = 16; o; o >>= 1) {
        float ov = __shfl_down_sync(0xffffffffu, bb, o);
        int oj = __shfl_down_sync(0xffffffffu, bj, o);
        if (ov > bb) { bb = ov; bj = oj; }
    }
    if (j == 0) {
        int tag = bj;
        tags[b * Sdim + Sdim - 1] = tag;
        for (int t = Sdim - 2; t >= 0; t--) {
            tag = hist[t * Ldim + tag];
            tags[b * Sdim + t] = tag;
        }
    }
}

// ---------------- finalize ----------------
__global__ void finalize_kernel(const float* __restrict__ logZ, const float* __restrict__ num,
                                const int* __restrict__ tags, float* __restrict__ out,
                                int out_size) {
    int i = blockIdx.x * blockDim.x + threadIdx.x;
    if (i >= out_size) return;
    if (i == 0) {
        float s = 0.f;
        for (int b = 0; b < Bdim; b++) s += logZ[b] - num[b];
        out[0] = s * (1.f / Bdim);
    } else if (i - 1 < Bdim * Sdim) {
        out[i] = (float)tags[i - 1];
    } else {
        out[i] = 0.f;
    }
}

// ---------------- host launch ----------------
extern "C" void kernel_launch(void* const* d_in, const int* in_sizes, int n_in,
                              void* d_out, int out_size) {
    const float* word_emb = (const float*)d_in[0];
    const float* pos_emb  = (const float*)d_in[1];
    const float* type_emb = (const float*)d_in[2];
    const float* eln_s    = (const float*)d_in[3];
    const float* eln_b    = (const float*)d_in[4];
    const float* Wq = (const float*)d_in[5];
    const float* bq = (const float*)d_in[6];
    const float* Wk = (const float*)d_in[7];
    const float* bk = (const float*)d_in[8];
    const float* Wv = (const float*)d_in[9];
    const float* bv = (const float*)d_in[10];
    const float* Wo = (const float*)d_in[11];
    const float* bo = (const float*)d_in[12];
    const float* ln1s = (const float*)d_in[13];
    const float* ln1b = (const float*)d_in[14];
    const float* W1 = (const float*)d_in[15];
    const float* b1 = (const float*)d_in[16];
    const float* W2 = (const float*)d_in[17];
    const float* b2 = (const float*)d_in[18];
    const float* ln2s = (const float*)d_in[19];
    const float* ln2b = (const float*)d_in[20];
    const float* clfW = (const float*)d_in[21];
    const float* clfb = (const float*)d_in[22];
    const float* crf_start = (const float*)d_in[23];
    const float* crf_end   = (const float*)d_in[24];
    const float* crf_trans = (const float*)d_in[25];
    const int* input_ids   = (const int*)d_in[26];
    const int* token_type  = (const int*)d_in[27];
    const int* attn_mask   = (const int*)d_in[28];
    const int* labels      = (const int*)d_in[29];

    float *h, *q, *k, *v, *t, *feats, *logZ, *num;
    int* tags;
    __nv_bfloat16 *hext, *ctxext, *ffext;
    unsigned int *Wqp, *Wkp, *Wvp, *Wop, *W1p, *W2p;
    cudaGetSymbolAddress((void**)&h, g_h);
    cudaGetSymbolAddress((void**)&q, g_q);
    cudaGetSymbolAddress((void**)&k, g_k);
    cudaGetSymbolAddress((void**)&v, g_v);
    cudaGetSymbolAddress((void**)&t, g_t);
    cudaGetSymbolAddress((void**)&feats, g_feats);
    cudaGetSymbolAddress((void**)&logZ, g_logZ);
    cudaGetSymbolAddress((void**)&num, g_num);
    cudaGetSymbolAddress((void**)&tags, g_tags);
    cudaGetSymbolAddress((void**)&hext, g_hext);
    cudaGetSymbolAddress((void**)&ctxext, g_ctxext);
    cudaGetSymbolAddress((void**)&ffext, g_ffext);
    cudaGetSymbolAddress((void**)&Wqp, g_Wqp);
    cudaGetSymbolAddress((void**)&Wkp, g_Wkp);
    cudaGetSymbolAddress((void**)&Wvp, g_Wvp);
    cudaGetSymbolAddress((void**)&Wop, g_Wop);
    cudaGetSymbolAddress((void**)&W1p, g_W1p);
    cudaGetSymbolAddress((void**)&W2p, g_W2p);

    cudaFuncSetAttribute(attn_kernel, cudaFuncAttributeMaxDynamicSharedMemorySize, ATTN_SMEM);
    cudaFuncSetAttribute(gemm_kh, cudaFuncAttributeMaxDynamicSharedMemorySize, GEMM_SMEM_H);
    cudaFuncSetAttribute(gemm_khg, cudaFuncAttributeMaxDynamicSharedMemorySize, GEMM_SMEM_H);
    cudaFuncSetAttribute(gemm_k3w, cudaFuncAttributeMaxDynamicSharedMemorySize, GEMM_SMEM_W);

    convP4_kernel<<<dim3(1, PKH, NLnum), 256>>>(Wq, Wqp, Hdim, Hdim);
    convP4_kernel<<<dim3(1, PKH, NLnum), 256>>>(Wk, Wkp, Hdim, Hdim);
    convP4_kernel<<<dim3(1, PKH, NLnum), 256>>>(Wv, Wvp, Hdim, Hdim);
    convP4_kernel<<<dim3(1, PKH, NLnum), 256>>>(Wo, Wop, Hdim, Hdim);
    convP4_kernel<<<dim3(3, PKH, NLnum), 256>>>(W1, W1p, Hdim, FFdim);
    convP4_kernel<<<dim3(1, PKF, NLnum), 256>>>(W2, W2p, FFdim, Hdim);
    embed_ln_kernel<<<Mtot, 256>>>(word_emb, pos_emb, type_emb, eln_s, eln_b,
                                   input_ids, token_type, h, hext);

    dim3 gQKV(Hdim / 256, Mtot / 128, 3);
    dim3 gFF1(FFdim / 128, Mtot / 64);       // 24 x 64 = 1536 CTAs (64x128 tiles)
    dim3 gHalf(Hdim / 128, Mtot / 64);
    dim3 gAttn(Sdim / 64, NHnum, Bdim);
    const size_t woff = (size_t)PKH * Hdim;
    const size_t w1off = (size_t)PKH * FFdim;
    const size_t w2off = (size_t)PKF * Hdim;

    for (int l = 0; l < NLnum; l++) {
        gemm_k3w<<<gQKV, 256, GEMM_SMEM_W>>>(hext, Wqp + l * woff, Wkp + l * woff,
                                             Wvp + l * woff, bq + l * Hdim, bk + l * Hdim,
                                             bv + l * Hdim, q, k, v, KE_H);
        attn_kernel<<<gAttn, 256, ATTN_SMEM>>>(q, k, v, attn_mask, ctxext);
        gemm_kh<<<gHalf, 256, GEMM_SMEM_H>>>(ctxext, Wop + l * woff, bo + l * Hdim, h, t,
                                             Hdim, KE_H);
        ln_kernel<<<Mtot, 256>>>(t, ln1s + l * Hdim, ln1b + l * Hdim, h, hext);
        gemm_khg<<<gFF1, 256, GEMM_SMEM_H>>>(hext, W1p + l * w1off, b1 + l * FFdim,
                                             ffext, FFdim, KE_H);
        gemm_kh<<<gHalf, 256, GEMM_SMEM_H>>>(ffext, W2p + l * w2off, b2 + l * Hdim, h, t,
                                             Hdim, KE_FF);
        ln_kernel<<<Mtot, 256>>>(t, ln2s + l * Hdim, ln2b + l * Hdim, h, hext);
    }

    clf_kernel<<<Mtot, 256>>>(h, clfW, clfb, feats);
    crf_num_kernel<<<Bdim, 256>>>(feats, attn_mask, labels, crf_start, crf_end, crf_trans, num);
    crf_fwd_kernel<<<1, 256>>>(feats, attn_mask, crf_start, crf_end, crf_trans, logZ);
    viterbi_kernel<<<Bdim, 32>>>(feats, attn_mask, crf_start, crf_end, crf_trans, tags);

    int nfin = (out_size + 255) / 256;
    if (nfin < 1) nfin = 1;
    finalize_kernel<<<nfin, 256>>>(logZ, num, tags, (float*)d_out, out_size);
}